// round 7
// baseline (speedup 1.0000x reference)
#include <cuda_runtime.h>
#include <cuda_bf16.h>
#include <cuda.h>
#include <cstdint>

// Problem dims (fixed by setup_inputs)
#define B_SZ   2
#define S_LEN  2048
#define DMODEL 2048
#define NHEAD  16
#define M_TOK  (B_SZ * S_LEN)     // 4096
#define N_QKV  (3 * DMODEL)       // 6144
#define KDIM   DMODEL             // 2048
#define QSCALE 0.0883883476483184f

// ---------------- scratch (static device globals: allocation-free) ----------
__device__ unsigned short g_qkvh[(size_t)M_TOK * N_QKV];
__device__ unsigned short g_qkvl[(size_t)M_TOK * N_QKV];
__device__ float g_o1[(size_t)M_TOK * DMODEL];
__device__ float g_o2[(size_t)M_TOK * DMODEL];
__device__ unsigned short g_Ah[(size_t)M_TOK * KDIM];
__device__ unsigned short g_Al[(size_t)M_TOK * KDIM];
__device__ unsigned short g_WAh[(size_t)N_QKV * KDIM];
__device__ unsigned short g_WAl[(size_t)N_QKV * KDIM];
__device__ unsigned short g_WPh[(size_t)DMODEL * KDIM];
__device__ unsigned short g_WPl[(size_t)DMODEL * KDIM];
__device__ unsigned short g_Oh[(size_t)M_TOK * KDIM];
__device__ unsigned short g_Ol[(size_t)M_TOK * KDIM];

// ---------------------------------------------------------------------------
// PTX helpers (base sm_90 only — no 'a'-gated instructions)
// ---------------------------------------------------------------------------
__device__ __forceinline__ uint32_t smem_u32(const void* p) {
    uint32_t a;
    asm("{ .reg .u64 t; cvta.to.shared.u64 t, %1; cvt.u32.u64 %0, t; }" : "=r"(a) : "l"(p));
    return a;
}

#define MBARRIER_INIT(addr, cnt) \
    asm volatile("mbarrier.init.shared.b64 [%0], %1;" :: "r"((uint32_t)(addr)), "r"((uint32_t)(cnt)) : "memory")

#define MBARRIER_ARRIVE(addr) \
    asm volatile("mbarrier.arrive.shared.b64 _, [%0];" :: "r"((uint32_t)(addr)) : "memory")

#define MBARRIER_EXPECT_TX(addr, bytes) \
    asm volatile("mbarrier.arrive.expect_tx.shared.b64 _, [%0], %1;" :: "r"((uint32_t)(addr)), "r"((uint32_t)(bytes)) : "memory")

#define MBARRIER_WAIT_PARITY(mbar_smem_addr, phase_parity) do { \
    uint32_t _mbar = (uint32_t)(mbar_smem_addr); \
    uint32_t _parity = (uint32_t)(phase_parity); \
    uint32_t _done; \
    asm volatile( \
        "{\n\t.reg .pred p;\n\t" \
        "mbarrier.try_wait.parity.acquire.cta.shared::cta.b64 p, [%1], %2;\n\t" \
        "selp.b32 %0, 1, 0, p;\n\t}" \
        : "=r"(_done) : "r"(_mbar), "r"(_parity) : "memory"); \
    if (!_done) { \
        asm volatile( \
            "{\n\t.reg .pred P1;\n\t" \
            "WAIT_LOOP_%=:\n\t" \
            "mbarrier.try_wait.parity.acquire.cta.shared::cta.b64 P1, [%0], %1, 0x989680;\n\t" \
            "@P1 bra.uni WAIT_DONE_%=;\n\t" \
            "bra.uni WAIT_LOOP_%=;\n\t" \
            "WAIT_DONE_%=:\n\t}" \
            :: "r"(_mbar), "r"(_parity) : "memory"); \
    } \
} while(0)

#define MBARRIER_WAIT_PARITY_RELAXED(mbar_smem_addr, phase_parity) do { \
    uint32_t _mbar = (uint32_t)(mbar_smem_addr); \
    uint32_t _parity = (uint32_t)(phase_parity); \
    uint32_t _done; \
    asm volatile( \
        "{\n\t.reg .pred p;\n\t" \
        "mbarrier.try_wait.parity.relaxed.cta.shared::cta.b64 p, [%1], %2, 0x989680;\n\t" \
        "selp.b32 %0, 1, 0, p;\n\t}" \
        : "=r"(_done) : "r"(_mbar), "r"(_parity) : "memory"); \
    if (!_done) { \
        asm volatile( \
            "{\n\t.reg .pred P1;\n\t" \
            "WAIT_LOOP_%=:\n\t" \
            "mbarrier.try_wait.parity.relaxed.cta.shared::cta.b64 P1, [%0], %1, 0x989680;\n\t" \
            "@P1 bra.uni WAIT_DONE_%=;\n\t" \
            "bra.uni WAIT_LOOP_%=;\n\t" \
            "WAIT_DONE_%=:\n\t}" \
            :: "r"(_mbar), "r"(_parity) : "memory"); \
    } \
} while(0)

__device__ __forceinline__ void tma2d(uint32_t dst, const void* map, int x, int y, uint32_t mbar) {
    asm volatile(
        "cp.async.bulk.tensor.2d.shared::cta.global.tile.mbarrier::complete_tx::bytes "
        "[%0], [%1, {%2, %3}], [%4];"
        :: "r"(dst), "l"(map), "r"(x), "r"(y), "r"(mbar) : "memory");
}

__device__ __forceinline__ void ldsm4(uint32_t* r, uint32_t addr) {
    asm volatile("ldmatrix.sync.aligned.m8n8.x4.shared.b16 {%0,%1,%2,%3}, [%4];"
                 : "=r"(r[0]), "=r"(r[1]), "=r"(r[2]), "=r"(r[3]) : "r"(addr));
}
__device__ __forceinline__ void ldsm4t(uint32_t* r, uint32_t addr) {
    asm volatile("ldmatrix.sync.aligned.m8n8.x4.trans.shared.b16 {%0,%1,%2,%3}, [%4];"
                 : "=r"(r[0]), "=r"(r[1]), "=r"(r[2]), "=r"(r[3]) : "r"(addr));
}

__device__ __forceinline__ void mma_bf16(float* d, const uint32_t* a, uint32_t b0, uint32_t b1) {
    asm volatile(
        "mma.sync.aligned.m16n8k16.row.col.f32.bf16.bf16.f32 "
        "{%0,%1,%2,%3}, {%4,%5,%6,%7}, {%8,%9}, {%0,%1,%2,%3};"
        : "+f"(d[0]), "+f"(d[1]), "+f"(d[2]), "+f"(d[3])
        : "r"(a[0]), "r"(a[1]), "r"(a[2]), "r"(a[3]), "r"(b0), "r"(b1));
}

__device__ __forceinline__ uint32_t pack2bf(float a, float b) {
    __nv_bfloat162 t = __floats2bfloat162_rn(a, b);
    return *reinterpret_cast<uint32_t*>(&t);
}

// Fast exp on the FMA pipe (no MUFU). Valid for x <= 0 (clamped below -80).
__device__ __forceinline__ float fexp(float x) {
    x = fmaxf(x, -80.0f);
    float t = x * 1.4426950408889634f;
    float z = t + 12582912.0f;
    int n = __float_as_int(z) - 0x4b400000;
    float f = t - (z - 12582912.0f);
    float u = f * 0.6931471805599453f;
    float r = 1.3888889e-3f;
    r = fmaf(r, u, 8.3333338e-3f);
    r = fmaf(r, u, 4.1666668e-2f);
    r = fmaf(r, u, 1.6666667e-1f);
    r = fmaf(r, u, 0.5f);
    r = fmaf(r, u, 1.0f);
    r = fmaf(r, u, 1.0f);
    return r * __int_as_float((n + 127) << 23);
}

// ---------------------------------------------------------------------------
// bf16x3 GEMM:  C[M,N] = A[M,K] @ B[N,K]^T + bias
// CTA 128x128, 4 warps (2M x 2N), warp tile 64x64 -> 33% less LDSM traffic.
// K-chunk 32 (64B rows, SW64), 3 stages, 2 CTAs/SM.
// ---------------------------------------------------------------------------
#define GSTAGES     3
#define GCHUNKS     64
#define GTILE_BYTES 8192
#define GSTAGE_BYTES (4 * GTILE_BYTES)
#define GSM_DATA    1024
#define GEMM_SMEM   (GSM_DATA + GSTAGES * GSTAGE_BYTES)

template <int MODE>
__global__ __launch_bounds__(128, 2)
void gemm_bf16x3_kernel(const __grid_constant__ CUtensorMap tmAh,
                        const __grid_constant__ CUtensorMap tmAl,
                        const __grid_constant__ CUtensorMap tmBh,
                        const __grid_constant__ CUtensorMap tmBl,
                        const float* __restrict__ bias,
                        float* __restrict__ C,
                        unsigned short* __restrict__ Ch,
                        unsigned short* __restrict__ Cl,
                        int N)
{
    extern __shared__ __align__(1024) char gsm[];
    const uint32_t sb = smem_u32(gsm);
    const int tid = threadIdx.x;
    const int lane = tid & 31;
    const int wid = tid >> 5;          // 0..3
    const int row0 = blockIdx.y * 128;
    const int col0 = blockIdx.x * 128;
    const int wm = (wid & 1) * 64;     // warp M offset
    const int wn = (wid >> 1) * 64;    // warp N offset

    if (tid == 0) {
#pragma unroll
        for (int s = 0; s < GSTAGES; ++s) {
            MBARRIER_INIT(sb + 8 * s, 1);
            MBARRIER_INIT(sb + 24 + 8 * s, 128);
        }
    }
    __syncthreads();

    if (tid == 0) {
#pragma unroll
        for (int p = 0; p < GSTAGES; ++p) {
            const uint32_t st = sb + GSM_DATA + p * GSTAGE_BYTES;
            MBARRIER_EXPECT_TX(sb + 8 * p, GSTAGE_BYTES);
            const int k0 = p * 32;
            tma2d(st,                  &tmAh, k0, row0, sb + 8 * p);
            tma2d(st + GTILE_BYTES,    &tmAl, k0, row0, sb + 8 * p);
            tma2d(st + 2 * GTILE_BYTES,&tmBh, k0, col0, sb + 8 * p);
            tma2d(st + 3 * GTILE_BYTES,&tmBl, k0, col0, sb + 8 * p);
        }
    }

    float acc[4][8][4];
#pragma unroll
    for (int i = 0; i < 4; i++)
#pragma unroll
        for (int j = 0; j < 8; j++)
#pragma unroll
            for (int k = 0; k < 4; k++) acc[i][j][k] = 0.f;

    // SW64 swizzle over 64B rows: mask = (row & 6) << 3
    const uint32_t cbase = (lane >> 4) * 16;
    uint32_t aRB[4], aMask[4], bRB[4], bMask[4];
#pragma unroll
    for (int mt = 0; mt < 4; ++mt) {
        const int r = wm + mt * 16 + (lane & 15);
        aRB[mt] = (uint32_t)r * 64;
        aMask[mt] = (uint32_t)((r & 6) << 3);
    }
#pragma unroll
    for (int j = 0; j < 4; ++j) {
        const int r = wn + j * 16 + (lane & 15);
        bRB[j] = (uint32_t)r * 64;
        bMask[j] = (uint32_t)((r & 6) << 3);
    }

    for (int c = 0; c < GCHUNKS; ++c) {
        const int u = c / 3;
        const int s = c - u * 3;
        MBARRIER_WAIT_PARITY(sb + 8 * s, (uint32_t)(u & 1));

        const uint32_t stA  = sb + GSM_DATA + s * GSTAGE_BYTES;
        const uint32_t stAl = stA + GTILE_BYTES;
        const uint32_t stB  = stA + 2 * GTILE_BYTES;
        const uint32_t stBl = stA + 3 * GTILE_BYTES;

#pragma unroll
        for (int kk = 0; kk < 2; ++kk) {
            const uint32_t kb = cbase + kk * 32;
            uint32_t ah[4][4], al[4][4], bh[4][4], bl[4][4];
#pragma unroll
            for (int mt = 0; mt < 4; ++mt) {
                ldsm4(ah[mt], stA  + aRB[mt] + (kb ^ aMask[mt]));
                ldsm4(al[mt], stAl + aRB[mt] + (kb ^ aMask[mt]));
            }
#pragma unroll
            for (int j = 0; j < 4; ++j) {
                ldsm4(bh[j], stB  + bRB[j] + (kb ^ bMask[j]));
                ldsm4(bl[j], stBl + bRB[j] + (kb ^ bMask[j]));
            }
            // term-pass 1: hi*hi (32 independent MMAs)
#pragma unroll
            for (int mt = 0; mt < 4; ++mt)
#pragma unroll
                for (int j = 0; j < 4; ++j) {
                    mma_bf16(acc[mt][2 * j],     ah[mt], bh[j][0], bh[j][2]);
                    mma_bf16(acc[mt][2 * j + 1], ah[mt], bh[j][1], bh[j][3]);
                }
            // term-pass 2: hi*lo
#pragma unroll
            for (int mt = 0; mt < 4; ++mt)
#pragma unroll
                for (int j = 0; j < 4; ++j) {
                    mma_bf16(acc[mt][2 * j],     ah[mt], bl[j][0], bl[j][2]);
                    mma_bf16(acc[mt][2 * j + 1], ah[mt], bl[j][1], bl[j][3]);
                }
            // term-pass 3: lo*hi
#pragma unroll
            for (int mt = 0; mt < 4; ++mt)
#pragma unroll
                for (int j = 0; j < 4; ++j) {
                    mma_bf16(acc[mt][2 * j],     al[mt], bh[j][0], bh[j][2]);
                    mma_bf16(acc[mt][2 * j + 1], al[mt], bh[j][1], bh[j][3]);
                }
        }

        MBARRIER_ARRIVE(sb + 24 + 8 * s);

        const int p = c + GSTAGES;
        if (tid == 0 && p < GCHUNKS) {
            const int up = p / 3;
            MBARRIER_WAIT_PARITY_RELAXED(sb + 24 + 8 * s, (uint32_t)((up & 1) ^ 1));
            const uint32_t st = sb + GSM_DATA + s * GSTAGE_BYTES;
            MBARRIER_EXPECT_TX(sb + 8 * s, GSTAGE_BYTES);
            const int k0 = p * 32;
            tma2d(st,                   &tmAh, k0, row0, sb + 8 * s);
            tma2d(st + GTILE_BYTES,     &tmAl, k0, row0, sb + 8 * s);
            tma2d(st + 2 * GTILE_BYTES, &tmBh, k0, col0, sb + 8 * s);
            tma2d(st + 3 * GTILE_BYTES, &tmBl, k0, col0, sb + 8 * s);
        }
    }

    // Epilogue
    const int rr = lane >> 2;
    const int cc = (lane & 3) * 2;
#pragma unroll
    for (int mt = 0; mt < 4; ++mt) {
        const int mrow = row0 + wm + mt * 16 + rr;
#pragma unroll
        for (int nt = 0; nt < 8; ++nt) {
            const int n = col0 + wn + nt * 8 + cc;
            const float2 bb = *(const float2*)(bias + n);
            float v00 = acc[mt][nt][0] + bb.x, v01 = acc[mt][nt][1] + bb.y;
            float v10 = acc[mt][nt][2] + bb.x, v11 = acc[mt][nt][3] + bb.y;
            if (MODE == 0) {
                *(float2*)(C + (size_t)mrow * N + n) = make_float2(v00, v01);
                *(float2*)(C + (size_t)(mrow + 8) * N + n) = make_float2(v10, v11);
            } else {
                const float sc = (n < 2048) ? QSCALE : 1.0f;
                v00 *= sc; v01 *= sc; v10 *= sc; v11 *= sc;
                float h00 = __bfloat162float(__float2bfloat16(v00));
                float h01 = __bfloat162float(__float2bfloat16(v01));
                float h10 = __bfloat162float(__float2bfloat16(v10));
                float h11 = __bfloat162float(__float2bfloat16(v11));
                *(uint32_t*)(Ch + (size_t)mrow * N + n)       = pack2bf(h00, h01);
                *(uint32_t*)(Cl + (size_t)mrow * N + n)       = pack2bf(v00 - h00, v01 - h01);
                *(uint32_t*)(Ch + (size_t)(mrow + 8) * N + n) = pack2bf(h10, h11);
                *(uint32_t*)(Cl + (size_t)(mrow + 8) * N + n) = pack2bf(v10 - h10, v11 - h11);
            }
        }
    }
}

// ---------------------------------------------------------------------------
// Differential flash attention (R4 config: key-block 64, Q in regs, 1 CTA/SM)
// Grid: (S/128, B*H, 2 streams). 8 warps, each warp 16 q-rows.
// ---------------------------------------------------------------------------
#define AT_STAGE_BYTES 49152           // Kh 8K | Kl 8K | Vh 16K | Vl 16K
#define AT_SMEM (49152 + 2 * AT_STAGE_BYTES)   // 147456

__global__ __launch_bounds__(256, 1)
void diff_attn_mma_kernel(const __grid_constant__ CUtensorMap tmQh,
                          const __grid_constant__ CUtensorMap tmQl,
                          const __grid_constant__ CUtensorMap tmKh,
                          const __grid_constant__ CUtensorMap tmKl,
                          const float* __restrict__ amask,
                          float* __restrict__ o1buf,
                          float* __restrict__ o2buf)
{
    extern __shared__ __align__(1024) char asmem[];
    const uint32_t sb = smem_u32(asmem);
    const int tid = threadIdx.x, lane = tid & 31, w = tid >> 5;
    const int qb = blockIdx.x, bh = blockIdx.y, strm = blockIdx.z;
    const int b = bh >> 4, h = bh & 15;
    const int q0 = qb * 128;
    const int tokbase = b * S_LEN;

    const uint32_t MB_Q = sb, MB_F0 = sb + 8, MB_F1 = sb + 16, MB_E0 = sb + 24, MB_E1 = sb + 32;
    float* maskSm = (float*)(asmem + 64);
    const uint32_t QH = sb + 16384, QL = QH + 16384;
    const uint32_t ST0 = sb + 49152;

    if (tid == 0) {
        MBARRIER_INIT(MB_Q, 1);
        MBARRIER_INIT(MB_F0, 1); MBARRIER_INIT(MB_F1, 1);
        MBARRIER_INIT(MB_E0, 256); MBARRIER_INIT(MB_E1, 256);
    }
    {
        const float4* mp = (const float4*)(amask + tokbase);
        float4* ms = (float4*)maskSm;
#pragma unroll
        for (int i = tid; i < 512; i += 256) {
            float4 v = mp[i];
            v.x = (1.f - v.x) * -10000.f;
            v.y = (1.f - v.y) * -10000.f;
            v.z = (1.f - v.z) * -10000.f;
            v.w = (1.f - v.w) * -10000.f;
            ms[i] = v;
        }
    }
    __syncthreads();

    const int qcol = strm * 1024 + h * 64;
    const int kcol = 2048 + strm * 1024 + h * 64;
    const int vcol = 4096 + h * 128;

    if (tid == 0) {
        MBARRIER_EXPECT_TX(MB_Q, 32768);
        tma2d(QH, &tmQh, qcol, tokbase + q0, MB_Q);
        tma2d(QL, &tmQl, qcol, tokbase + q0, MB_Q);
#pragma unroll
        for (int s = 0; s < 2; ++s) {
            const uint32_t st = ST0 + s * AT_STAGE_BYTES;
            const uint32_t fb = s ? MB_F1 : MB_F0;
            MBARRIER_EXPECT_TX(fb, AT_STAGE_BYTES);
            const int k0 = tokbase + s * 64;
            tma2d(st,         &tmKh, kcol,      k0, fb);
            tma2d(st + 8192,  &tmKl, kcol,      k0, fb);
            tma2d(st + 16384, &tmKh, vcol,      k0, fb);
            tma2d(st + 24576, &tmKh, vcol + 64, k0, fb);
            tma2d(st + 32768, &tmKl, vcol,      k0, fb);
            tma2d(st + 40960, &tmKl, vcol + 64, k0, fb);
        }
    }

    // Q fragments (held in regs for the whole kernel)
    MBARRIER_WAIT_PARITY(MB_Q, 0);
    uint32_t qh[4][4], ql[4][4];
    {
        const int r = 16 * w + (lane & 15);
        const uint32_t rb = (uint32_t)r * 128;
        const uint32_t msk = (uint32_t)((r & 7) << 4);
        const uint32_t cbq = (uint32_t)(lane >> 4) * 16;
#pragma unroll
        for (int kk = 0; kk < 4; ++kk) {
            ldsm4(qh[kk], QH + rb + ((cbq + kk * 32) ^ msk));
            ldsm4(ql[kk], QL + rb + ((cbq + kk * 32) ^ msk));
        }
    }

    float o[16][4];
#pragma unroll
    for (int i = 0; i < 16; i++)
#pragma unroll
        for (int j = 0; j < 4; j++) o[i][j] = 0.f;
    float m0 = -1e30f, m1 = -1e30f, l0 = 0.f, l1 = 0.f;

    uint32_t kRB[4], kMask[4];
#pragma unroll
    for (int g = 0; g < 4; ++g) {
        const int r = 16 * g + (lane & 15);
        kRB[g] = (uint32_t)r * 128;
        kMask[g] = (uint32_t)((r & 7) << 4);
    }
    const uint32_t cb = (uint32_t)(lane >> 4) * 16;

    for (int kb = 0; kb < 32; ++kb) {
        const int s = kb & 1, u = kb >> 1;
        const uint32_t FULL = s ? MB_F1 : MB_F0;
        const uint32_t EMPTY = s ? MB_E1 : MB_E0;
        const uint32_t ST = ST0 + s * AT_STAGE_BYTES;
        MBARRIER_WAIT_PARITY(FULL, (uint32_t)(u & 1));

        // ---- scores: 3-term bf16 split MMA ----
        float scf[8][4];
#pragma unroll
        for (int t = 0; t < 8; t++)
#pragma unroll
            for (int j = 0; j < 4; j++) scf[t][j] = 0.f;

#pragma unroll
        for (int kk = 0; kk < 4; ++kk) {
            uint32_t kh[4][4], kl[4][4];
#pragma unroll
            for (int g = 0; g < 4; ++g) {
                const uint32_t a = cb + kk * 32;
                ldsm4(kh[g], ST + kRB[g] + (a ^ kMask[g]));
                ldsm4(kl[g], ST + 8192 + kRB[g] + (a ^ kMask[g]));
            }
#pragma unroll
            for (int g = 0; g < 4; ++g) {
                mma_bf16(scf[2 * g],     qh[kk], kh[g][0], kh[g][2]);
                mma_bf16(scf[2 * g + 1], qh[kk], kh[g][1], kh[g][3]);
            }
#pragma unroll
            for (int g = 0; g < 4; ++g) {
                mma_bf16(scf[2 * g],     qh[kk], kl[g][0], kl[g][2]);
                mma_bf16(scf[2 * g + 1], qh[kk], kl[g][1], kl[g][3]);
            }
#pragma unroll
            for (int g = 0; g < 4; ++g) {
                mma_bf16(scf[2 * g],     ql[kk], kh[g][0], kh[g][2]);
                mma_bf16(scf[2 * g + 1], ql[kk], kh[g][1], kh[g][3]);
            }
        }

        // ---- mask + dual-row online softmax ----
        const int kbase = kb * 64 + 2 * (lane & 3);
        float nm0 = m0, nm1 = m1;
#pragma unroll
        for (int t = 0; t < 8; ++t) {
            const float mv0 = maskSm[kbase + 8 * t];
            const float mv1 = maskSm[kbase + 8 * t + 1];
            scf[t][0] += mv0; scf[t][1] += mv1;
            scf[t][2] += mv0; scf[t][3] += mv1;
            nm0 = fmaxf(nm0, fmaxf(scf[t][0], scf[t][1]));
            nm1 = fmaxf(nm1, fmaxf(scf[t][2], scf[t][3]));
        }
        nm0 = fmaxf(nm0, __shfl_xor_sync(0xffffffffu, nm0, 1));
        nm0 = fmaxf(nm0, __shfl_xor_sync(0xffffffffu, nm0, 2));
        nm1 = fmaxf(nm1, __shfl_xor_sync(0xffffffffu, nm1, 1));
        nm1 = fmaxf(nm1, __shfl_xor_sync(0xffffffffu, nm1, 2));
        const float a0 = fexp(m0 - nm0), a1 = fexp(m1 - nm1);
        m0 = nm0; m1 = nm1;
#pragma unroll
        for (int nt = 0; nt < 16; ++nt) {
            o[nt][0] *= a0; o[nt][1] *= a0;
            o[nt][2] *= a1; o[nt][3] *= a1;
        }

        uint32_t pha[4][4], pla[4][4];
        float rs0 = 0.f, rs1 = 0.f;
#pragma unroll
        for (int t = 0; t < 8; ++t) {
            const float e0 = fexp(scf[t][0] - m0), e1 = fexp(scf[t][1] - m0);
            const float e2 = fexp(scf[t][2] - m1), e3 = fexp(scf[t][3] - m1);
            rs0 += e0 + e1; rs1 += e2 + e3;
            const float h0 = __bfloat162float(__float2bfloat16(e0));
            const float h1 = __bfloat162float(__float2bfloat16(e1));
            const float h2 = __bfloat162float(__float2bfloat16(e2));
            const float h3 = __bfloat162float(__float2bfloat16(e3));
            pha[t >> 1][2 * (t & 1)]     = pack2bf(h0, h1);
            pha[t >> 1][2 * (t & 1) + 1] = pack2bf(h2, h3);
            pla[t >> 1][2 * (t & 1)]     = pack2bf(e0 - h0, e1 - h1);
            pla[t >> 1][2 * (t & 1) + 1] = pack2bf(e2 - h2, e3 - h3);
        }
        rs0 += __shfl_xor_sync(0xffffffffu, rs0, 1);
        rs0 += __shfl_xor_sync(0xffffffffu, rs0, 2);
        rs1 += __shfl_xor_sync(0xffffffffu, rs1, 1);
        rs1 += __shfl_xor_sync(0xffffffffu, rs1, 2);
        l0 = l0 * a0 + rs0;
        l1 = l1 * a1 + rs1;

        // ---- PV: 3-term split, V via trans ldmatrix ----
#pragma unroll
        for (int kk = 0; kk < 4; ++kk) {
            const int r = 16 * kk + (lane & 15);
            const uint32_t vrb = (uint32_t)r * 128;
            const uint32_t vmsk = (uint32_t)((r & 7) << 4);
#pragma unroll
            for (int g = 0; g < 8; ++g) {
                const uint32_t base = ST + 16384 + ((g >> 2) ? 8192u : 0u);
                const uint32_t a = ((uint32_t)((g & 3) * 32) + cb) ^ vmsk;
                uint32_t vh[4], vl[4];
                ldsm4t(vh, base + vrb + a);
                ldsm4t(vl, base + 16384 + vrb + a);
                mma_bf16(o[2 * g],     pha[kk], vh[0], vh[1]);
                mma_bf16(o[2 * g],     pla[kk], vh[0], vh[1]);
                mma_bf16(o[2 * g],     pha[kk], vl[0], vl[1]);
                mma_bf16(o[2 * g + 1], pha[kk], vh[2], vh[3]);
                mma_bf16(o[2 * g + 1], pla[kk], vh[2], vh[3]);
                mma_bf16(o[2 * g + 1], pha[kk], vl[2], vl[3]);
            }
        }

        MBARRIER_ARRIVE(EMPTY);

        if (tid == 0 && kb + 2 < 32) {
            const int p = kb + 2;
            MBARRIER_WAIT_PARITY_RELAXED(EMPTY, (uint32_t)((((p >> 1) & 1) ^ 1)));
            MBARRIER_EXPECT_TX(FULL, AT_STAGE_BYTES);
            const int k0 = tokbase + p * 64;
            tma2d(ST,         &tmKh, kcol,      k0, FULL);
            tma2d(ST + 8192,  &tmKl, kcol,      k0, FULL);
            tma2d(ST + 16384, &tmKh, vcol,      k0, FULL);
            tma2d(ST + 24576, &tmKh, vcol + 64, k0, FULL);
            tma2d(ST + 32768, &tmKl, vcol,      k0, FULL);
            tma2d(ST + 40960, &tmKl, vcol + 64, k0, FULL);
        }
    }

    // ---- normalize + store ----
    const float inv0 = 1.f / l0, inv1 = 1.f / l1;
    float* ob = strm ? o2buf : o1buf;
    const int row = tokbase + q0 + 16 * w + (lane >> 2);
    float* p0 = ob + (size_t)row * DMODEL + h * 128 + 2 * (lane & 3);
    float* p1 = p0 + 8 * DMODEL;
#pragma unroll
    for (int nt = 0; nt < 16; ++nt) {
        *(float2*)(p0 + 8 * nt) = make_float2(o[nt][0] * inv0, o[nt][1] * inv0);
        *(float2*)(p1 + 8 * nt) = make_float2(o[nt][2] * inv1, o[nt][3] * inv1);
    }
}

// ---------------------------------------------------------------------------
// combine (o1 - lam*o2) + bf16 hi/lo split
// ---------------------------------------------------------------------------
__global__ __launch_bounds__(256)
void combine_split_kernel(const float4* __restrict__ o1, const float4* __restrict__ o2,
                          const float* __restrict__ lamp,
                          uint2* __restrict__ hi, uint2* __restrict__ lo, int n4)
{
    int i = blockIdx.x * blockDim.x + threadIdx.x;
    if (i >= n4) return;
    const float lam = *lamp;
    float4 a = o1[i], c = o2[i];
    float v0 = a.x - lam * c.x, v1 = a.y - lam * c.y;
    float v2 = a.z - lam * c.z, v3 = a.w - lam * c.w;
    float h0 = __bfloat162float(__float2bfloat16(v0));
    float h1 = __bfloat162float(__float2bfloat16(v1));
    float h2 = __bfloat162float(__float2bfloat16(v2));
    float h3 = __bfloat162float(__float2bfloat16(v3));
    uint2 H, L;
    H.x = pack2bf(h0, h1); H.y = pack2bf(h2, h3);
    L.x = pack2bf(v0 - h0, v1 - h1); L.y = pack2bf(v2 - h2, v3 - h3);
    hi[i] = H;
    lo[i] = L;
}

__global__ __launch_bounds__(256)
void split_kernel(const float4* __restrict__ x, uint2* __restrict__ hi,
                  uint2* __restrict__ lo, int n4)
{
    int i = blockIdx.x * blockDim.x + threadIdx.x;
    if (i >= n4) return;
    float4 v = x[i];
    float h0 = __bfloat162float(__float2bfloat16(v.x));
    float h1 = __bfloat162float(__float2bfloat16(v.y));
    float h2 = __bfloat162float(__float2bfloat16(v.z));
    float h3 = __bfloat162float(__float2bfloat16(v.w));
    uint2 H, L;
    H.x = pack2bf(h0, h1); H.y = pack2bf(h2, h3);
    L.x = pack2bf(v.x - h0, v.y - h1); L.y = pack2bf(v.z - h2, v.w - h3);
    hi[i] = H;
    lo[i] = L;
}

__global__ __launch_bounds__(256)
void splitT_kernel(const float* __restrict__ W, __nv_bfloat16* __restrict__ hiT,
                   __nv_bfloat16* __restrict__ loT, int K, int N)
{
    __shared__ float t[32][33];
    const int tx = threadIdx.x, ty = threadIdx.y;
    const int n0 = blockIdx.x * 32, k0 = blockIdx.y * 32;
#pragma unroll
    for (int r = 0; r < 4; ++r)
        t[ty + 8 * r][tx] = W[(size_t)(k0 + ty + 8 * r) * N + n0 + tx];
    __syncthreads();
#pragma unroll
    for (int r = 0; r < 4; ++r) {
        const int nn = ty + 8 * r;
        float v = t[tx][nn];
        __nv_bfloat16 hbf = __float2bfloat16(v);
        __nv_bfloat16 lbf = __float2bfloat16(v - __bfloat162float(hbf));
        const size_t off = (size_t)(n0 + nn) * K + k0 + tx;
        hiT[off] = hbf;
        loT[off] = lbf;
    }
}

// ---------------------------------------------------------------------------
// Host side
// ---------------------------------------------------------------------------
typedef CUresult (*PFN_tmEncode)(
    CUtensorMap*, CUtensorMapDataType, cuuint32_t, void*,
    const cuuint64_t*, const cuuint64_t*, const cuuint32_t*, const cuuint32_t*,
    CUtensorMapInterleave, CUtensorMapSwizzle, CUtensorMapL2promotion,
    CUtensorMapFloatOOBfill);

static void make_map(PFN_tmEncode fn, CUtensorMap* m, void* ptr,
                     unsigned long long rows, unsigned long long cols,
                     unsigned box0, unsigned box1, CUtensorMapSwizzle sw)
{
    cuuint64_t dims[2]    = {(cuuint64_t)cols, (cuuint64_t)rows};
    cuuint64_t strides[1] = {(cuuint64_t)cols * 2};
    cuuint32_t box[2]     = {box0, box1};
    cuuint32_t es[2]      = {1u, 1u};
    fn(m, CU_TENSOR_MAP_DATA_TYPE_BFLOAT16, 2, ptr, dims, strides, box, es,
       CU_TENSOR_MAP_INTERLEAVE_NONE, sw,
       CU_TENSOR_MAP_L2_PROMOTION_L2_128B, CU_TENSOR_MAP_FLOAT_OOB_FILL_NONE);
}

extern "C" void kernel_launch(void* const* d_in, const int* in_sizes, int n_in,
                              void* d_out, int out_size)
{
    const float* hidden = (const float*)d_in[0];
    const float* amask  = (const float*)d_in[1];
    const float* W_attn = (const float*)d_in[2];
    const float* b_attn = (const float*)d_in[3];
    const float* W_proj = (const float*)d_in[4];
    const float* b_proj = (const float*)d_in[5];
    const float* lam    = (const float*)d_in[6];
    float* out = (float*)d_out;

    void *qkvh, *qkvl, *o1, *o2, *Ah, *Al, *WAh, *WAl, *WPh, *WPl, *Oh, *Ol;
    cudaGetSymbolAddress(&qkvh, g_qkvh); cudaGetSymbolAddress(&qkvl, g_qkvl);
    cudaGetSymbolAddress(&o1, g_o1);     cudaGetSymbolAddress(&o2, g_o2);
    cudaGetSymbolAddress(&Ah, g_Ah);     cudaGetSymbolAddress(&Al, g_Al);
    cudaGetSymbolAddress(&WAh, g_WAh);   cudaGetSymbolAddress(&WAl, g_WAl);
    cudaGetSymbolAddress(&WPh, g_WPh);   cudaGetSymbolAddress(&WPl, g_WPl);
    cudaGetSymbolAddress(&Oh, g_Oh);     cudaGetSymbolAddress(&Ol, g_Ol);

    void* fnp = nullptr;
    cudaDriverEntryPointQueryResult qres;
    cudaGetDriverEntryPointByVersion("cuTensorMapEncodeTiled", &fnp, 12000,
                                     cudaEnableDefault, &qres);
    PFN_tmEncode enc = (PFN_tmEncode)fnp;

    CUtensorMap tAh, tAl, tWAh, tWAl, tWPh, tWPl, tOh, tOl;
    CUtensorMap tQh, tQl, tKh, tKl;
    make_map(enc, &tAh,  Ah,  M_TOK, KDIM, 32, 128, CU_TENSOR_MAP_SWIZZLE_64B);
    make_map(enc, &tAl,  Al,  M_TOK, KDIM, 32, 128, CU_TENSOR_MAP_SWIZZLE_64B);
    make_map(enc, &tWAh, WAh, N_QKV, KDIM, 32, 128, CU_TENSOR_MAP_SWIZZLE_64B);
    make_map(enc, &tWAl, WAl, N_QKV, KDIM, 32, 128, CU_TENSOR_MAP_SWIZZLE_64B);
    make_map(enc, &tWPh, WPh, DMODEL, KDIM, 32, 128, CU_TENSOR_MAP_SWIZZLE_64B);
    make_map(enc, &tWPl, WPl, DMODEL, KDIM, 32, 128, CU_TENSOR_MAP_SWIZZLE_64B);
    make_map(enc, &tOh,  Oh,  M_TOK, KDIM, 32, 128, CU_TENSOR_MAP_SWIZZLE_64B);
    make_map(enc, &tOl,  Ol,  M_TOK, KDIM, 32, 128, CU_TENSOR_MAP_SWIZZLE_64B);
    make_map(enc, &tQh,  qkvh, M_TOK, N_QKV, 64, 128, CU_TENSOR_MAP_SWIZZLE_128B);
    make_map(enc, &tQl,  qkvl, M_TOK, N_QKV, 64, 128, CU_TENSOR_MAP_SWIZZLE_128B);
    make_map(enc, &tKh,  qkvh, M_TOK, N_QKV, 64, 64, CU_TENSOR_MAP_SWIZZLE_128B);
    make_map(enc, &tKl,  qkvl, M_TOK, N_QKV, 64, 64, CU_TENSOR_MAP_SWIZZLE_128B);

    cudaFuncSetAttribute(gemm_bf16x3_kernel<0>,
                         cudaFuncAttributeMaxDynamicSharedMemorySize, GEMM_SMEM);
    cudaFuncSetAttribute(gemm_bf16x3_kernel<1>,
                         cudaFuncAttributeMaxDynamicSharedMemorySize, GEMM_SMEM);
    cudaFuncSetAttribute(diff_attn_mma_kernel,
                         cudaFuncAttributeMaxDynamicSharedMemorySize, AT_SMEM);

    {
        int n4 = (M_TOK * KDIM) / 4;
        split_kernel<<<n4 / 256, 256>>>((const float4*)hidden, (uint2*)Ah, (uint2*)Al, n4);
    }
    {
        dim3 g(N_QKV / 32, KDIM / 32);
        splitT_kernel<<<g, dim3(32, 8)>>>(W_attn, (__nv_bfloat16*)WAh, (__nv_bfloat16*)WAl, KDIM, N_QKV);
    }
    {
        dim3 g(DMODEL / 32, KDIM / 32);
        splitT_kernel<<<g, dim3(32, 8)>>>(W_proj, (__nv_bfloat16*)WPh, (__nv_bfloat16*)WPl, KDIM, DMODEL);
    }
    {
        dim3 g(N_QKV / 128, M_TOK / 128);
        gemm_bf16x3_kernel<1><<<g, 128, GEMM_SMEM>>>(tAh, tAl, tWAh, tWAl, b_attn,
                                                     nullptr, (unsigned short*)qkvh,
                                                     (unsigned short*)qkvl, N_QKV);
    }
    {
        dim3 g(S_LEN / 128, B_SZ * NHEAD, 2);
        diff_attn_mma_kernel<<<g, 256, AT_SMEM>>>(tQh, tQl, tKh, tKl, amask,
                                                  (float*)o1, (float*)o2);
    }
    {
        int n4 = (M_TOK * DMODEL) / 4;
        combine_split_kernel<<<n4 / 256, 256>>>((const float4*)o1, (const float4*)o2,
                                                lam, (uint2*)Oh, (uint2*)Ol, n4);
    }
    {
        dim3 g(DMODEL / 128, M_TOK / 128);
        gemm_bf16x3_kernel<0><<<g, 128, GEMM_SMEM>>>(tOh, tOl, tWPh, tWPl, b_proj,
                                                     out, nullptr, nullptr, DMODEL);
    }
}

// round 8
// speedup vs baseline: 1.2591x; 1.2591x over previous
#include <cuda_runtime.h>
#include <cuda_bf16.h>
#include <cuda_fp16.h>
#include <cuda.h>
#include <cstdint>

// Problem dims (fixed by setup_inputs)
#define B_SZ   2
#define S_LEN  2048
#define DMODEL 2048
#define NHEAD  16
#define M_TOK  (B_SZ * S_LEN)     // 4096
#define N_QKV  (3 * DMODEL)       // 6144
#define KDIM   DMODEL             // 2048
#define QSCALE 0.0883883476483184f

// ---------------- scratch (static device globals: allocation-free) ----------
__device__ unsigned short g_qkvh[(size_t)M_TOK * N_QKV];   // bf16 hi (attention in)
__device__ unsigned short g_qkvl[(size_t)M_TOK * N_QKV];   // bf16 lo
__device__ float g_o1[(size_t)M_TOK * DMODEL];
__device__ float g_o2[(size_t)M_TOK * DMODEL];
__device__ unsigned short g_A16[(size_t)M_TOK * KDIM];     // fp16 hidden
__device__ unsigned short g_WAh[(size_t)N_QKV * KDIM];     // fp16 hi
__device__ unsigned short g_WAl[(size_t)N_QKV * KDIM];     // fp16 lo
__device__ unsigned short g_WPh[(size_t)DMODEL * KDIM];
__device__ unsigned short g_WPl[(size_t)DMODEL * KDIM];
__device__ unsigned short g_O16[(size_t)M_TOK * KDIM];     // fp16 combined attn out

// ---------------------------------------------------------------------------
// PTX helpers (base sm_90 only — no 'a'-gated instructions)
// ---------------------------------------------------------------------------
__device__ __forceinline__ uint32_t smem_u32(const void* p) {
    uint32_t a;
    asm("{ .reg .u64 t; cvta.to.shared.u64 t, %1; cvt.u32.u64 %0, t; }" : "=r"(a) : "l"(p));
    return a;
}

#define MBARRIER_INIT(addr, cnt) \
    asm volatile("mbarrier.init.shared.b64 [%0], %1;" :: "r"((uint32_t)(addr)), "r"((uint32_t)(cnt)) : "memory")

#define MBARRIER_ARRIVE(addr) \
    asm volatile("mbarrier.arrive.shared.b64 _, [%0];" :: "r"((uint32_t)(addr)) : "memory")

#define MBARRIER_EXPECT_TX(addr, bytes) \
    asm volatile("mbarrier.arrive.expect_tx.shared.b64 _, [%0], %1;" :: "r"((uint32_t)(addr)), "r"((uint32_t)(bytes)) : "memory")

#define MBARRIER_WAIT_PARITY(mbar_smem_addr, phase_parity) do { \
    uint32_t _mbar = (uint32_t)(mbar_smem_addr); \
    uint32_t _parity = (uint32_t)(phase_parity); \
    uint32_t _done; \
    asm volatile( \
        "{\n\t.reg .pred p;\n\t" \
        "mbarrier.try_wait.parity.acquire.cta.shared::cta.b64 p, [%1], %2;\n\t" \
        "selp.b32 %0, 1, 0, p;\n\t}" \
        : "=r"(_done) : "r"(_mbar), "r"(_parity) : "memory"); \
    if (!_done) { \
        asm volatile( \
            "{\n\t.reg .pred P1;\n\t" \
            "WAIT_LOOP_%=:\n\t" \
            "mbarrier.try_wait.parity.acquire.cta.shared::cta.b64 P1, [%0], %1, 0x989680;\n\t" \
            "@P1 bra.uni WAIT_DONE_%=;\n\t" \
            "bra.uni WAIT_LOOP_%=;\n\t" \
            "WAIT_DONE_%=:\n\t}" \
            :: "r"(_mbar), "r"(_parity) : "memory"); \
    } \
} while(0)

#define MBARRIER_WAIT_PARITY_RELAXED(mbar_smem_addr, phase_parity) do { \
    uint32_t _mbar = (uint32_t)(mbar_smem_addr); \
    uint32_t _parity = (uint32_t)(phase_parity); \
    uint32_t _done; \
    asm volatile( \
        "{\n\t.reg .pred p;\n\t" \
        "mbarrier.try_wait.parity.relaxed.cta.shared::cta.b64 p, [%1], %2, 0x989680;\n\t" \
        "selp.b32 %0, 1, 0, p;\n\t}" \
        : "=r"(_done) : "r"(_mbar), "r"(_parity) : "memory"); \
    if (!_done) { \
        asm volatile( \
            "{\n\t.reg .pred P1;\n\t" \
            "WAIT_LOOP_%=:\n\t" \
            "mbarrier.try_wait.parity.relaxed.cta.shared::cta.b64 P1, [%0], %1, 0x989680;\n\t" \
            "@P1 bra.uni WAIT_DONE_%=;\n\t" \
            "bra.uni WAIT_LOOP_%=;\n\t" \
            "WAIT_DONE_%=:\n\t}" \
            :: "r"(_mbar), "r"(_parity) : "memory"); \
    } \
} while(0)

__device__ __forceinline__ void tma2d(uint32_t dst, const void* map, int x, int y, uint32_t mbar) {
    asm volatile(
        "cp.async.bulk.tensor.2d.shared::cta.global.tile.mbarrier::complete_tx::bytes "
        "[%0], [%1, {%2, %3}], [%4];"
        :: "r"(dst), "l"(map), "r"(x), "r"(y), "r"(mbar) : "memory");
}

__device__ __forceinline__ void ldsm4(uint32_t* r, uint32_t addr) {
    asm volatile("ldmatrix.sync.aligned.m8n8.x4.shared.b16 {%0,%1,%2,%3}, [%4];"
                 : "=r"(r[0]), "=r"(r[1]), "=r"(r[2]), "=r"(r[3]) : "r"(addr));
}
__device__ __forceinline__ void ldsm4t(uint32_t* r, uint32_t addr) {
    asm volatile("ldmatrix.sync.aligned.m8n8.x4.trans.shared.b16 {%0,%1,%2,%3}, [%4];"
                 : "=r"(r[0]), "=r"(r[1]), "=r"(r[2]), "=r"(r[3]) : "r"(addr));
}

__device__ __forceinline__ void mma_bf16(float* d, const uint32_t* a, uint32_t b0, uint32_t b1) {
    asm volatile(
        "mma.sync.aligned.m16n8k16.row.col.f32.bf16.bf16.f32 "
        "{%0,%1,%2,%3}, {%4,%5,%6,%7}, {%8,%9}, {%0,%1,%2,%3};"
        : "+f"(d[0]), "+f"(d[1]), "+f"(d[2]), "+f"(d[3])
        : "r"(a[0]), "r"(a[1]), "r"(a[2]), "r"(a[3]), "r"(b0), "r"(b1));
}

__device__ __forceinline__ void mma_fp16(float* d, const uint32_t* a, uint32_t b0, uint32_t b1) {
    asm volatile(
        "mma.sync.aligned.m16n8k16.row.col.f32.f16.f16.f32 "
        "{%0,%1,%2,%3}, {%4,%5,%6,%7}, {%8,%9}, {%0,%1,%2,%3};"
        : "+f"(d[0]), "+f"(d[1]), "+f"(d[2]), "+f"(d[3])
        : "r"(a[0]), "r"(a[1]), "r"(a[2]), "r"(a[3]), "r"(b0), "r"(b1));
}

__device__ __forceinline__ uint32_t pack2bf(float a, float b) {
    __nv_bfloat162 t = __floats2bfloat162_rn(a, b);
    return *reinterpret_cast<uint32_t*>(&t);
}
__device__ __forceinline__ uint32_t pack2h(float a, float b) {
    __half2 t = __floats2half2_rn(a, b);
    return *reinterpret_cast<uint32_t*>(&t);
}

// Fast exp on the FMA pipe (no MUFU). Valid for x <= 0 (clamped below -80).
__device__ __forceinline__ float fexp(float x) {
    x = fmaxf(x, -80.0f);
    float t = x * 1.4426950408889634f;
    float z = t + 12582912.0f;
    int n = __float_as_int(z) - 0x4b400000;
    float f = t - (z - 12582912.0f);
    float u = f * 0.6931471805599453f;
    float r = 1.3888889e-3f;
    r = fmaf(r, u, 8.3333338e-3f);
    r = fmaf(r, u, 4.1666668e-2f);
    r = fmaf(r, u, 1.6666667e-1f);
    r = fmaf(r, u, 0.5f);
    r = fmaf(r, u, 1.0f);
    r = fmaf(r, u, 1.0f);
    return r * __int_as_float((n + 127) << 23);
}

// ---------------------------------------------------------------------------
// fp16x2 GEMM:  C[M,N] = A[M,K] @ B[N,K]^T + bias
// A: fp16 single.  B: fp16 (hi, lo) — lo is the subnormal-range residual.
// 2 MMA terms (A*Bh, A*Bl). CTA 128x128, 8 warps 4Mx2N, K-chunk 64, SW128,
// 3-stage TMA. MODE 0: fp32 out.  MODE 1: bf16 hi/lo out, q-cols pre-scaled.
// ---------------------------------------------------------------------------
#define GSTAGES     3
#define GCHUNKS     32                     // K=2048 / 64
#define GTILE_BYTES 16384                  // 128 rows x 64 halves (128B rows)
#define GSTAGE_BYTES (3 * GTILE_BYTES)     // A, Bh, Bl
#define GSM_DATA    1024
#define GEMM_SMEM   (GSM_DATA + GSTAGES * GSTAGE_BYTES)   // 148480

template <int MODE>
__global__ __launch_bounds__(256, 1)
void gemm_fp16x2_kernel(const __grid_constant__ CUtensorMap tmA,
                        const __grid_constant__ CUtensorMap tmBh,
                        const __grid_constant__ CUtensorMap tmBl,
                        const float* __restrict__ bias,
                        float* __restrict__ C,
                        unsigned short* __restrict__ Ch,
                        unsigned short* __restrict__ Cl,
                        int N)
{
    extern __shared__ __align__(1024) char gsm[];
    const uint32_t sb = smem_u32(gsm);
    const int tid = threadIdx.x;
    const int lane = tid & 31;
    const int wid = tid >> 5;
    const int row0 = blockIdx.y * 128;
    const int col0 = blockIdx.x * 128;
    const int wm = (wid & 3) * 32;
    const int wn = (wid >> 2) * 64;

    if (tid == 0) {
#pragma unroll
        for (int s = 0; s < GSTAGES; ++s) {
            MBARRIER_INIT(sb + 8 * s, 1);
            MBARRIER_INIT(sb + 24 + 8 * s, 256);
        }
    }
    __syncthreads();

    if (tid == 0) {
#pragma unroll
        for (int p = 0; p < GSTAGES; ++p) {
            const uint32_t st = sb + GSM_DATA + p * GSTAGE_BYTES;
            MBARRIER_EXPECT_TX(sb + 8 * p, GSTAGE_BYTES);
            const int k0 = p * 64;
            tma2d(st,                   &tmA,  k0, row0, sb + 8 * p);
            tma2d(st + GTILE_BYTES,     &tmBh, k0, col0, sb + 8 * p);
            tma2d(st + 2 * GTILE_BYTES, &tmBl, k0, col0, sb + 8 * p);
        }
    }

    float acc[2][8][4];
#pragma unroll
    for (int i = 0; i < 2; i++)
#pragma unroll
        for (int j = 0; j < 8; j++)
#pragma unroll
            for (int k = 0; k < 4; k++) acc[i][j][k] = 0.f;

    // SW128 over 128B rows: mask = (row & 7) << 4
    const uint32_t cbase = (lane >> 4) * 16;
    uint32_t aRB[2], aMask[2], bRB[4], bMask[4];
#pragma unroll
    for (int mt = 0; mt < 2; ++mt) {
        const int r = wm + mt * 16 + (lane & 15);
        aRB[mt] = (uint32_t)r * 128;
        aMask[mt] = (uint32_t)((r & 7) << 4);
    }
#pragma unroll
    for (int j = 0; j < 4; ++j) {
        const int r = wn + j * 16 + (lane & 15);
        bRB[j] = (uint32_t)r * 128;
        bMask[j] = (uint32_t)((r & 7) << 4);
    }

    for (int c = 0; c < GCHUNKS; ++c) {
        const int u = c / 3;
        const int s = c - u * 3;
        MBARRIER_WAIT_PARITY(sb + 8 * s, (uint32_t)(u & 1));

        const uint32_t stA  = sb + GSM_DATA + s * GSTAGE_BYTES;
        const uint32_t stBh = stA + GTILE_BYTES;
        const uint32_t stBl = stA + 2 * GTILE_BYTES;

#pragma unroll
        for (int kk = 0; kk < 4; ++kk) {
            const uint32_t kb = cbase + kk * 32;
            uint32_t a[2][4], bh[4][4], bl[4][4];
#pragma unroll
            for (int mt = 0; mt < 2; ++mt)
                ldsm4(a[mt], stA + aRB[mt] + (kb ^ aMask[mt]));
#pragma unroll
            for (int j = 0; j < 4; ++j) {
                ldsm4(bh[j], stBh + bRB[j] + (kb ^ bMask[j]));
                ldsm4(bl[j], stBl + bRB[j] + (kb ^ bMask[j]));
            }
            // term-pass 1: A * Bh
#pragma unroll
            for (int mt = 0; mt < 2; ++mt)
#pragma unroll
                for (int j = 0; j < 4; ++j) {
                    mma_fp16(acc[mt][2 * j],     a[mt], bh[j][0], bh[j][2]);
                    mma_fp16(acc[mt][2 * j + 1], a[mt], bh[j][1], bh[j][3]);
                }
            // term-pass 2: A * Bl
#pragma unroll
            for (int mt = 0; mt < 2; ++mt)
#pragma unroll
                for (int j = 0; j < 4; ++j) {
                    mma_fp16(acc[mt][2 * j],     a[mt], bl[j][0], bl[j][2]);
                    mma_fp16(acc[mt][2 * j + 1], a[mt], bl[j][1], bl[j][3]);
                }
        }

        MBARRIER_ARRIVE(sb + 24 + 8 * s);

        const int p = c + GSTAGES;
        if (tid == 0 && p < GCHUNKS) {
            const int up = p / 3;
            MBARRIER_WAIT_PARITY_RELAXED(sb + 24 + 8 * s, (uint32_t)((up & 1) ^ 1));
            const uint32_t st = sb + GSM_DATA + s * GSTAGE_BYTES;
            MBARRIER_EXPECT_TX(sb + 8 * s, GSTAGE_BYTES);
            const int k0 = p * 64;
            tma2d(st,                   &tmA,  k0, row0, sb + 8 * s);
            tma2d(st + GTILE_BYTES,     &tmBh, k0, col0, sb + 8 * s);
            tma2d(st + 2 * GTILE_BYTES, &tmBl, k0, col0, sb + 8 * s);
        }
    }

    // Epilogue
    const int rr = lane >> 2;
    const int cc = (lane & 3) * 2;
#pragma unroll
    for (int mt = 0; mt < 2; ++mt) {
        const int mrow = row0 + wm + mt * 16 + rr;
#pragma unroll
        for (int nt = 0; nt < 8; ++nt) {
            const int n = col0 + wn + nt * 8 + cc;
            const float2 bb = *(const float2*)(bias + n);
            float v00 = acc[mt][nt][0] + bb.x, v01 = acc[mt][nt][1] + bb.y;
            float v10 = acc[mt][nt][2] + bb.x, v11 = acc[mt][nt][3] + bb.y;
            if (MODE == 0) {
                *(float2*)(C + (size_t)mrow * N + n) = make_float2(v00, v01);
                *(float2*)(C + (size_t)(mrow + 8) * N + n) = make_float2(v10, v11);
            } else {
                const float sc = (n < 2048) ? QSCALE : 1.0f;
                v00 *= sc; v01 *= sc; v10 *= sc; v11 *= sc;
                float h00 = __bfloat162float(__float2bfloat16(v00));
                float h01 = __bfloat162float(__float2bfloat16(v01));
                float h10 = __bfloat162float(__float2bfloat16(v10));
                float h11 = __bfloat162float(__float2bfloat16(v11));
                *(uint32_t*)(Ch + (size_t)mrow * N + n)       = pack2bf(h00, h01);
                *(uint32_t*)(Cl + (size_t)mrow * N + n)       = pack2bf(v00 - h00, v01 - h01);
                *(uint32_t*)(Ch + (size_t)(mrow + 8) * N + n) = pack2bf(h10, h11);
                *(uint32_t*)(Cl + (size_t)(mrow + 8) * N + n) = pack2bf(v10 - h10, v11 - h11);
            }
        }
    }
}

// ---------------------------------------------------------------------------
// Differential flash attention (R4 config: bf16x3, key-block 64, Q in regs).
// Grid: (S/128, B*H, 2 streams). 8 warps, each warp 16 q-rows.
// ---------------------------------------------------------------------------
#define AT_STAGE_BYTES 49152           // Kh 8K | Kl 8K | Vh 16K | Vl 16K
#define AT_SMEM (49152 + 2 * AT_STAGE_BYTES)   // 147456

__global__ __launch_bounds__(256, 1)
void diff_attn_mma_kernel(const __grid_constant__ CUtensorMap tmQh,
                          const __grid_constant__ CUtensorMap tmQl,
                          const __grid_constant__ CUtensorMap tmKh,
                          const __grid_constant__ CUtensorMap tmKl,
                          const float* __restrict__ amask,
                          float* __restrict__ o1buf,
                          float* __restrict__ o2buf)
{
    extern __shared__ __align__(1024) char asmem[];
    const uint32_t sb = smem_u32(asmem);
    const int tid = threadIdx.x, lane = tid & 31, w = tid >> 5;
    const int qb = blockIdx.x, bh = blockIdx.y, strm = blockIdx.z;
    const int b = bh >> 4, h = bh & 15;
    const int q0 = qb * 128;
    const int tokbase = b * S_LEN;

    const uint32_t MB_Q = sb, MB_F0 = sb + 8, MB_F1 = sb + 16, MB_E0 = sb + 24, MB_E1 = sb + 32;
    float* maskSm = (float*)(asmem + 64);
    const uint32_t QH = sb + 16384, QL = QH + 16384;
    const uint32_t ST0 = sb + 49152;

    if (tid == 0) {
        MBARRIER_INIT(MB_Q, 1);
        MBARRIER_INIT(MB_F0, 1); MBARRIER_INIT(MB_F1, 1);
        MBARRIER_INIT(MB_E0, 256); MBARRIER_INIT(MB_E1, 256);
    }
    {
        const float4* mp = (const float4*)(amask + tokbase);
        float4* ms = (float4*)maskSm;
#pragma unroll
        for (int i = tid; i < 512; i += 256) {
            float4 v = mp[i];
            v.x = (1.f - v.x) * -10000.f;
            v.y = (1.f - v.y) * -10000.f;
            v.z = (1.f - v.z) * -10000.f;
            v.w = (1.f - v.w) * -10000.f;
            ms[i] = v;
        }
    }
    __syncthreads();

    const int qcol = strm * 1024 + h * 64;
    const int kcol = 2048 + strm * 1024 + h * 64;
    const int vcol = 4096 + h * 128;

    if (tid == 0) {
        MBARRIER_EXPECT_TX(MB_Q, 32768);
        tma2d(QH, &tmQh, qcol, tokbase + q0, MB_Q);
        tma2d(QL, &tmQl, qcol, tokbase + q0, MB_Q);
#pragma unroll
        for (int s = 0; s < 2; ++s) {
            const uint32_t st = ST0 + s * AT_STAGE_BYTES;
            const uint32_t fb = s ? MB_F1 : MB_F0;
            MBARRIER_EXPECT_TX(fb, AT_STAGE_BYTES);
            const int k0 = tokbase + s * 64;
            tma2d(st,         &tmKh, kcol,      k0, fb);
            tma2d(st + 8192,  &tmKl, kcol,      k0, fb);
            tma2d(st + 16384, &tmKh, vcol,      k0, fb);
            tma2d(st + 24576, &tmKh, vcol + 64, k0, fb);
            tma2d(st + 32768, &tmKl, vcol,      k0, fb);
            tma2d(st + 40960, &tmKl, vcol + 64, k0, fb);
        }
    }

    MBARRIER_WAIT_PARITY(MB_Q, 0);
    uint32_t qh[4][4], ql[4][4];
    {
        const int r = 16 * w + (lane & 15);
        const uint32_t rb = (uint32_t)r * 128;
        const uint32_t msk = (uint32_t)((r & 7) << 4);
        const uint32_t cbq = (uint32_t)(lane >> 4) * 16;
#pragma unroll
        for (int kk = 0; kk < 4; ++kk) {
            ldsm4(qh[kk], QH + rb + ((cbq + kk * 32) ^ msk));
            ldsm4(ql[kk], QL + rb + ((cbq + kk * 32) ^ msk));
        }
    }

    float o[16][4];
#pragma unroll
    for (int i = 0; i < 16; i++)
#pragma unroll
        for (int j = 0; j < 4; j++) o[i][j] = 0.f;
    float m0 = -1e30f, m1 = -1e30f, l0 = 0.f, l1 = 0.f;

    uint32_t kRB[4], kMask[4];
#pragma unroll
    for (int g = 0; g < 4; ++g) {
        const int r = 16 * g + (lane & 15);
        kRB[g] = (uint32_t)r * 128;
        kMask[g] = (uint32_t)((r & 7) << 4);
    }
    const uint32_t cb = (uint32_t)(lane >> 4) * 16;

    for (int kb = 0; kb < 32; ++kb) {
        const int s = kb & 1, u = kb >> 1;
        const uint32_t FULL = s ? MB_F1 : MB_F0;
        const uint32_t EMPTY = s ? MB_E1 : MB_E0;
        const uint32_t ST = ST0 + s * AT_STAGE_BYTES;
        MBARRIER_WAIT_PARITY(FULL, (uint32_t)(u & 1));

        float scf[8][4];
#pragma unroll
        for (int t = 0; t < 8; t++)
#pragma unroll
            for (int j = 0; j < 4; j++) scf[t][j] = 0.f;

#pragma unroll
        for (int kk = 0; kk < 4; ++kk) {
            uint32_t kh[4][4], kl[4][4];
#pragma unroll
            for (int g = 0; g < 4; ++g) {
                const uint32_t a = cb + kk * 32;
                ldsm4(kh[g], ST + kRB[g] + (a ^ kMask[g]));
                ldsm4(kl[g], ST + 8192 + kRB[g] + (a ^ kMask[g]));
            }
#pragma unroll
            for (int g = 0; g < 4; ++g) {
                mma_bf16(scf[2 * g],     qh[kk], kh[g][0], kh[g][2]);
                mma_bf16(scf[2 * g + 1], qh[kk], kh[g][1], kh[g][3]);
            }
#pragma unroll
            for (int g = 0; g < 4; ++g) {
                mma_bf16(scf[2 * g],     qh[kk], kl[g][0], kl[g][2]);
                mma_bf16(scf[2 * g + 1], qh[kk], kl[g][1], kl[g][3]);
            }
#pragma unroll
            for (int g = 0; g < 4; ++g) {
                mma_bf16(scf[2 * g],     ql[kk], kh[g][0], kh[g][2]);
                mma_bf16(scf[2 * g + 1], ql[kk], kh[g][1], kh[g][3]);
            }
        }

        const int kbase = kb * 64 + 2 * (lane & 3);
        float nm0 = m0, nm1 = m1;
#pragma unroll
        for (int t = 0; t < 8; ++t) {
            const float mv0 = maskSm[kbase + 8 * t];
            const float mv1 = maskSm[kbase + 8 * t + 1];
            scf[t][0] += mv0; scf[t][1] += mv1;
            scf[t][2] += mv0; scf[t][3] += mv1;
            nm0 = fmaxf(nm0, fmaxf(scf[t][0], scf[t][1]));
            nm1 = fmaxf(nm1, fmaxf(scf[t][2], scf[t][3]));
        }
        nm0 = fmaxf(nm0, __shfl_xor_sync(0xffffffffu, nm0, 1));
        nm0 = fmaxf(nm0, __shfl_xor_sync(0xffffffffu, nm0, 2));
        nm1 = fmaxf(nm1, __shfl_xor_sync(0xffffffffu, nm1, 1));
        nm1 = fmaxf(nm1, __shfl_xor_sync(0xffffffffu, nm1, 2));
        const float a0 = fexp(m0 - nm0), a1 = fexp(m1 - nm1);
        m0 = nm0; m1 = nm1;
#pragma unroll
        for (int nt = 0; nt < 16; ++nt) {
            o[nt][0] *= a0; o[nt][1] *= a0;
            o[nt][2] *= a1; o[nt][3] *= a1;
        }

        uint32_t pha[4][4], pla[4][4];
        float rs0 = 0.f, rs1 = 0.f;
#pragma unroll
        for (int t = 0; t < 8; ++t) {
            const float e0 = fexp(scf[t][0] - m0), e1 = fexp(scf[t][1] - m0);
            const float e2 = fexp(scf[t][2] - m1), e3 = fexp(scf[t][3] - m1);
            rs0 += e0 + e1; rs1 += e2 + e3;
            const float h0 = __bfloat162float(__float2bfloat16(e0));
            const float h1 = __bfloat162float(__float2bfloat16(e1));
            const float h2 = __bfloat162float(__float2bfloat16(e2));
            const float h3 = __bfloat162float(__float2bfloat16(e3));
            pha[t >> 1][2 * (t & 1)]     = pack2bf(h0, h1);
            pha[t >> 1][2 * (t & 1) + 1] = pack2bf(h2, h3);
            pla[t >> 1][2 * (t & 1)]     = pack2bf(e0 - h0, e1 - h1);
            pla[t >> 1][2 * (t & 1) + 1] = pack2bf(e2 - h2, e3 - h3);
        }
        rs0 += __shfl_xor_sync(0xffffffffu, rs0, 1);
        rs0 += __shfl_xor_sync(0xffffffffu, rs0, 2);
        rs1 += __shfl_xor_sync(0xffffffffu, rs1, 1);
        rs1 += __shfl_xor_sync(0xffffffffu, rs1, 2);
        l0 = l0 * a0 + rs0;
        l1 = l1 * a1 + rs1;

#pragma unroll
        for (int kk = 0; kk < 4; ++kk) {
            const int r = 16 * kk + (lane & 15);
            const uint32_t vrb = (uint32_t)r * 128;
            const uint32_t vmsk = (uint32_t)((r & 7) << 4);
#pragma unroll
            for (int g = 0; g < 8; ++g) {
                const uint32_t base = ST + 16384 + ((g >> 2) ? 8192u : 0u);
                const uint32_t a = ((uint32_t)((g & 3) * 32) + cb) ^ vmsk;
                uint32_t vh[4], vl[4];
                ldsm4t(vh, base + vrb + a);
                ldsm4t(vl, base + 16384 + vrb + a);
                mma_bf16(o[2 * g],     pha[kk], vh[0], vh[1]);
                mma_bf16(o[2 * g],     pla[kk], vh[0], vh[1]);
                mma_bf16(o[2 * g],     pha[kk], vl[0], vl[1]);
                mma_bf16(o[2 * g + 1], pha[kk], vh[2], vh[3]);
                mma_bf16(o[2 * g + 1], pla[kk], vh[2], vh[3]);
                mma_bf16(o[2 * g + 1], pha[kk], vl[2], vl[3]);
            }
        }

        MBARRIER_ARRIVE(EMPTY);

        if (tid == 0 && kb + 2 < 32) {
            const int p = kb + 2;
            MBARRIER_WAIT_PARITY_RELAXED(EMPTY, (uint32_t)((((p >> 1) & 1) ^ 1)));
            MBARRIER_EXPECT_TX(FULL, AT_STAGE_BYTES);
            const int k0 = tokbase + p * 64;
            tma2d(ST,         &tmKh, kcol,      k0, FULL);
            tma2d(ST + 8192,  &tmKl, kcol,      k0, FULL);
            tma2d(ST + 16384, &tmKh, vcol,      k0, FULL);
            tma2d(ST + 24576, &tmKh, vcol + 64, k0, FULL);
            tma2d(ST + 32768, &tmKl, vcol,      k0, FULL);
            tma2d(ST + 40960, &tmKl, vcol + 64, k0, FULL);
        }
    }

    const float inv0 = 1.f / l0, inv1 = 1.f / l1;
    float* ob = strm ? o2buf : o1buf;
    const int row = tokbase + q0 + 16 * w + (lane >> 2);
    float* p0 = ob + (size_t)row * DMODEL + h * 128 + 2 * (lane & 3);
    float* p1 = p0 + 8 * DMODEL;
#pragma unroll
    for (int nt = 0; nt < 16; ++nt) {
        *(float2*)(p0 + 8 * nt) = make_float2(o[nt][0] * inv0, o[nt][1] * inv0);
        *(float2*)(p1 + 8 * nt) = make_float2(o[nt][2] * inv1, o[nt][3] * inv1);
    }
}

// ---------------------------------------------------------------------------
// combine (o1 - lam*o2) -> fp16 single (proj GEMM A input)
// ---------------------------------------------------------------------------
__global__ __launch_bounds__(256)
void combine_fp16_kernel(const float4* __restrict__ o1, const float4* __restrict__ o2,
                         const float* __restrict__ lamp, uint2* __restrict__ out16, int n4)
{
    int i = blockIdx.x * blockDim.x + threadIdx.x;
    if (i >= n4) return;
    const float lam = *lamp;
    float4 a = o1[i], c = o2[i];
    uint2 H;
    H.x = pack2h(a.x - lam * c.x, a.y - lam * c.y);
    H.y = pack2h(a.z - lam * c.z, a.w - lam * c.w);
    out16[i] = H;
}

// fp32 -> fp16 single (hidden -> A)
__global__ __launch_bounds__(256)
void tofp16_kernel(const float4* __restrict__ x, uint2* __restrict__ y, int n4)
{
    int i = blockIdx.x * blockDim.x + threadIdx.x;
    if (i >= n4) return;
    float4 v = x[i];
    uint2 H;
    H.x = pack2h(v.x, v.y);
    H.y = pack2h(v.z, v.w);
    y[i] = H;
}

// fp32 W[K][N] -> transposed fp16 hi/lo: hiT[N][K], loT[N][K]
__global__ __launch_bounds__(256)
void splitT16_kernel(const float* __restrict__ W, __half* __restrict__ hiT,
                     __half* __restrict__ loT, int K, int N)
{
    __shared__ float t[32][33];
    const int tx = threadIdx.x, ty = threadIdx.y;
    const int n0 = blockIdx.x * 32, k0 = blockIdx.y * 32;
#pragma unroll
    for (int r = 0; r < 4; ++r)
        t[ty + 8 * r][tx] = W[(size_t)(k0 + ty + 8 * r) * N + n0 + tx];
    __syncthreads();
#pragma unroll
    for (int r = 0; r < 4; ++r) {
        const int nn = ty + 8 * r;
        float v = t[tx][nn];
        __half hh = __float2half_rn(v);
        __half ll = __float2half_rn(v - __half2float(hh));
        const size_t off = (size_t)(n0 + nn) * K + k0 + tx;
        hiT[off] = hh;
        loT[off] = ll;
    }
}

// ---------------------------------------------------------------------------
// Host side
// ---------------------------------------------------------------------------
typedef CUresult (*PFN_tmEncode)(
    CUtensorMap*, CUtensorMapDataType, cuuint32_t, void*,
    const cuuint64_t*, const cuuint64_t*, const cuuint32_t*, const cuuint32_t*,
    CUtensorMapInterleave, CUtensorMapSwizzle, CUtensorMapL2promotion,
    CUtensorMapFloatOOBfill);

static void make_map(PFN_tmEncode fn, CUtensorMap* m, void* ptr,
                     unsigned long long rows, unsigned long long cols,
                     unsigned box0, unsigned box1)
{
    cuuint64_t dims[2]    = {(cuuint64_t)cols, (cuuint64_t)rows};
    cuuint64_t strides[1] = {(cuuint64_t)cols * 2};
    cuuint32_t box[2]     = {box0, box1};
    cuuint32_t es[2]      = {1u, 1u};
    fn(m, CU_TENSOR_MAP_DATA_TYPE_BFLOAT16, 2, ptr, dims, strides, box, es,
       CU_TENSOR_MAP_INTERLEAVE_NONE, CU_TENSOR_MAP_SWIZZLE_128B,
       CU_TENSOR_MAP_L2_PROMOTION_L2_128B, CU_TENSOR_MAP_FLOAT_OOB_FILL_NONE);
}

extern "C" void kernel_launch(void* const* d_in, const int* in_sizes, int n_in,
                              void* d_out, int out_size)
{
    const float* hidden = (const float*)d_in[0];
    const float* amask  = (const float*)d_in[1];
    const float* W_attn = (const float*)d_in[2];
    const float* b_attn = (const float*)d_in[3];
    const float* W_proj = (const float*)d_in[4];
    const float* b_proj = (const float*)d_in[5];
    const float* lam    = (const float*)d_in[6];
    float* out = (float*)d_out;

    void *qkvh, *qkvl, *o1, *o2, *A16, *WAh, *WAl, *WPh, *WPl, *O16;
    cudaGetSymbolAddress(&qkvh, g_qkvh); cudaGetSymbolAddress(&qkvl, g_qkvl);
    cudaGetSymbolAddress(&o1, g_o1);     cudaGetSymbolAddress(&o2, g_o2);
    cudaGetSymbolAddress(&A16, g_A16);
    cudaGetSymbolAddress(&WAh, g_WAh);   cudaGetSymbolAddress(&WAl, g_WAl);
    cudaGetSymbolAddress(&WPh, g_WPh);   cudaGetSymbolAddress(&WPl, g_WPl);
    cudaGetSymbolAddress(&O16, g_O16);

    void* fnp = nullptr;
    cudaDriverEntryPointQueryResult qres;
    cudaGetDriverEntryPointByVersion("cuTensorMapEncodeTiled", &fnp, 12000,
                                     cudaEnableDefault, &qres);
    PFN_tmEncode enc = (PFN_tmEncode)fnp;

    CUtensorMap tA, tWAh, tWAl, tWPh, tWPl, tO;
    CUtensorMap tQh, tQl, tKh, tKl;
    make_map(enc, &tA,   A16, M_TOK, KDIM, 64, 128);
    make_map(enc, &tWAh, WAh, N_QKV, KDIM, 64, 128);
    make_map(enc, &tWAl, WAl, N_QKV, KDIM, 64, 128);
    make_map(enc, &tWPh, WPh, DMODEL, KDIM, 64, 128);
    make_map(enc, &tWPl, WPl, DMODEL, KDIM, 64, 128);
    make_map(enc, &tO,   O16, M_TOK, KDIM, 64, 128);
    make_map(enc, &tQh,  qkvh, M_TOK, N_QKV, 64, 128);
    make_map(enc, &tQl,  qkvl, M_TOK, N_QKV, 64, 128);
    make_map(enc, &tKh,  qkvh, M_TOK, N_QKV, 64, 64);
    make_map(enc, &tKl,  qkvl, M_TOK, N_QKV, 64, 64);

    cudaFuncSetAttribute(gemm_fp16x2_kernel<0>,
                         cudaFuncAttributeMaxDynamicSharedMemorySize, GEMM_SMEM);
    cudaFuncSetAttribute(gemm_fp16x2_kernel<1>,
                         cudaFuncAttributeMaxDynamicSharedMemorySize, GEMM_SMEM);
    cudaFuncSetAttribute(diff_attn_mma_kernel,
                         cudaFuncAttributeMaxDynamicSharedMemorySize, AT_SMEM);

    // 1) hidden -> fp16
    {
        int n4 = (M_TOK * KDIM) / 4;
        tofp16_kernel<<<n4 / 256, 256>>>((const float4*)hidden, (uint2*)A16, n4);
    }
    // 2) split+transpose weights (fp16 hi/lo)
    {
        dim3 g(N_QKV / 32, KDIM / 32);
        splitT16_kernel<<<g, dim3(32, 8)>>>(W_attn, (__half*)WAh, (__half*)WAl, KDIM, N_QKV);
    }
    {
        dim3 g(DMODEL / 32, KDIM / 32);
        splitT16_kernel<<<g, dim3(32, 8)>>>(W_proj, (__half*)WPh, (__half*)WPl, KDIM, DMODEL);
    }
    // 3) QKV GEMM (fp16x2) -> bf16 hi/lo (q pre-scaled)
    {
        dim3 g(N_QKV / 128, M_TOK / 128);
        gemm_fp16x2_kernel<1><<<g, 256, GEMM_SMEM>>>(tA, tWAh, tWAl, b_attn,
                                                     nullptr, (unsigned short*)qkvh,
                                                     (unsigned short*)qkvl, N_QKV);
    }
    // 4) differential attention (bf16x3, both streams)
    {
        dim3 g(S_LEN / 128, B_SZ * NHEAD, 2);
        diff_attn_mma_kernel<<<g, 256, AT_SMEM>>>(tQh, tQl, tKh, tKl, amask,
                                                  (float*)o1, (float*)o2);
    }
    // 5) combine -> fp16
    {
        int n4 = (M_TOK * DMODEL) / 4;
        combine_fp16_kernel<<<n4 / 256, 256>>>((const float4*)o1, (const float4*)o2,
                                               lam, (uint2*)O16, n4);
    }
    // 6) output projection (fp16x2, fp32 out)
    {
        dim3 g(DMODEL / 128, M_TOK / 128);
        gemm_fp16x2_kernel<0><<<g, 256, GEMM_SMEM>>>(tO, tWPh, tWPl, b_proj,
                                                     out, nullptr, nullptr, DMODEL);
    }
}

// round 9
// speedup vs baseline: 1.4716x; 1.1687x over previous
#include <cuda_runtime.h>
#include <cuda_bf16.h>
#include <cuda_fp16.h>
#include <cuda.h>
#include <cstdint>

// Problem dims (fixed by setup_inputs)
#define B_SZ   2
#define S_LEN  2048
#define DMODEL 2048
#define NHEAD  16
#define M_TOK  (B_SZ * S_LEN)     // 4096
#define N_QKV  (3 * DMODEL)       // 6144
#define KDIM   DMODEL             // 2048
#define QSCALE 0.0883883476483184f

// ---------------- scratch (static device globals: allocation-free) ----------
__device__ unsigned short g_qkvh[(size_t)M_TOK * N_QKV];   // fp16 hi (attention in)
__device__ unsigned short g_qkvl[(size_t)M_TOK * N_QKV];   // fp16 lo (K residual)
__device__ float g_o1[(size_t)M_TOK * DMODEL];
__device__ float g_o2[(size_t)M_TOK * DMODEL];
__device__ unsigned short g_A16[(size_t)M_TOK * KDIM];     // fp16 hidden
__device__ unsigned short g_WAh[(size_t)N_QKV * KDIM];     // fp16 hi
__device__ unsigned short g_WAl[(size_t)N_QKV * KDIM];     // fp16 lo
__device__ unsigned short g_WPh[(size_t)DMODEL * KDIM];
__device__ unsigned short g_WPl[(size_t)DMODEL * KDIM];
__device__ unsigned short g_O16[(size_t)M_TOK * KDIM];     // fp16 combined attn out

// ---------------------------------------------------------------------------
// PTX helpers (base sm_90 only — no 'a'-gated instructions)
// ---------------------------------------------------------------------------
__device__ __forceinline__ uint32_t smem_u32(const void* p) {
    uint32_t a;
    asm("{ .reg .u64 t; cvta.to.shared.u64 t, %1; cvt.u32.u64 %0, t; }" : "=r"(a) : "l"(p));
    return a;
}

#define MBARRIER_INIT(addr, cnt) \
    asm volatile("mbarrier.init.shared.b64 [%0], %1;" :: "r"((uint32_t)(addr)), "r"((uint32_t)(cnt)) : "memory")

#define MBARRIER_ARRIVE(addr) \
    asm volatile("mbarrier.arrive.shared.b64 _, [%0];" :: "r"((uint32_t)(addr)) : "memory")

#define MBARRIER_EXPECT_TX(addr, bytes) \
    asm volatile("mbarrier.arrive.expect_tx.shared.b64 _, [%0], %1;" :: "r"((uint32_t)(addr)), "r"((uint32_t)(bytes)) : "memory")

#define MBARRIER_WAIT_PARITY(mbar_smem_addr, phase_parity) do { \
    uint32_t _mbar = (uint32_t)(mbar_smem_addr); \
    uint32_t _parity = (uint32_t)(phase_parity); \
    uint32_t _done; \
    asm volatile( \
        "{\n\t.reg .pred p;\n\t" \
        "mbarrier.try_wait.parity.acquire.cta.shared::cta.b64 p, [%1], %2;\n\t" \
        "selp.b32 %0, 1, 0, p;\n\t}" \
        : "=r"(_done) : "r"(_mbar), "r"(_parity) : "memory"); \
    if (!_done) { \
        asm volatile( \
            "{\n\t.reg .pred P1;\n\t" \
            "WAIT_LOOP_%=:\n\t" \
            "mbarrier.try_wait.parity.acquire.cta.shared::cta.b64 P1, [%0], %1, 0x989680;\n\t" \
            "@P1 bra.uni WAIT_DONE_%=;\n\t" \
            "bra.uni WAIT_LOOP_%=;\n\t" \
            "WAIT_DONE_%=:\n\t}" \
            :: "r"(_mbar), "r"(_parity) : "memory"); \
    } \
} while(0)

#define MBARRIER_WAIT_PARITY_RELAXED(mbar_smem_addr, phase_parity) do { \
    uint32_t _mbar = (uint32_t)(mbar_smem_addr); \
    uint32_t _parity = (uint32_t)(phase_parity); \
    uint32_t _done; \
    asm volatile( \
        "{\n\t.reg .pred p;\n\t" \
        "mbarrier.try_wait.parity.relaxed.cta.shared::cta.b64 p, [%1], %2, 0x989680;\n\t" \
        "selp.b32 %0, 1, 0, p;\n\t}" \
        : "=r"(_done) : "r"(_mbar), "r"(_parity) : "memory"); \
    if (!_done) { \
        asm volatile( \
            "{\n\t.reg .pred P1;\n\t" \
            "WAIT_LOOP_%=:\n\t" \
            "mbarrier.try_wait.parity.relaxed.cta.shared::cta.b64 P1, [%0], %1, 0x989680;\n\t" \
            "@P1 bra.uni WAIT_DONE_%=;\n\t" \
            "bra.uni WAIT_LOOP_%=;\n\t" \
            "WAIT_DONE_%=:\n\t}" \
            :: "r"(_mbar), "r"(_parity) : "memory"); \
    } \
} while(0)

__device__ __forceinline__ void tma2d(uint32_t dst, const void* map, int x, int y, uint32_t mbar) {
    asm volatile(
        "cp.async.bulk.tensor.2d.shared::cta.global.tile.mbarrier::complete_tx::bytes "
        "[%0], [%1, {%2, %3}], [%4];"
        :: "r"(dst), "l"(map), "r"(x), "r"(y), "r"(mbar) : "memory");
}

__device__ __forceinline__ void ldsm4(uint32_t* r, uint32_t addr) {
    asm volatile("ldmatrix.sync.aligned.m8n8.x4.shared.b16 {%0,%1,%2,%3}, [%4];"
                 : "=r"(r[0]), "=r"(r[1]), "=r"(r[2]), "=r"(r[3]) : "r"(addr));
}
__device__ __forceinline__ void ldsm4t(uint32_t* r, uint32_t addr) {
    asm volatile("ldmatrix.sync.aligned.m8n8.x4.trans.shared.b16 {%0,%1,%2,%3}, [%4];"
                 : "=r"(r[0]), "=r"(r[1]), "=r"(r[2]), "=r"(r[3]) : "r"(addr));
}

__device__ __forceinline__ void mma_fp16(float* d, const uint32_t* a, uint32_t b0, uint32_t b1) {
    asm volatile(
        "mma.sync.aligned.m16n8k16.row.col.f32.f16.f16.f32 "
        "{%0,%1,%2,%3}, {%4,%5,%6,%7}, {%8,%9}, {%0,%1,%2,%3};"
        : "+f"(d[0]), "+f"(d[1]), "+f"(d[2]), "+f"(d[3])
        : "r"(a[0]), "r"(a[1]), "r"(a[2]), "r"(a[3]), "r"(b0), "r"(b1));
}

__device__ __forceinline__ uint32_t pack2h(float a, float b) {
    __half2 t = __floats2half2_rn(a, b);
    return *reinterpret_cast<uint32_t*>(&t);
}

// Fast exp on the FMA pipe (no MUFU). Valid for x <= 0 (clamped below -80).
__device__ __forceinline__ float fexp(float x) {
    x = fmaxf(x, -80.0f);
    float t = x * 1.4426950408889634f;
    float z = t + 12582912.0f;
    int n = __float_as_int(z) - 0x4b400000;
    float f = t - (z - 12582912.0f);
    float u = f * 0.6931471805599453f;
    float r = 1.3888889e-3f;
    r = fmaf(r, u, 8.3333338e-3f);
    r = fmaf(r, u, 4.1666668e-2f);
    r = fmaf(r, u, 1.6666667e-1f);
    r = fmaf(r, u, 0.5f);
    r = fmaf(r, u, 1.0f);
    r = fmaf(r, u, 1.0f);
    return r * __int_as_float((n + 127) << 23);
}

// ---------------------------------------------------------------------------
// fp16x2 GEMM:  C[M,N] = A[M,K] @ B[N,K]^T + bias
// A: fp16 single.  B: fp16 (hi, lo residual). 2 MMA terms.
// CTA 128x128, 8 warps 4Mx2N, K-chunk 64, SW128, 3-stage TMA.
// MODE 0: fp32 out.  MODE 1: fp16 hi/lo out, q-cols pre-scaled.
// ---------------------------------------------------------------------------
#define GSTAGES     3
#define GCHUNKS     32
#define GTILE_BYTES 16384
#define GSTAGE_BYTES (3 * GTILE_BYTES)
#define GSM_DATA    1024
#define GEMM_SMEM   (GSM_DATA + GSTAGES * GSTAGE_BYTES)

template <int MODE>
__global__ __launch_bounds__(256, 1)
void gemm_fp16x2_kernel(const __grid_constant__ CUtensorMap tmA,
                        const __grid_constant__ CUtensorMap tmBh,
                        const __grid_constant__ CUtensorMap tmBl,
                        const float* __restrict__ bias,
                        float* __restrict__ C,
                        unsigned short* __restrict__ Ch,
                        unsigned short* __restrict__ Cl,
                        int N)
{
    extern __shared__ __align__(1024) char gsm[];
    const uint32_t sb = smem_u32(gsm);
    const int tid = threadIdx.x;
    const int lane = tid & 31;
    const int wid = tid >> 5;
    const int row0 = blockIdx.y * 128;
    const int col0 = blockIdx.x * 128;
    const int wm = (wid & 3) * 32;
    const int wn = (wid >> 2) * 64;

    if (tid == 0) {
#pragma unroll
        for (int s = 0; s < GSTAGES; ++s) {
            MBARRIER_INIT(sb + 8 * s, 1);
            MBARRIER_INIT(sb + 24 + 8 * s, 256);
        }
    }
    __syncthreads();

    if (tid == 0) {
#pragma unroll
        for (int p = 0; p < GSTAGES; ++p) {
            const uint32_t st = sb + GSM_DATA + p * GSTAGE_BYTES;
            MBARRIER_EXPECT_TX(sb + 8 * p, GSTAGE_BYTES);
            const int k0 = p * 64;
            tma2d(st,                   &tmA,  k0, row0, sb + 8 * p);
            tma2d(st + GTILE_BYTES,     &tmBh, k0, col0, sb + 8 * p);
            tma2d(st + 2 * GTILE_BYTES, &tmBl, k0, col0, sb + 8 * p);
        }
    }

    float acc[2][8][4];
#pragma unroll
    for (int i = 0; i < 2; i++)
#pragma unroll
        for (int j = 0; j < 8; j++)
#pragma unroll
            for (int k = 0; k < 4; k++) acc[i][j][k] = 0.f;

    const uint32_t cbase = (lane >> 4) * 16;
    uint32_t aRB[2], aMask[2], bRB[4], bMask[4];
#pragma unroll
    for (int mt = 0; mt < 2; ++mt) {
        const int r = wm + mt * 16 + (lane & 15);
        aRB[mt] = (uint32_t)r * 128;
        aMask[mt] = (uint32_t)((r & 7) << 4);
    }
#pragma unroll
    for (int j = 0; j < 4; ++j) {
        const int r = wn + j * 16 + (lane & 15);
        bRB[j] = (uint32_t)r * 128;
        bMask[j] = (uint32_t)((r & 7) << 4);
    }

    for (int c = 0; c < GCHUNKS; ++c) {
        const int u = c / 3;
        const int s = c - u * 3;
        MBARRIER_WAIT_PARITY(sb + 8 * s, (uint32_t)(u & 1));

        const uint32_t stA  = sb + GSM_DATA + s * GSTAGE_BYTES;
        const uint32_t stBh = stA + GTILE_BYTES;
        const uint32_t stBl = stA + 2 * GTILE_BYTES;

#pragma unroll
        for (int kk = 0; kk < 4; ++kk) {
            const uint32_t kb = cbase + kk * 32;
            uint32_t a[2][4], bh[4][4], bl[4][4];
#pragma unroll
            for (int mt = 0; mt < 2; ++mt)
                ldsm4(a[mt], stA + aRB[mt] + (kb ^ aMask[mt]));
#pragma unroll
            for (int j = 0; j < 4; ++j) {
                ldsm4(bh[j], stBh + bRB[j] + (kb ^ bMask[j]));
                ldsm4(bl[j], stBl + bRB[j] + (kb ^ bMask[j]));
            }
#pragma unroll
            for (int mt = 0; mt < 2; ++mt)
#pragma unroll
                for (int j = 0; j < 4; ++j) {
                    mma_fp16(acc[mt][2 * j],     a[mt], bh[j][0], bh[j][2]);
                    mma_fp16(acc[mt][2 * j + 1], a[mt], bh[j][1], bh[j][3]);
                }
#pragma unroll
            for (int mt = 0; mt < 2; ++mt)
#pragma unroll
                for (int j = 0; j < 4; ++j) {
                    mma_fp16(acc[mt][2 * j],     a[mt], bl[j][0], bl[j][2]);
                    mma_fp16(acc[mt][2 * j + 1], a[mt], bl[j][1], bl[j][3]);
                }
        }

        MBARRIER_ARRIVE(sb + 24 + 8 * s);

        const int p = c + GSTAGES;
        if (tid == 0 && p < GCHUNKS) {
            const int up = p / 3;
            MBARRIER_WAIT_PARITY_RELAXED(sb + 24 + 8 * s, (uint32_t)((up & 1) ^ 1));
            const uint32_t st = sb + GSM_DATA + s * GSTAGE_BYTES;
            MBARRIER_EXPECT_TX(sb + 8 * s, GSTAGE_BYTES);
            const int k0 = p * 64;
            tma2d(st,                   &tmA,  k0, row0, sb + 8 * s);
            tma2d(st + GTILE_BYTES,     &tmBh, k0, col0, sb + 8 * s);
            tma2d(st + 2 * GTILE_BYTES, &tmBl, k0, col0, sb + 8 * s);
        }
    }

    // Epilogue
    const int rr = lane >> 2;
    const int cc = (lane & 3) * 2;
#pragma unroll
    for (int mt = 0; mt < 2; ++mt) {
        const int mrow = row0 + wm + mt * 16 + rr;
#pragma unroll
        for (int nt = 0; nt < 8; ++nt) {
            const int n = col0 + wn + nt * 8 + cc;
            const float2 bb = *(const float2*)(bias + n);
            float v00 = acc[mt][nt][0] + bb.x, v01 = acc[mt][nt][1] + bb.y;
            float v10 = acc[mt][nt][2] + bb.x, v11 = acc[mt][nt][3] + bb.y;
            if (MODE == 0) {
                *(float2*)(C + (size_t)mrow * N + n) = make_float2(v00, v01);
                *(float2*)(C + (size_t)(mrow + 8) * N + n) = make_float2(v10, v11);
            } else {
                const float sc = (n < 2048) ? QSCALE : 1.0f;
                v00 *= sc; v01 *= sc; v10 *= sc; v11 *= sc;
                float h00 = __half2float(__float2half_rn(v00));
                float h01 = __half2float(__float2half_rn(v01));
                float h10 = __half2float(__float2half_rn(v10));
                float h11 = __half2float(__float2half_rn(v11));
                *(uint32_t*)(Ch + (size_t)mrow * N + n)       = pack2h(h00, h01);
                *(uint32_t*)(Cl + (size_t)mrow * N + n)       = pack2h(v00 - h00, v01 - h01);
                *(uint32_t*)(Ch + (size_t)(mrow + 8) * N + n) = pack2h(h10, h11);
                *(uint32_t*)(Cl + (size_t)(mrow + 8) * N + n) = pack2h(v10 - h10, v11 - h11);
            }
        }
    }
}

// ---------------------------------------------------------------------------
// Differential flash attention, fp16x2.
// Q: fp16 single (in regs).  K: fp16 hi/lo.  V: fp16 single.  P: fp16 hi/lo.
// Scores: 2 MMA terms; PV: 2 MMA terms. Key-block 64, 2 stages.
// Grid: (S/128, B*H, 2 streams). 8 warps, each warp 16 q-rows.
// ---------------------------------------------------------------------------
#define AT_STAGE_BYTES 32768           // Kh 8K | Kl 8K | V 16K
#define AT_SMEM (32768 + 2 * AT_STAGE_BYTES)   // 98304

__global__ __launch_bounds__(256, 1)
void diff_attn_mma_kernel(const __grid_constant__ CUtensorMap tmQ,
                          const __grid_constant__ CUtensorMap tmKh,
                          const __grid_constant__ CUtensorMap tmKl,
                          const float* __restrict__ amask,
                          float* __restrict__ o1buf,
                          float* __restrict__ o2buf)
{
    extern __shared__ __align__(1024) char asmem[];
    const uint32_t sb = smem_u32(asmem);
    const int tid = threadIdx.x, lane = tid & 31, w = tid >> 5;
    const int qb = blockIdx.x, bh = blockIdx.y, strm = blockIdx.z;
    const int b = bh >> 4, h = bh & 15;
    const int q0 = qb * 128;
    const int tokbase = b * S_LEN;

    const uint32_t MB_Q = sb, MB_F0 = sb + 8, MB_F1 = sb + 16, MB_E0 = sb + 24, MB_E1 = sb + 32;
    float* maskSm = (float*)(asmem + 64);            // 8KB
    const uint32_t QH = sb + 16384;                  // 16KB fp16 Q tile
    const uint32_t ST0 = sb + 32768;

    if (tid == 0) {
        MBARRIER_INIT(MB_Q, 1);
        MBARRIER_INIT(MB_F0, 1); MBARRIER_INIT(MB_F1, 1);
        MBARRIER_INIT(MB_E0, 256); MBARRIER_INIT(MB_E1, 256);
    }
    {
        const float4* mp = (const float4*)(amask + tokbase);
        float4* ms = (float4*)maskSm;
#pragma unroll
        for (int i = tid; i < 512; i += 256) {
            float4 v = mp[i];
            v.x = (1.f - v.x) * -10000.f;
            v.y = (1.f - v.y) * -10000.f;
            v.z = (1.f - v.z) * -10000.f;
            v.w = (1.f - v.w) * -10000.f;
            ms[i] = v;
        }
    }
    __syncthreads();

    const int qcol = strm * 1024 + h * 64;
    const int kcol = 2048 + strm * 1024 + h * 64;
    const int vcol = 4096 + h * 128;

    if (tid == 0) {
        MBARRIER_EXPECT_TX(MB_Q, 16384);
        tma2d(QH, &tmQ, qcol, tokbase + q0, MB_Q);
#pragma unroll
        for (int s = 0; s < 2; ++s) {
            const uint32_t st = ST0 + s * AT_STAGE_BYTES;
            const uint32_t fb = s ? MB_F1 : MB_F0;
            MBARRIER_EXPECT_TX(fb, AT_STAGE_BYTES);
            const int k0 = tokbase + s * 64;
            tma2d(st,         &tmKh, kcol,      k0, fb);
            tma2d(st + 8192,  &tmKl, kcol,      k0, fb);
            tma2d(st + 16384, &tmKh, vcol,      k0, fb);
            tma2d(st + 24576, &tmKh, vcol + 64, k0, fb);
        }
    }

    // Q fragments (single fp16, held in regs for the whole kernel)
    MBARRIER_WAIT_PARITY(MB_Q, 0);
    uint32_t qh[4][4];
    {
        const int r = 16 * w + (lane & 15);
        const uint32_t rb = (uint32_t)r * 128;
        const uint32_t msk = (uint32_t)((r & 7) << 4);
        const uint32_t cbq = (uint32_t)(lane >> 4) * 16;
#pragma unroll
        for (int kk = 0; kk < 4; ++kk)
            ldsm4(qh[kk], QH + rb + ((cbq + kk * 32) ^ msk));
    }

    float o[16][4];
#pragma unroll
    for (int i = 0; i < 16; i++)
#pragma unroll
        for (int j = 0; j < 4; j++) o[i][j] = 0.f;
    float m0 = -1e30f, m1 = -1e30f, l0 = 0.f, l1 = 0.f;

    uint32_t kRB[4], kMask[4];
#pragma unroll
    for (int g = 0; g < 4; ++g) {
        const int r = 16 * g + (lane & 15);
        kRB[g] = (uint32_t)r * 128;
        kMask[g] = (uint32_t)((r & 7) << 4);
    }
    const uint32_t cb = (uint32_t)(lane >> 4) * 16;

    for (int kb = 0; kb < 32; ++kb) {
        const int s = kb & 1, u = kb >> 1;
        const uint32_t FULL = s ? MB_F1 : MB_F0;
        const uint32_t EMPTY = s ? MB_E1 : MB_E0;
        const uint32_t ST = ST0 + s * AT_STAGE_BYTES;
        MBARRIER_WAIT_PARITY(FULL, (uint32_t)(u & 1));

        // ---- scores: 2-term fp16 MMA (Q * Kh, Q * Kl) ----
        float scf[8][4];
#pragma unroll
        for (int t = 0; t < 8; t++)
#pragma unroll
            for (int j = 0; j < 4; j++) scf[t][j] = 0.f;

#pragma unroll
        for (int kk = 0; kk < 4; ++kk) {
            uint32_t kh[4][4], kl[4][4];
#pragma unroll
            for (int g = 0; g < 4; ++g) {
                const uint32_t a = cb + kk * 32;
                ldsm4(kh[g], ST + kRB[g] + (a ^ kMask[g]));
                ldsm4(kl[g], ST + 8192 + kRB[g] + (a ^ kMask[g]));
            }
#pragma unroll
            for (int g = 0; g < 4; ++g) {
                mma_fp16(scf[2 * g],     qh[kk], kh[g][0], kh[g][2]);
                mma_fp16(scf[2 * g + 1], qh[kk], kh[g][1], kh[g][3]);
            }
#pragma unroll
            for (int g = 0; g < 4; ++g) {
                mma_fp16(scf[2 * g],     qh[kk], kl[g][0], kl[g][2]);
                mma_fp16(scf[2 * g + 1], qh[kk], kl[g][1], kl[g][3]);
            }
        }

        // ---- mask + dual-row online softmax ----
        const int kbase = kb * 64 + 2 * (lane & 3);
        float nm0 = m0, nm1 = m1;
#pragma unroll
        for (int t = 0; t < 8; ++t) {
            const float mv0 = maskSm[kbase + 8 * t];
            const float mv1 = maskSm[kbase + 8 * t + 1];
            scf[t][0] += mv0; scf[t][1] += mv1;
            scf[t][2] += mv0; scf[t][3] += mv1;
            nm0 = fmaxf(nm0, fmaxf(scf[t][0], scf[t][1]));
            nm1 = fmaxf(nm1, fmaxf(scf[t][2], scf[t][3]));
        }
        nm0 = fmaxf(nm0, __shfl_xor_sync(0xffffffffu, nm0, 1));
        nm0 = fmaxf(nm0, __shfl_xor_sync(0xffffffffu, nm0, 2));
        nm1 = fmaxf(nm1, __shfl_xor_sync(0xffffffffu, nm1, 1));
        nm1 = fmaxf(nm1, __shfl_xor_sync(0xffffffffu, nm1, 2));
        const float a0 = fexp(m0 - nm0), a1 = fexp(m1 - nm1);
        m0 = nm0; m1 = nm1;
#pragma unroll
        for (int nt = 0; nt < 16; ++nt) {
            o[nt][0] *= a0; o[nt][1] *= a0;
            o[nt][2] *= a1; o[nt][3] *= a1;
        }

        uint32_t pha[4][4], pla[4][4];
        float rs0 = 0.f, rs1 = 0.f;
#pragma unroll
        for (int t = 0; t < 8; ++t) {
            const float e0 = fexp(scf[t][0] - m0), e1 = fexp(scf[t][1] - m0);
            const float e2 = fexp(scf[t][2] - m1), e3 = fexp(scf[t][3] - m1);
            rs0 += e0 + e1; rs1 += e2 + e3;
            const float h0 = __half2float(__float2half_rn(e0));
            const float h1 = __half2float(__float2half_rn(e1));
            const float h2 = __half2float(__float2half_rn(e2));
            const float h3 = __half2float(__float2half_rn(e3));
            pha[t >> 1][2 * (t & 1)]     = pack2h(h0, h1);
            pha[t >> 1][2 * (t & 1) + 1] = pack2h(h2, h3);
            pla[t >> 1][2 * (t & 1)]     = pack2h(e0 - h0, e1 - h1);
            pla[t >> 1][2 * (t & 1) + 1] = pack2h(e2 - h2, e3 - h3);
        }
        rs0 += __shfl_xor_sync(0xffffffffu, rs0, 1);
        rs0 += __shfl_xor_sync(0xffffffffu, rs0, 2);
        rs1 += __shfl_xor_sync(0xffffffffu, rs1, 1);
        rs1 += __shfl_xor_sync(0xffffffffu, rs1, 2);
        l0 = l0 * a0 + rs0;
        l1 = l1 * a1 + rs1;

        // ---- PV: 2-term fp16 MMA (Ph * V, Pl * V) ----
#pragma unroll
        for (int kk = 0; kk < 4; ++kk) {
            const int r = 16 * kk + (lane & 15);
            const uint32_t vrb = (uint32_t)r * 128;
            const uint32_t vmsk = (uint32_t)((r & 7) << 4);
#pragma unroll
            for (int g = 0; g < 8; ++g) {
                const uint32_t base = ST + 16384 + ((g >> 2) ? 8192u : 0u);
                const uint32_t a = ((uint32_t)((g & 3) * 32) + cb) ^ vmsk;
                uint32_t vh[4];
                ldsm4t(vh, base + vrb + a);
                mma_fp16(o[2 * g],     pha[kk], vh[0], vh[1]);
                mma_fp16(o[2 * g],     pla[kk], vh[0], vh[1]);
                mma_fp16(o[2 * g + 1], pha[kk], vh[2], vh[3]);
                mma_fp16(o[2 * g + 1], pla[kk], vh[2], vh[3]);
            }
        }

        MBARRIER_ARRIVE(EMPTY);

        if (tid == 0 && kb + 2 < 32) {
            const int p = kb + 2;
            MBARRIER_WAIT_PARITY_RELAXED(EMPTY, (uint32_t)((((p >> 1) & 1) ^ 1)));
            MBARRIER_EXPECT_TX(FULL, AT_STAGE_BYTES);
            const int k0 = tokbase + p * 64;
            tma2d(ST,         &tmKh, kcol,      k0, FULL);
            tma2d(ST + 8192,  &tmKl, kcol,      k0, FULL);
            tma2d(ST + 16384, &tmKh, vcol,      k0, FULL);
            tma2d(ST + 24576, &tmKh, vcol + 64, k0, FULL);
        }
    }

    // ---- normalize + store ----
    const float inv0 = 1.f / l0, inv1 = 1.f / l1;
    float* ob = strm ? o2buf : o1buf;
    const int row = tokbase + q0 + 16 * w + (lane >> 2);
    float* p0 = ob + (size_t)row * DMODEL + h * 128 + 2 * (lane & 3);
    float* p1 = p0 + 8 * DMODEL;
#pragma unroll
    for (int nt = 0; nt < 16; ++nt) {
        *(float2*)(p0 + 8 * nt) = make_float2(o[nt][0] * inv0, o[nt][1] * inv0);
        *(float2*)(p1 + 8 * nt) = make_float2(o[nt][2] * inv1, o[nt][3] * inv1);
    }
}

// ---------------------------------------------------------------------------
// combine (o1 - lam*o2) -> fp16 single (proj GEMM A input)
// ---------------------------------------------------------------------------
__global__ __launch_bounds__(256)
void combine_fp16_kernel(const float4* __restrict__ o1, const float4* __restrict__ o2,
                         const float* __restrict__ lamp, uint2* __restrict__ out16, int n4)
{
    int i = blockIdx.x * blockDim.x + threadIdx.x;
    if (i >= n4) return;
    const float lam = *lamp;
    float4 a = o1[i], c = o2[i];
    uint2 H;
    H.x = pack2h(a.x - lam * c.x, a.y - lam * c.y);
    H.y = pack2h(a.z - lam * c.z, a.w - lam * c.w);
    out16[i] = H;
}

// fp32 -> fp16 single (hidden -> A)
__global__ __launch_bounds__(256)
void tofp16_kernel(const float4* __restrict__ x, uint2* __restrict__ y, int n4)
{
    int i = blockIdx.x * blockDim.x + threadIdx.x;
    if (i >= n4) return;
    float4 v = x[i];
    uint2 H;
    H.x = pack2h(v.x, v.y);
    H.y = pack2h(v.z, v.w);
    y[i] = H;
}

// fp32 W[K][N] -> transposed fp16 hi/lo: hiT[N][K], loT[N][K]
__global__ __launch_bounds__(256)
void splitT16_kernel(const float* __restrict__ W, __half* __restrict__ hiT,
                     __half* __restrict__ loT, int K, int N)
{
    __shared__ float t[32][33];
    const int tx = threadIdx.x, ty = threadIdx.y;
    const int n0 = blockIdx.x * 32, k0 = blockIdx.y * 32;
#pragma unroll
    for (int r = 0; r < 4; ++r)
        t[ty + 8 * r][tx] = W[(size_t)(k0 + ty + 8 * r) * N + n0 + tx];
    __syncthreads();
#pragma unroll
    for (int r = 0; r < 4; ++r) {
        const int nn = ty + 8 * r;
        float v = t[tx][nn];
        __half hh = __float2half_rn(v);
        __half ll = __float2half_rn(v - __half2float(hh));
        const size_t off = (size_t)(n0 + nn) * K + k0 + tx;
        hiT[off] = hh;
        loT[off] = ll;
    }
}

// ---------------------------------------------------------------------------
// Host side
// ---------------------------------------------------------------------------
typedef CUresult (*PFN_tmEncode)(
    CUtensorMap*, CUtensorMapDataType, cuuint32_t, void*,
    const cuuint64_t*, const cuuint64_t*, const cuuint32_t*, const cuuint32_t*,
    CUtensorMapInterleave, CUtensorMapSwizzle, CUtensorMapL2promotion,
    CUtensorMapFloatOOBfill);

static void make_map(PFN_tmEncode fn, CUtensorMap* m, void* ptr,
                     unsigned long long rows, unsigned long long cols,
                     unsigned box0, unsigned box1)
{
    cuuint64_t dims[2]    = {(cuuint64_t)cols, (cuuint64_t)rows};
    cuuint64_t strides[1] = {(cuuint64_t)cols * 2};
    cuuint32_t box[2]     = {box0, box1};
    cuuint32_t es[2]      = {1u, 1u};
    fn(m, CU_TENSOR_MAP_DATA_TYPE_BFLOAT16, 2, ptr, dims, strides, box, es,
       CU_TENSOR_MAP_INTERLEAVE_NONE, CU_TENSOR_MAP_SWIZZLE_128B,
       CU_TENSOR_MAP_L2_PROMOTION_L2_128B, CU_TENSOR_MAP_FLOAT_OOB_FILL_NONE);
}

extern "C" void kernel_launch(void* const* d_in, const int* in_sizes, int n_in,
                              void* d_out, int out_size)
{
    const float* hidden = (const float*)d_in[0];
    const float* amask  = (const float*)d_in[1];
    const float* W_attn = (const float*)d_in[2];
    const float* b_attn = (const float*)d_in[3];
    const float* W_proj = (const float*)d_in[4];
    const float* b_proj = (const float*)d_in[5];
    const float* lam    = (const float*)d_in[6];
    float* out = (float*)d_out;

    void *qkvh, *qkvl, *o1, *o2, *A16, *WAh, *WAl, *WPh, *WPl, *O16;
    cudaGetSymbolAddress(&qkvh, g_qkvh); cudaGetSymbolAddress(&qkvl, g_qkvl);
    cudaGetSymbolAddress(&o1, g_o1);     cudaGetSymbolAddress(&o2, g_o2);
    cudaGetSymbolAddress(&A16, g_A16);
    cudaGetSymbolAddress(&WAh, g_WAh);   cudaGetSymbolAddress(&WAl, g_WAl);
    cudaGetSymbolAddress(&WPh, g_WPh);   cudaGetSymbolAddress(&WPl, g_WPl);
    cudaGetSymbolAddress(&O16, g_O16);

    void* fnp = nullptr;
    cudaDriverEntryPointQueryResult qres;
    cudaGetDriverEntryPointByVersion("cuTensorMapEncodeTiled", &fnp, 12000,
                                     cudaEnableDefault, &qres);
    PFN_tmEncode enc = (PFN_tmEncode)fnp;

    CUtensorMap tA, tWAh, tWAl, tWPh, tWPl, tO;
    CUtensorMap tQ, tKh, tKl;
    make_map(enc, &tA,   A16, M_TOK, KDIM, 64, 128);
    make_map(enc, &tWAh, WAh, N_QKV, KDIM, 64, 128);
    make_map(enc, &tWAl, WAl, N_QKV, KDIM, 64, 128);
    make_map(enc, &tWPh, WPh, DMODEL, KDIM, 64, 128);
    make_map(enc, &tWPl, WPl, DMODEL, KDIM, 64, 128);
    make_map(enc, &tO,   O16, M_TOK, KDIM, 64, 128);
    make_map(enc, &tQ,   qkvh, M_TOK, N_QKV, 64, 128);
    make_map(enc, &tKh,  qkvh, M_TOK, N_QKV, 64, 64);
    make_map(enc, &tKl,  qkvl, M_TOK, N_QKV, 64, 64);

    cudaFuncSetAttribute(gemm_fp16x2_kernel<0>,
                         cudaFuncAttributeMaxDynamicSharedMemorySize, GEMM_SMEM);
    cudaFuncSetAttribute(gemm_fp16x2_kernel<1>,
                         cudaFuncAttributeMaxDynamicSharedMemorySize, GEMM_SMEM);
    cudaFuncSetAttribute(diff_attn_mma_kernel,
                         cudaFuncAttributeMaxDynamicSharedMemorySize, AT_SMEM);

    // 1) hidden -> fp16
    {
        int n4 = (M_TOK * KDIM) / 4;
        tofp16_kernel<<<n4 / 256, 256>>>((const float4*)hidden, (uint2*)A16, n4);
    }
    // 2) split+transpose weights (fp16 hi/lo)
    {
        dim3 g(N_QKV / 32, KDIM / 32);
        splitT16_kernel<<<g, dim3(32, 8)>>>(W_attn, (__half*)WAh, (__half*)WAl, KDIM, N_QKV);
    }
    {
        dim3 g(DMODEL / 32, KDIM / 32);
        splitT16_kernel<<<g, dim3(32, 8)>>>(W_proj, (__half*)WPh, (__half*)WPl, KDIM, DMODEL);
    }
    // 3) QKV GEMM (fp16x2) -> fp16 hi/lo (q pre-scaled)
    {
        dim3 g(N_QKV / 128, M_TOK / 128);
        gemm_fp16x2_kernel<1><<<g, 256, GEMM_SMEM>>>(tA, tWAh, tWAl, b_attn,
                                                     nullptr, (unsigned short*)qkvh,
                                                     (unsigned short*)qkvl, N_QKV);
    }
    // 4) differential attention (fp16x2, both streams)
    {
        dim3 g(S_LEN / 128, B_SZ * NHEAD, 2);
        diff_attn_mma_kernel<<<g, 256, AT_SMEM>>>(tQ, tKh, tKl, amask,
                                                  (float*)o1, (float*)o2);
    }
    // 5) combine -> fp16
    {
        int n4 = (M_TOK * DMODEL) / 4;
        combine_fp16_kernel<<<n4 / 256, 256>>>((const float4*)o1, (const float4*)o2,
                                               lam, (uint2*)O16, n4);
    }
    // 6) output projection (fp16x2, fp32 out)
    {
        dim3 g(DMODEL / 128, M_TOK / 128);
        gemm_fp16x2_kernel<0><<<g, 256, GEMM_SMEM>>>(tO, tWPh, tWPl, b_proj,
                                                     out, nullptr, nullptr, DMODEL);
    }
}

// round 11
// speedup vs baseline: 1.7238x; 1.1714x over previous
#include <cuda_runtime.h>
#include <cuda_bf16.h>
#include <cuda_fp16.h>
#include <cuda.h>
#include <cstdint>

// Problem dims (fixed by setup_inputs)
#define B_SZ   2
#define S_LEN  2048
#define DMODEL 2048
#define NHEAD  16
#define M_TOK  (B_SZ * S_LEN)     // 4096
#define N_QKV  (3 * DMODEL)       // 6144
#define KDIM   DMODEL             // 2048
#define QSCALE 0.0883883476483184f

// ---------------- scratch (static device globals: allocation-free) ----------
__device__ unsigned short g_qkv16[(size_t)M_TOK * N_QKV];  // fp16 qkv (attention in)
__device__ float g_o1[(size_t)M_TOK * DMODEL];
__device__ float g_o2[(size_t)M_TOK * DMODEL];
__device__ unsigned short g_A16[(size_t)M_TOK * KDIM];     // fp16 hidden
__device__ unsigned short g_WAh[(size_t)N_QKV * KDIM];     // fp16 W_attn^T hi
__device__ unsigned short g_WAl[(size_t)N_QKV * KDIM];     // fp16 W_attn^T lo
__device__ unsigned short g_WPh[(size_t)DMODEL * KDIM];    // fp16 W_proj^T hi
__device__ unsigned short g_WPl[(size_t)DMODEL * KDIM];    // fp16 W_proj^T lo
__device__ unsigned short g_O16[(size_t)M_TOK * KDIM];     // fp16 combined attn out

// ---------------------------------------------------------------------------
// PTX helpers (base sm_90 only — no 'a'-gated instructions)
// ---------------------------------------------------------------------------
__device__ __forceinline__ uint32_t smem_u32(const void* p) {
    uint32_t a;
    asm("{ .reg .u64 t; cvta.to.shared.u64 t, %1; cvt.u32.u64 %0, t; }" : "=r"(a) : "l"(p));
    return a;
}

#define MBARRIER_INIT(addr, cnt) \
    asm volatile("mbarrier.init.shared.b64 [%0], %1;" :: "r"((uint32_t)(addr)), "r"((uint32_t)(cnt)) : "memory")

#define MBARRIER_ARRIVE(addr) \
    asm volatile("mbarrier.arrive.shared.b64 _, [%0];" :: "r"((uint32_t)(addr)) : "memory")

#define MBARRIER_EXPECT_TX(addr, bytes) \
    asm volatile("mbarrier.arrive.expect_tx.shared.b64 _, [%0], %1;" :: "r"((uint32_t)(addr)), "r"((uint32_t)(bytes)) : "memory")

#define MBARRIER_WAIT_PARITY(mbar_smem_addr, phase_parity) do { \
    uint32_t _mbar = (uint32_t)(mbar_smem_addr); \
    uint32_t _parity = (uint32_t)(phase_parity); \
    uint32_t _done; \
    asm volatile( \
        "{\n\t.reg .pred p;\n\t" \
        "mbarrier.try_wait.parity.acquire.cta.shared::cta.b64 p, [%1], %2;\n\t" \
        "selp.b32 %0, 1, 0, p;\n\t}" \
        : "=r"(_done) : "r"(_mbar), "r"(_parity) : "memory"); \
    if (!_done) { \
        asm volatile( \
            "{\n\t.reg .pred P1;\n\t" \
            "WAIT_LOOP_%=:\n\t" \
            "mbarrier.try_wait.parity.acquire.cta.shared::cta.b64 P1, [%0], %1, 0x989680;\n\t" \
            "@P1 bra.uni WAIT_DONE_%=;\n\t" \
            "bra.uni WAIT_LOOP_%=;\n\t" \
            "WAIT_DONE_%=:\n\t}" \
            :: "r"(_mbar), "r"(_parity) : "memory"); \
    } \
} while(0)

#define MBARRIER_WAIT_PARITY_RELAXED(mbar_smem_addr, phase_parity) do { \
    uint32_t _mbar = (uint32_t)(mbar_smem_addr); \
    uint32_t _parity = (uint32_t)(phase_parity); \
    uint32_t _done; \
    asm volatile( \
        "{\n\t.reg .pred p;\n\t" \
        "mbarrier.try_wait.parity.relaxed.cta.shared::cta.b64 p, [%1], %2, 0x989680;\n\t" \
        "selp.b32 %0, 1, 0, p;\n\t}" \
        : "=r"(_done) : "r"(_mbar), "r"(_parity) : "memory"); \
    if (!_done) { \
        asm volatile( \
            "{\n\t.reg .pred P1;\n\t" \
            "WAIT_LOOP_%=:\n\t" \
            "mbarrier.try_wait.parity.relaxed.cta.shared::cta.b64 P1, [%0], %1, 0x989680;\n\t" \
            "@P1 bra.uni WAIT_DONE_%=;\n\t" \
            "bra.uni WAIT_LOOP_%=;\n\t" \
            "WAIT_DONE_%=:\n\t}" \
            :: "r"(_mbar), "r"(_parity) : "memory"); \
    } \
} while(0)

__device__ __forceinline__ void tma2d(uint32_t dst, const void* map, int x, int y, uint32_t mbar) {
    asm volatile(
        "cp.async.bulk.tensor.2d.shared::cta.global.tile.mbarrier::complete_tx::bytes "
        "[%0], [%1, {%2, %3}], [%4];"
        :: "r"(dst), "l"(map), "r"(x), "r"(y), "r"(mbar) : "memory");
}

__device__ __forceinline__ void ldsm4(uint32_t* r, uint32_t addr) {
    asm volatile("ldmatrix.sync.aligned.m8n8.x4.shared.b16 {%0,%1,%2,%3}, [%4];"
                 : "=r"(r[0]), "=r"(r[1]), "=r"(r[2]), "=r"(r[3]) : "r"(addr));
}
__device__ __forceinline__ void ldsm4t(uint32_t* r, uint32_t addr) {
    asm volatile("ldmatrix.sync.aligned.m8n8.x4.trans.shared.b16 {%0,%1,%2,%3}, [%4];"
                 : "=r"(r[0]), "=r"(r[1]), "=r"(r[2]), "=r"(r[3]) : "r"(addr));
}

__device__ __forceinline__ void mma_fp16(float* d, const uint32_t* a, uint32_t b0, uint32_t b1) {
    asm volatile(
        "mma.sync.aligned.m16n8k16.row.col.f32.f16.f16.f32 "
        "{%0,%1,%2,%3}, {%4,%5,%6,%7}, {%8,%9}, {%0,%1,%2,%3};"
        : "+f"(d[0]), "+f"(d[1]), "+f"(d[2]), "+f"(d[3])
        : "r"(a[0]), "r"(a[1]), "r"(a[2]), "r"(a[3]), "r"(b0), "r"(b1));
}

__device__ __forceinline__ uint32_t pack2h(float a, float b) {
    __half2 t = __floats2half2_rn(a, b);
    return *reinterpret_cast<uint32_t*>(&t);
}

// Fast exp on the FMA pipe (no MUFU). Valid for x <= 0 (clamped below -80).
__device__ __forceinline__ float fexp(float x) {
    x = fmaxf(x, -80.0f);
    float t = x * 1.4426950408889634f;
    float z = t + 12582912.0f;
    int n = __float_as_int(z) - 0x4b400000;
    float f = t - (z - 12582912.0f);
    float u = f * 0.6931471805599453f;
    float r = 1.3888889e-3f;
    r = fmaf(r, u, 8.3333338e-3f);
    r = fmaf(r, u, 4.1666668e-2f);
    r = fmaf(r, u, 1.6666667e-1f);
    r = fmaf(r, u, 0.5f);
    r = fmaf(r, u, 1.0f);
    r = fmaf(r, u, 1.0f);
    return r * __int_as_float((n + 127) << 23);
}

// ---------------------------------------------------------------------------
// fp16x2 GEMM:  C[M,N] = A[M,K] @ B[N,K]^T + bias
// A: fp16 single.  B: fp16 (hi, lo residual). 2 MMA terms.
// CTA 128x128, 8 warps 4Mx2N, K-chunk 64, SW128, 3-stage TMA.
// MODE 0: fp32 out.  MODE 1: fp16 single out, q-cols pre-scaled.
// ---------------------------------------------------------------------------
#define GCHUNKS     32
#define GTILE_BYTES 16384
#define GSTAGE_BYTES (3 * GTILE_BYTES)
#define GSM_DATA    1024
#define GEMM_SMEM   (GSM_DATA + 3 * GSTAGE_BYTES)

template <int MODE>
__global__ __launch_bounds__(256, 1)
void gemm_fp16x2_kernel(const __grid_constant__ CUtensorMap tmA,
                        const __grid_constant__ CUtensorMap tmBh,
                        const __grid_constant__ CUtensorMap tmBl,
                        const float* __restrict__ bias,
                        float* __restrict__ C,
                        unsigned short* __restrict__ Ch,
                        int N)
{
    extern __shared__ __align__(1024) char gsm[];
    const uint32_t sb = smem_u32(gsm);
    const int tid = threadIdx.x;
    const int lane = tid & 31;
    const int wid = tid >> 5;
    const int row0 = blockIdx.y * 128;
    const int col0 = blockIdx.x * 128;
    const int wm = (wid & 3) * 32;
    const int wn = (wid >> 2) * 64;

    if (tid == 0) {
#pragma unroll
        for (int s = 0; s < 3; ++s) {
            MBARRIER_INIT(sb + 8 * s, 1);
            MBARRIER_INIT(sb + 24 + 8 * s, 256);
        }
    }
    __syncthreads();

    if (tid == 0) {
#pragma unroll
        for (int p = 0; p < 3; ++p) {
            const uint32_t st = sb + GSM_DATA + p * GSTAGE_BYTES;
            MBARRIER_EXPECT_TX(sb + 8 * p, GSTAGE_BYTES);
            const int k0 = p * 64;
            tma2d(st,                   &tmA,  k0, row0, sb + 8 * p);
            tma2d(st + GTILE_BYTES,     &tmBh, k0, col0, sb + 8 * p);
            tma2d(st + 2 * GTILE_BYTES, &tmBl, k0, col0, sb + 8 * p);
        }
    }

    float acc[2][8][4];
#pragma unroll
    for (int i = 0; i < 2; i++)
#pragma unroll
        for (int j = 0; j < 8; j++)
#pragma unroll
            for (int k = 0; k < 4; k++) acc[i][j][k] = 0.f;

    const uint32_t cbase = (lane >> 4) * 16;
    uint32_t aRB[2], aMask[2], bRB[4], bMask[4];
#pragma unroll
    for (int mt = 0; mt < 2; ++mt) {
        const int r = wm + mt * 16 + (lane & 15);
        aRB[mt] = (uint32_t)r * 128;
        aMask[mt] = (uint32_t)((r & 7) << 4);
    }
#pragma unroll
    for (int j = 0; j < 4; ++j) {
        const int r = wn + j * 16 + (lane & 15);
        bRB[j] = (uint32_t)r * 128;
        bMask[j] = (uint32_t)((r & 7) << 4);
    }

    for (int c = 0; c < GCHUNKS; ++c) {
        const int u = c / 3;
        const int s = c - u * 3;
        MBARRIER_WAIT_PARITY(sb + 8 * s, (uint32_t)(u & 1));

        const uint32_t stA  = sb + GSM_DATA + s * GSTAGE_BYTES;
        const uint32_t stBh = stA + GTILE_BYTES;
        const uint32_t stBl = stA + 2 * GTILE_BYTES;

#pragma unroll
        for (int kk = 0; kk < 4; ++kk) {
            const uint32_t kb = cbase + kk * 32;
            uint32_t a[2][4], bh[4][4], bl[4][4];
#pragma unroll
            for (int mt = 0; mt < 2; ++mt)
                ldsm4(a[mt], stA + aRB[mt] + (kb ^ aMask[mt]));
#pragma unroll
            for (int j = 0; j < 4; ++j) {
                ldsm4(bh[j], stBh + bRB[j] + (kb ^ bMask[j]));
                ldsm4(bl[j], stBl + bRB[j] + (kb ^ bMask[j]));
            }
#pragma unroll
            for (int mt = 0; mt < 2; ++mt)
#pragma unroll
                for (int j = 0; j < 4; ++j) {
                    mma_fp16(acc[mt][2 * j],     a[mt], bh[j][0], bh[j][2]);
                    mma_fp16(acc[mt][2 * j + 1], a[mt], bh[j][1], bh[j][3]);
                }
#pragma unroll
            for (int mt = 0; mt < 2; ++mt)
#pragma unroll
                for (int j = 0; j < 4; ++j) {
                    mma_fp16(acc[mt][2 * j],     a[mt], bl[j][0], bl[j][2]);
                    mma_fp16(acc[mt][2 * j + 1], a[mt], bl[j][1], bl[j][3]);
                }
        }

        MBARRIER_ARRIVE(sb + 24 + 8 * s);

        const int p = c + 3;
        if (tid == 0 && p < GCHUNKS) {
            const int up = p / 3;
            MBARRIER_WAIT_PARITY_RELAXED(sb + 24 + 8 * s, (uint32_t)((up & 1) ^ 1));
            const uint32_t st = sb + GSM_DATA + s * GSTAGE_BYTES;
            MBARRIER_EXPECT_TX(sb + 8 * s, GSTAGE_BYTES);
            const int k0 = p * 64;
            tma2d(st,                   &tmA,  k0, row0, sb + 8 * s);
            tma2d(st + GTILE_BYTES,     &tmBh, k0, col0, sb + 8 * s);
            tma2d(st + 2 * GTILE_BYTES, &tmBl, k0, col0, sb + 8 * s);
        }
    }

    // Epilogue
    const int rr = lane >> 2;
    const int cc = (lane & 3) * 2;
#pragma unroll
    for (int mt = 0; mt < 2; ++mt) {
        const int mrow = row0 + wm + mt * 16 + rr;
#pragma unroll
        for (int nt = 0; nt < 8; ++nt) {
            const int n = col0 + wn + nt * 8 + cc;
            const float2 bb = *(const float2*)(bias + n);
            float v00 = acc[mt][nt][0] + bb.x, v01 = acc[mt][nt][1] + bb.y;
            float v10 = acc[mt][nt][2] + bb.x, v11 = acc[mt][nt][3] + bb.y;
            if (MODE == 0) {
                *(float2*)(C + (size_t)mrow * N + n) = make_float2(v00, v01);
                *(float2*)(C + (size_t)(mrow + 8) * N + n) = make_float2(v10, v11);
            } else {
                const float sc = (n < 2048) ? QSCALE : 1.0f;
                *(uint32_t*)(Ch + (size_t)mrow * N + n)       = pack2h(v00 * sc, v01 * sc);
                *(uint32_t*)(Ch + (size_t)(mrow + 8) * N + n) = pack2h(v10 * sc, v11 * sc);
            }
        }
    }
}

// ---------------------------------------------------------------------------
// Differential flash attention, single-term fp16 (unchanged from R10).
// Q, K, V, P all single fp16; scores 1 MMA term, PV 1 MMA term.
// Key-block 64, 2 stages. Grid: (S/128, B*H, 2 streams).
// ---------------------------------------------------------------------------
#define AT_STAGE_BYTES 24576           // K 8K | V 16K
#define AT_SMEM (32768 + 2 * AT_STAGE_BYTES)   // 81920

__global__ __launch_bounds__(256, 1)
void diff_attn_mma_kernel(const __grid_constant__ CUtensorMap tmQ,
                          const __grid_constant__ CUtensorMap tmK,
                          const float* __restrict__ amask,
                          float* __restrict__ o1buf,
                          float* __restrict__ o2buf)
{
    extern __shared__ __align__(1024) char asmem[];
    const uint32_t sb = smem_u32(asmem);
    const int tid = threadIdx.x, lane = tid & 31, w = tid >> 5;
    const int qb = blockIdx.x, bh = blockIdx.y, strm = blockIdx.z;
    const int b = bh >> 4, h = bh & 15;
    const int q0 = qb * 128;
    const int tokbase = b * S_LEN;

    const uint32_t MB_Q = sb, MB_F0 = sb + 8, MB_F1 = sb + 16, MB_E0 = sb + 24, MB_E1 = sb + 32;
    float* maskSm = (float*)(asmem + 64);
    const uint32_t QH = sb + 16384;
    const uint32_t ST0 = sb + 32768;

    if (tid == 0) {
        MBARRIER_INIT(MB_Q, 1);
        MBARRIER_INIT(MB_F0, 1); MBARRIER_INIT(MB_F1, 1);
        MBARRIER_INIT(MB_E0, 256); MBARRIER_INIT(MB_E1, 256);
    }
    {
        const float4* mp = (const float4*)(amask + tokbase);
        float4* ms = (float4*)maskSm;
#pragma unroll
        for (int i = tid; i < 512; i += 256) {
            float4 v = mp[i];
            v.x = (1.f - v.x) * -10000.f;
            v.y = (1.f - v.y) * -10000.f;
            v.z = (1.f - v.z) * -10000.f;
            v.w = (1.f - v.w) * -10000.f;
            ms[i] = v;
        }
    }
    __syncthreads();

    const int qcol = strm * 1024 + h * 64;
    const int kcol = 2048 + strm * 1024 + h * 64;
    const int vcol = 4096 + h * 128;

    if (tid == 0) {
        MBARRIER_EXPECT_TX(MB_Q, 16384);
        tma2d(QH, &tmQ, qcol, tokbase + q0, MB_Q);
#pragma unroll
        for (int s = 0; s < 2; ++s) {
            const uint32_t st = ST0 + s * AT_STAGE_BYTES;
            const uint32_t fb = s ? MB_F1 : MB_F0;
            MBARRIER_EXPECT_TX(fb, AT_STAGE_BYTES);
            const int k0 = tokbase + s * 64;
            tma2d(st,         &tmK, kcol,      k0, fb);
            tma2d(st + 8192,  &tmK, vcol,      k0, fb);
            tma2d(st + 16384, &tmK, vcol + 64, k0, fb);
        }
    }

    MBARRIER_WAIT_PARITY(MB_Q, 0);
    uint32_t qh[4][4];
    {
        const int r = 16 * w + (lane & 15);
        const uint32_t rb = (uint32_t)r * 128;
        const uint32_t msk = (uint32_t)((r & 7) << 4);
        const uint32_t cbq = (uint32_t)(lane >> 4) * 16;
#pragma unroll
        for (int kk = 0; kk < 4; ++kk)
            ldsm4(qh[kk], QH + rb + ((cbq + kk * 32) ^ msk));
    }

    float o[16][4];
#pragma unroll
    for (int i = 0; i < 16; i++)
#pragma unroll
        for (int j = 0; j < 4; j++) o[i][j] = 0.f;
    float m0 = -1e30f, m1 = -1e30f, l0 = 0.f, l1 = 0.f;

    uint32_t kRB[4], kMask[4];
#pragma unroll
    for (int g = 0; g < 4; ++g) {
        const int r = 16 * g + (lane & 15);
        kRB[g] = (uint32_t)r * 128;
        kMask[g] = (uint32_t)((r & 7) << 4);
    }
    const uint32_t cb = (uint32_t)(lane >> 4) * 16;

    for (int kb = 0; kb < 32; ++kb) {
        const int s = kb & 1, u = kb >> 1;
        const uint32_t FULL = s ? MB_F1 : MB_F0;
        const uint32_t EMPTY = s ? MB_E1 : MB_E0;
        const uint32_t ST = ST0 + s * AT_STAGE_BYTES;
        MBARRIER_WAIT_PARITY(FULL, (uint32_t)(u & 1));

        // ---- scores: single-term fp16 MMA (Q * K) ----
        float scf[8][4];
#pragma unroll
        for (int t = 0; t < 8; t++)
#pragma unroll
            for (int j = 0; j < 4; j++) scf[t][j] = 0.f;

#pragma unroll
        for (int kk = 0; kk < 4; ++kk) {
            uint32_t kh[4][4];
#pragma unroll
            for (int g = 0; g < 4; ++g) {
                const uint32_t a = cb + kk * 32;
                ldsm4(kh[g], ST + kRB[g] + (a ^ kMask[g]));
            }
#pragma unroll
            for (int g = 0; g < 4; ++g) {
                mma_fp16(scf[2 * g],     qh[kk], kh[g][0], kh[g][2]);
                mma_fp16(scf[2 * g + 1], qh[kk], kh[g][1], kh[g][3]);
            }
        }

        // ---- mask + dual-row online softmax ----
        const int kbase = kb * 64 + 2 * (lane & 3);
        float nm0 = m0, nm1 = m1;
#pragma unroll
        for (int t = 0; t < 8; ++t) {
            const float mv0 = maskSm[kbase + 8 * t];
            const float mv1 = maskSm[kbase + 8 * t + 1];
            scf[t][0] += mv0; scf[t][1] += mv1;
            scf[t][2] += mv0; scf[t][3] += mv1;
            nm0 = fmaxf(nm0, fmaxf(scf[t][0], scf[t][1]));
            nm1 = fmaxf(nm1, fmaxf(scf[t][2], scf[t][3]));
        }
        nm0 = fmaxf(nm0, __shfl_xor_sync(0xffffffffu, nm0, 1));
        nm0 = fmaxf(nm0, __shfl_xor_sync(0xffffffffu, nm0, 2));
        nm1 = fmaxf(nm1, __shfl_xor_sync(0xffffffffu, nm1, 1));
        nm1 = fmaxf(nm1, __shfl_xor_sync(0xffffffffu, nm1, 2));
        const float a0 = fexp(m0 - nm0), a1 = fexp(m1 - nm1);
        m0 = nm0; m1 = nm1;
#pragma unroll
        for (int nt = 0; nt < 16; ++nt) {
            o[nt][0] *= a0; o[nt][1] *= a0;
            o[nt][2] *= a1; o[nt][3] *= a1;
        }

        uint32_t pha[4][4];
        float rs0 = 0.f, rs1 = 0.f;
#pragma unroll
        for (int t = 0; t < 8; ++t) {
            const float e0 = fexp(scf[t][0] - m0), e1 = fexp(scf[t][1] - m0);
            const float e2 = fexp(scf[t][2] - m1), e3 = fexp(scf[t][3] - m1);
            rs0 += e0 + e1; rs1 += e2 + e3;
            pha[t >> 1][2 * (t & 1)]     = pack2h(e0, e1);
            pha[t >> 1][2 * (t & 1) + 1] = pack2h(e2, e3);
        }
        rs0 += __shfl_xor_sync(0xffffffffu, rs0, 1);
        rs0 += __shfl_xor_sync(0xffffffffu, rs0, 2);
        rs1 += __shfl_xor_sync(0xffffffffu, rs1, 1);
        rs1 += __shfl_xor_sync(0xffffffffu, rs1, 2);
        l0 = l0 * a0 + rs0;
        l1 = l1 * a1 + rs1;

        // ---- PV: single-term fp16 MMA (P * V) ----
#pragma unroll
        for (int kk = 0; kk < 4; ++kk) {
            const int r = 16 * kk + (lane & 15);
            const uint32_t vrb = (uint32_t)r * 128;
            const uint32_t vmsk = (uint32_t)((r & 7) << 4);
#pragma unroll
            for (int g = 0; g < 8; ++g) {
                const uint32_t base = ST + 8192 + ((g >> 2) ? 8192u : 0u);
                const uint32_t a = ((uint32_t)((g & 3) * 32) + cb) ^ vmsk;
                uint32_t vh[4];
                ldsm4t(vh, base + vrb + a);
                mma_fp16(o[2 * g],     pha[kk], vh[0], vh[1]);
                mma_fp16(o[2 * g + 1], pha[kk], vh[2], vh[3]);
            }
        }

        MBARRIER_ARRIVE(EMPTY);

        if (tid == 0 && kb + 2 < 32) {
            const int p = kb + 2;
            MBARRIER_WAIT_PARITY_RELAXED(EMPTY, (uint32_t)((((p >> 1) & 1) ^ 1)));
            MBARRIER_EXPECT_TX(FULL, AT_STAGE_BYTES);
            const int k0 = tokbase + p * 64;
            tma2d(ST,         &tmK, kcol,      k0, FULL);
            tma2d(ST + 8192,  &tmK, vcol,      k0, FULL);
            tma2d(ST + 16384, &tmK, vcol + 64, k0, FULL);
        }
    }

    // ---- normalize + store ----
    const float inv0 = 1.f / l0, inv1 = 1.f / l1;
    float* ob = strm ? o2buf : o1buf;
    const int row = tokbase + q0 + 16 * w + (lane >> 2);
    float* p0 = ob + (size_t)row * DMODEL + h * 128 + 2 * (lane & 3);
    float* p1 = p0 + 8 * DMODEL;
#pragma unroll
    for (int nt = 0; nt < 16; ++nt) {
        *(float2*)(p0 + 8 * nt) = make_float2(o[nt][0] * inv0, o[nt][1] * inv0);
        *(float2*)(p1 + 8 * nt) = make_float2(o[nt][2] * inv1, o[nt][3] * inv1);
    }
}

// ---------------------------------------------------------------------------
// combine (o1 - lam*o2) -> fp16 single (proj GEMM A input)
// ---------------------------------------------------------------------------
__global__ __launch_bounds__(256)
void combine_fp16_kernel(const float4* __restrict__ o1, const float4* __restrict__ o2,
                         const float* __restrict__ lamp, uint2* __restrict__ out16, int n4)
{
    int i = blockIdx.x * blockDim.x + threadIdx.x;
    if (i >= n4) return;
    const float lam = *lamp;
    float4 a = o1[i], c = o2[i];
    uint2 H;
    H.x = pack2h(a.x - lam * c.x, a.y - lam * c.y);
    H.y = pack2h(a.z - lam * c.z, a.w - lam * c.w);
    out16[i] = H;
}

// fp32 -> fp16 single (hidden -> A)
__global__ __launch_bounds__(256)
void tofp16_kernel(const float4* __restrict__ x, uint2* __restrict__ y, int n4)
{
    int i = blockIdx.x * blockDim.x + threadIdx.x;
    if (i >= n4) return;
    float4 v = x[i];
    uint2 H;
    H.x = pack2h(v.x, v.y);
    H.y = pack2h(v.z, v.w);
    y[i] = H;
}

// fp32 W[K][N] -> transposed fp16 hi/lo: hiT[N][K], loT[N][K]
__global__ __launch_bounds__(256)
void splitT16_kernel(const float* __restrict__ W, __half* __restrict__ hiT,
                     __half* __restrict__ loT, int K, int N)
{
    __shared__ float t[32][33];
    const int tx = threadIdx.x, ty = threadIdx.y;
    const int n0 = blockIdx.x * 32, k0 = blockIdx.y * 32;
#pragma unroll
    for (int r = 0; r < 4; ++r)
        t[ty + 8 * r][tx] = W[(size_t)(k0 + ty + 8 * r) * N + n0 + tx];
    __syncthreads();
#pragma unroll
    for (int r = 0; r < 4; ++r) {
        const int nn = ty + 8 * r;
        float v = t[tx][nn];
        __half hh = __float2half_rn(v);
        __half ll = __float2half_rn(v - __half2float(hh));
        const size_t off = (size_t)(n0 + nn) * K + k0 + tx;
        hiT[off] = hh;
        loT[off] = ll;
    }
}

// ---------------------------------------------------------------------------
// Host side
// ---------------------------------------------------------------------------
typedef CUresult (*PFN_tmEncode)(
    CUtensorMap*, CUtensorMapDataType, cuuint32_t, void*,
    const cuuint64_t*, const cuuint64_t*, const cuuint32_t*, const cuuint32_t*,
    CUtensorMapInterleave, CUtensorMapSwizzle, CUtensorMapL2promotion,
    CUtensorMapFloatOOBfill);

static void make_map(PFN_tmEncode fn, CUtensorMap* m, void* ptr,
                     unsigned long long rows, unsigned long long cols,
                     unsigned box0, unsigned box1)
{
    cuuint64_t dims[2]    = {(cuuint64_t)cols, (cuuint64_t)rows};
    cuuint64_t strides[1] = {(cuuint64_t)cols * 2};
    cuuint32_t box[2]     = {box0, box1};
    cuuint32_t es[2]      = {1u, 1u};
    fn(m, CU_TENSOR_MAP_DATA_TYPE_BFLOAT16, 2, ptr, dims, strides, box, es,
       CU_TENSOR_MAP_INTERLEAVE_NONE, CU_TENSOR_MAP_SWIZZLE_128B,
       CU_TENSOR_MAP_L2_PROMOTION_L2_128B, CU_TENSOR_MAP_FLOAT_OOB_FILL_NONE);
}

extern "C" void kernel_launch(void* const* d_in, const int* in_sizes, int n_in,
                              void* d_out, int out_size)
{
    const float* hidden = (const float*)d_in[0];
    const float* amask  = (const float*)d_in[1];
    const float* W_attn = (const float*)d_in[2];
    const float* b_attn = (const float*)d_in[3];
    const float* W_proj = (const float*)d_in[4];
    const float* b_proj = (const float*)d_in[5];
    const float* lam    = (const float*)d_in[6];
    float* out = (float*)d_out;

    void *qkv16, *o1, *o2, *A16, *WAh, *WAl, *WPh, *WPl, *O16;
    cudaGetSymbolAddress(&qkv16, g_qkv16);
    cudaGetSymbolAddress(&o1, g_o1);     cudaGetSymbolAddress(&o2, g_o2);
    cudaGetSymbolAddress(&A16, g_A16);
    cudaGetSymbolAddress(&WAh, g_WAh);   cudaGetSymbolAddress(&WAl, g_WAl);
    cudaGetSymbolAddress(&WPh, g_WPh);   cudaGetSymbolAddress(&WPl, g_WPl);
    cudaGetSymbolAddress(&O16, g_O16);

    void* fnp = nullptr;
    cudaDriverEntryPointQueryResult qres;
    cudaGetDriverEntryPointByVersion("cuTensorMapEncodeTiled", &fnp, 12000,
                                     cudaEnableDefault, &qres);
    PFN_tmEncode enc = (PFN_tmEncode)fnp;

    CUtensorMap tA, tWAh, tWAl, tWPh, tWPl, tO, tQ, tK;
    make_map(enc, &tA,   A16,  M_TOK,  KDIM, 64, 128);
    make_map(enc, &tWAh, WAh,  N_QKV,  KDIM, 64, 128);
    make_map(enc, &tWAl, WAl,  N_QKV,  KDIM, 64, 128);
    make_map(enc, &tWPh, WPh,  DMODEL, KDIM, 64, 128);
    make_map(enc, &tWPl, WPl,  DMODEL, KDIM, 64, 128);
    make_map(enc, &tO,   O16,  M_TOK,  KDIM, 64, 128);
    make_map(enc, &tQ,   qkv16, M_TOK, N_QKV, 64, 128);
    make_map(enc, &tK,   qkv16, M_TOK, N_QKV, 64, 64);

    cudaFuncSetAttribute(gemm_fp16x2_kernel<0>,
                         cudaFuncAttributeMaxDynamicSharedMemorySize, GEMM_SMEM);
    cudaFuncSetAttribute(gemm_fp16x2_kernel<1>,
                         cudaFuncAttributeMaxDynamicSharedMemorySize, GEMM_SMEM);
    cudaFuncSetAttribute(diff_attn_mma_kernel,
                         cudaFuncAttributeMaxDynamicSharedMemorySize, AT_SMEM);

    // 1) hidden -> fp16
    {
        int n4 = (M_TOK * KDIM) / 4;
        tofp16_kernel<<<n4 / 256, 256>>>((const float4*)hidden, (uint2*)A16, n4);
    }
    // 2) transpose+split weights (fp16 hi/lo for both)
    {
        dim3 g(N_QKV / 32, KDIM / 32);
        splitT16_kernel<<<g, dim3(32, 8)>>>(W_attn, (__half*)WAh, (__half*)WAl, KDIM, N_QKV);
    }
    {
        dim3 g(DMODEL / 32, KDIM / 32);
        splitT16_kernel<<<g, dim3(32, 8)>>>(W_proj, (__half*)WPh, (__half*)WPl, KDIM, DMODEL);
    }
    // 3) QKV GEMM (fp16 x2) -> fp16 single (q pre-scaled)
    {
        dim3 g(N_QKV / 128, M_TOK / 128);
        gemm_fp16x2_kernel<1><<<g, 256, GEMM_SMEM>>>(tA, tWAh, tWAl, b_attn,
                                                     nullptr, (unsigned short*)qkv16, N_QKV);
    }
    // 4) differential attention (fp16 x1, both streams)
    {
        dim3 g(S_LEN / 128, B_SZ * NHEAD, 2);
        diff_attn_mma_kernel<<<g, 256, AT_SMEM>>>(tQ, tK, amask,
                                                  (float*)o1, (float*)o2);
    }
    // 5) combine -> fp16
    {
        int n4 = (M_TOK * DMODEL) / 4;
        combine_fp16_kernel<<<n4 / 256, 256>>>((const float4*)o1, (const float4*)o2,
                                               lam, (uint2*)O16, n4);
    }
    // 6) output projection (fp16 x2, fp32 out)
    {
        dim3 g(DMODEL / 128, M_TOK / 128);
        gemm_fp16x2_kernel<0><<<g, 256, GEMM_SMEM>>>(tO, tWPh, tWPl, b_proj,
                                                     out, nullptr, DMODEL);
    }
}

// round 12
// speedup vs baseline: 1.7339x; 1.0058x over previous
#include <cuda_runtime.h>
#include <cuda_fp16.h>
#include <cuda.h>
#include <cstdint>

// Problem dims (fixed by setup_inputs)
#define B_SZ   2
#define S_LEN  2048
#define DMODEL 2048
#define NHEAD  16
#define M_TOK  (B_SZ * S_LEN)     // 4096
#define N_QKV  (3 * DMODEL)       // 6144
#define KDIM   DMODEL             // 2048
#define QSCALE 0.0883883476483184f

// ---------------- scratch (static device globals: allocation-free) ----------
__device__ unsigned short g_qkv16[(size_t)M_TOK * N_QKV];  // fp16 qkv
__device__ unsigned short g_A16[(size_t)M_TOK * KDIM];     // fp16 hidden
__device__ unsigned short g_WAh[(size_t)N_QKV * KDIM];     // fp16 W_attn^T hi
__device__ unsigned short g_WAl[(size_t)N_QKV * KDIM];     // fp16 W_attn^T lo
__device__ unsigned short g_WPh[(size_t)DMODEL * KDIM];
__device__ unsigned short g_WPl[(size_t)DMODEL * KDIM];
__device__ unsigned short g_O16[(size_t)M_TOK * KDIM];     // fp16 combined attn out

// ---------------------------------------------------------------------------
// PTX helpers (base sm_90 only — no 'a'-gated instructions)
// ---------------------------------------------------------------------------
__device__ __forceinline__ uint32_t smem_u32(const void* p) {
    uint32_t a;
    asm("{ .reg .u64 t; cvta.to.shared.u64 t, %1; cvt.u32.u64 %0, t; }" : "=r"(a) : "l"(p));
    return a;
}

#define MBARRIER_INIT(addr, cnt) \
    asm volatile("mbarrier.init.shared.b64 [%0], %1;" :: "r"((uint32_t)(addr)), "r"((uint32_t)(cnt)) : "memory")

#define MBARRIER_ARRIVE(addr) \
    asm volatile("mbarrier.arrive.shared.b64 _, [%0];" :: "r"((uint32_t)(addr)) : "memory")

#define MBARRIER_EXPECT_TX(addr, bytes) \
    asm volatile("mbarrier.arrive.expect_tx.shared.b64 _, [%0], %1;" :: "r"((uint32_t)(addr)), "r"((uint32_t)(bytes)) : "memory")

#define MBARRIER_WAIT_PARITY(mbar_smem_addr, phase_parity) do { \
    uint32_t _mbar = (uint32_t)(mbar_smem_addr); \
    uint32_t _parity = (uint32_t)(phase_parity); \
    uint32_t _done; \
    asm volatile( \
        "{\n\t.reg .pred p;\n\t" \
        "mbarrier.try_wait.parity.acquire.cta.shared::cta.b64 p, [%1], %2;\n\t" \
        "selp.b32 %0, 1, 0, p;\n\t}" \
        : "=r"(_done) : "r"(_mbar), "r"(_parity) : "memory"); \
    if (!_done) { \
        asm volatile( \
            "{\n\t.reg .pred P1;\n\t" \
            "WAIT_LOOP_%=:\n\t" \
            "mbarrier.try_wait.parity.acquire.cta.shared::cta.b64 P1, [%0], %1, 0x989680;\n\t" \
            "@P1 bra.uni WAIT_DONE_%=;\n\t" \
            "bra.uni WAIT_LOOP_%=;\n\t" \
            "WAIT_DONE_%=:\n\t}" \
            :: "r"(_mbar), "r"(_parity) : "memory"); \
    } \
} while(0)

#define MBARRIER_WAIT_PARITY_RELAXED(mbar_smem_addr, phase_parity) do { \
    uint32_t _mbar = (uint32_t)(mbar_smem_addr); \
    uint32_t _parity = (uint32_t)(phase_parity); \
    uint32_t _done; \
    asm volatile( \
        "{\n\t.reg .pred p;\n\t" \
        "mbarrier.try_wait.parity.relaxed.cta.shared::cta.b64 p, [%1], %2, 0x989680;\n\t" \
        "selp.b32 %0, 1, 0, p;\n\t}" \
        : "=r"(_done) : "r"(_mbar), "r"(_parity) : "memory"); \
    if (!_done) { \
        asm volatile( \
            "{\n\t.reg .pred P1;\n\t" \
            "WAIT_LOOP_%=:\n\t" \
            "mbarrier.try_wait.parity.relaxed.cta.shared::cta.b64 P1, [%0], %1, 0x989680;\n\t" \
            "@P1 bra.uni WAIT_DONE_%=;\n\t" \
            "bra.uni WAIT_LOOP_%=;\n\t" \
            "WAIT_DONE_%=:\n\t}" \
            :: "r"(_mbar), "r"(_parity) : "memory"); \
    } \
} while(0)

__device__ __forceinline__ void tma2d(uint32_t dst, const void* map, int x, int y, uint32_t mbar) {
    asm volatile(
        "cp.async.bulk.tensor.2d.shared::cta.global.tile.mbarrier::complete_tx::bytes "
        "[%0], [%1, {%2, %3}], [%4];"
        :: "r"(dst), "l"(map), "r"(x), "r"(y), "r"(mbar) : "memory");
}

__device__ __forceinline__ void ldsm4(uint32_t* r, uint32_t addr) {
    asm volatile("ldmatrix.sync.aligned.m8n8.x4.shared.b16 {%0,%1,%2,%3}, [%4];"
                 : "=r"(r[0]), "=r"(r[1]), "=r"(r[2]), "=r"(r[3]) : "r"(addr));
}
__device__ __forceinline__ void ldsm4t(uint32_t* r, uint32_t addr) {
    asm volatile("ldmatrix.sync.aligned.m8n8.x4.trans.shared.b16 {%0,%1,%2,%3}, [%4];"
                 : "=r"(r[0]), "=r"(r[1]), "=r"(r[2]), "=r"(r[3]) : "r"(addr));
}

__device__ __forceinline__ void mma_fp16(float* d, const uint32_t* a, uint32_t b0, uint32_t b1) {
    asm volatile(
        "mma.sync.aligned.m16n8k16.row.col.f32.f16.f16.f32 "
        "{%0,%1,%2,%3}, {%4,%5,%6,%7}, {%8,%9}, {%0,%1,%2,%3};"
        : "+f"(d[0]), "+f"(d[1]), "+f"(d[2]), "+f"(d[3])
        : "r"(a[0]), "r"(a[1]), "r"(a[2]), "r"(a[3]), "r"(b0), "r"(b1));
}

__device__ __forceinline__ uint32_t pack2h(float a, float b) {
    __half2 t = __floats2half2_rn(a, b);
    return *reinterpret_cast<uint32_t*>(&t);
}

// Fast exp on the FMA pipe (no MUFU). Valid for x <= 0 (clamped below -80).
__device__ __forceinline__ float fexp(float x) {
    x = fmaxf(x, -80.0f);
    float t = x * 1.4426950408889634f;
    float z = t + 12582912.0f;
    int n = __float_as_int(z) - 0x4b400000;
    float f = t - (z - 12582912.0f);
    float u = f * 0.6931471805599453f;
    float r = 1.3888889e-3f;
    r = fmaf(r, u, 8.3333338e-3f);
    r = fmaf(r, u, 4.1666668e-2f);
    r = fmaf(r, u, 1.6666667e-1f);
    r = fmaf(r, u, 0.5f);
    r = fmaf(r, u, 1.0f);
    r = fmaf(r, u, 1.0f);
    return r * __int_as_float((n + 127) << 23);
}

// ---------------------------------------------------------------------------
// fp16x2 GEMM (unchanged from R11):  C[M,N] = A[M,K] @ B[N,K]^T + bias
// ---------------------------------------------------------------------------
#define GCHUNKS     32
#define GTILE_BYTES 16384
#define GSTAGE_BYTES (3 * GTILE_BYTES)
#define GSM_DATA    1024
#define GEMM_SMEM   (GSM_DATA + 3 * GSTAGE_BYTES)

template <int MODE>
__global__ __launch_bounds__(256, 1)
void gemm_fp16x2_kernel(const __grid_constant__ CUtensorMap tmA,
                        const __grid_constant__ CUtensorMap tmBh,
                        const __grid_constant__ CUtensorMap tmBl,
                        const float* __restrict__ bias,
                        float* __restrict__ C,
                        unsigned short* __restrict__ Ch,
                        int N)
{
    extern __shared__ __align__(1024) char gsm[];
    const uint32_t sb = smem_u32(gsm);
    const int tid = threadIdx.x;
    const int lane = tid & 31;
    const int wid = tid >> 5;
    const int row0 = blockIdx.y * 128;
    const int col0 = blockIdx.x * 128;
    const int wm = (wid & 3) * 32;
    const int wn = (wid >> 2) * 64;

    if (tid == 0) {
#pragma unroll
        for (int s = 0; s < 3; ++s) {
            MBARRIER_INIT(sb + 8 * s, 1);
            MBARRIER_INIT(sb + 24 + 8 * s, 256);
        }
    }
    __syncthreads();

    if (tid == 0) {
#pragma unroll
        for (int p = 0; p < 3; ++p) {
            const uint32_t st = sb + GSM_DATA + p * GSTAGE_BYTES;
            MBARRIER_EXPECT_TX(sb + 8 * p, GSTAGE_BYTES);
            const int k0 = p * 64;
            tma2d(st,                   &tmA,  k0, row0, sb + 8 * p);
            tma2d(st + GTILE_BYTES,     &tmBh, k0, col0, sb + 8 * p);
            tma2d(st + 2 * GTILE_BYTES, &tmBl, k0, col0, sb + 8 * p);
        }
    }

    float acc[2][8][4];
#pragma unroll
    for (int i = 0; i < 2; i++)
#pragma unroll
        for (int j = 0; j < 8; j++)
#pragma unroll
            for (int k = 0; k < 4; k++) acc[i][j][k] = 0.f;

    const uint32_t cbase = (lane >> 4) * 16;
    uint32_t aRB[2], aMask[2], bRB[4], bMask[4];
#pragma unroll
    for (int mt = 0; mt < 2; ++mt) {
        const int r = wm + mt * 16 + (lane & 15);
        aRB[mt] = (uint32_t)r * 128;
        aMask[mt] = (uint32_t)((r & 7) << 4);
    }
#pragma unroll
    for (int j = 0; j < 4; ++j) {
        const int r = wn + j * 16 + (lane & 15);
        bRB[j] = (uint32_t)r * 128;
        bMask[j] = (uint32_t)((r & 7) << 4);
    }

    for (int c = 0; c < GCHUNKS; ++c) {
        const int u = c / 3;
        const int s = c - u * 3;
        MBARRIER_WAIT_PARITY(sb + 8 * s, (uint32_t)(u & 1));

        const uint32_t stA  = sb + GSM_DATA + s * GSTAGE_BYTES;
        const uint32_t stBh = stA + GTILE_BYTES;
        const uint32_t stBl = stA + 2 * GTILE_BYTES;

#pragma unroll
        for (int kk = 0; kk < 4; ++kk) {
            const uint32_t kb = cbase + kk * 32;
            uint32_t a[2][4], bh[4][4], bl[4][4];
#pragma unroll
            for (int mt = 0; mt < 2; ++mt)
                ldsm4(a[mt], stA + aRB[mt] + (kb ^ aMask[mt]));
#pragma unroll
            for (int j = 0; j < 4; ++j) {
                ldsm4(bh[j], stBh + bRB[j] + (kb ^ bMask[j]));
                ldsm4(bl[j], stBl + bRB[j] + (kb ^ bMask[j]));
            }
#pragma unroll
            for (int mt = 0; mt < 2; ++mt)
#pragma unroll
                for (int j = 0; j < 4; ++j) {
                    mma_fp16(acc[mt][2 * j],     a[mt], bh[j][0], bh[j][2]);
                    mma_fp16(acc[mt][2 * j + 1], a[mt], bh[j][1], bh[j][3]);
                }
#pragma unroll
            for (int mt = 0; mt < 2; ++mt)
#pragma unroll
                for (int j = 0; j < 4; ++j) {
                    mma_fp16(acc[mt][2 * j],     a[mt], bl[j][0], bl[j][2]);
                    mma_fp16(acc[mt][2 * j + 1], a[mt], bl[j][1], bl[j][3]);
                }
        }

        MBARRIER_ARRIVE(sb + 24 + 8 * s);

        const int p = c + 3;
        if (tid == 0 && p < GCHUNKS) {
            const int up = p / 3;
            MBARRIER_WAIT_PARITY_RELAXED(sb + 24 + 8 * s, (uint32_t)((up & 1) ^ 1));
            const uint32_t st = sb + GSM_DATA + s * GSTAGE_BYTES;
            MBARRIER_EXPECT_TX(sb + 8 * s, GSTAGE_BYTES);
            const int k0 = p * 64;
            tma2d(st,                   &tmA,  k0, row0, sb + 8 * s);
            tma2d(st + GTILE_BYTES,     &tmBh, k0, col0, sb + 8 * s);
            tma2d(st + 2 * GTILE_BYTES, &tmBl, k0, col0, sb + 8 * s);
        }
    }

    // Epilogue
    const int rr = lane >> 2;
    const int cc = (lane & 3) * 2;
#pragma unroll
    for (int mt = 0; mt < 2; ++mt) {
        const int mrow = row0 + wm + mt * 16 + rr;
#pragma unroll
        for (int nt = 0; nt < 8; ++nt) {
            const int n = col0 + wn + nt * 8 + cc;
            const float2 bb = *(const float2*)(bias + n);
            float v00 = acc[mt][nt][0] + bb.x, v01 = acc[mt][nt][1] + bb.y;
            float v10 = acc[mt][nt][2] + bb.x, v11 = acc[mt][nt][3] + bb.y;
            if (MODE == 0) {
                *(float2*)(C + (size_t)mrow * N + n) = make_float2(v00, v01);
                *(float2*)(C + (size_t)(mrow + 8) * N + n) = make_float2(v10, v11);
            } else {
                const float sc = (n < 2048) ? QSCALE : 1.0f;
                *(uint32_t*)(Ch + (size_t)mrow * N + n)       = pack2h(v00 * sc, v01 * sc);
                *(uint32_t*)(Ch + (size_t)(mrow + 8) * N + n) = pack2h(v10 * sc, v11 * sc);
            }
        }
    }
}

// ---------------------------------------------------------------------------
// Fused dual-stream differential flash attention, single-term fp16.
// CTA = 64 q-rows x BOTH streams: warps 0-3 stream 1, warps 4-7 stream 2.
// K1+K2+V per stage (V loaded once). In-kernel combine o1 - lam*o2 -> fp16.
// Grid: (S/64, B*H). Key-block 64, 2 stages.
// ---------------------------------------------------------------------------
#define AT_STAGE_BYTES 32768           // K1 8K | K2 8K | V 16K
#define AT_SMEM (32768 + 2 * AT_STAGE_BYTES)   // 98304

__global__ __launch_bounds__(256, 1)
void diff_attn_fused_kernel(const __grid_constant__ CUtensorMap tmT,
                            const float* __restrict__ amask,
                            const float* __restrict__ lambda_p,
                            unsigned short* __restrict__ O16)
{
    extern __shared__ __align__(1024) char asmem[];
    const uint32_t sb = smem_u32(asmem);
    const int tid = threadIdx.x, lane = tid & 31, w = tid >> 5;
    const int s_id = w >> 2;           // stream (0 or 1)
    const int wq = w & 3;              // warp index within stream
    const int qb = blockIdx.x, bh = blockIdx.y;
    const int b = bh >> 4, h = bh & 15;
    const int q0 = qb * 64;
    const int tokbase = b * S_LEN;

    const uint32_t MB_Q = sb, MB_F0 = sb + 8, MB_F1 = sb + 16, MB_E0 = sb + 24, MB_E1 = sb + 32;
    float* maskSm = (float*)(asmem + 64);           // 8KB
    const uint32_t Q1 = sb + 16384;                  // 8KB
    const uint32_t Q2 = sb + 24576;                  // 8KB
    const uint32_t ST0 = sb + 32768;                 // 2 x 32KB stages

    if (tid == 0) {
        MBARRIER_INIT(MB_Q, 1);
        MBARRIER_INIT(MB_F0, 1); MBARRIER_INIT(MB_F1, 1);
        MBARRIER_INIT(MB_E0, 256); MBARRIER_INIT(MB_E1, 256);
    }
    {
        const float4* mp = (const float4*)(amask + tokbase);
        float4* ms = (float4*)maskSm;
#pragma unroll
        for (int i = tid; i < 512; i += 256) {
            float4 v = mp[i];
            v.x = (1.f - v.x) * -10000.f;
            v.y = (1.f - v.y) * -10000.f;
            v.z = (1.f - v.z) * -10000.f;
            v.w = (1.f - v.w) * -10000.f;
            ms[i] = v;
        }
    }
    __syncthreads();

    const int q1col = h * 64;
    const int q2col = 1024 + h * 64;
    const int k1col = 2048 + h * 64;
    const int k2col = 3072 + h * 64;
    const int vcol  = 4096 + h * 128;

    if (tid == 0) {
        MBARRIER_EXPECT_TX(MB_Q, 16384);
        tma2d(Q1, &tmT, q1col, tokbase + q0, MB_Q);
        tma2d(Q2, &tmT, q2col, tokbase + q0, MB_Q);
#pragma unroll
        for (int s = 0; s < 2; ++s) {
            const uint32_t st = ST0 + s * AT_STAGE_BYTES;
            const uint32_t fb = s ? MB_F1 : MB_F0;
            MBARRIER_EXPECT_TX(fb, AT_STAGE_BYTES);
            const int k0 = tokbase + s * 64;
            tma2d(st,         &tmT, k1col,     k0, fb);
            tma2d(st + 8192,  &tmT, k2col,     k0, fb);
            tma2d(st + 16384, &tmT, vcol,      k0, fb);
            tma2d(st + 24576, &tmT, vcol + 64, k0, fb);
        }
    }

    // Q fragments: warp loads its stream's Q tile rows 16*wq..16*wq+15
    MBARRIER_WAIT_PARITY(MB_Q, 0);
    uint32_t qh[4][4];
    {
        const uint32_t QT = s_id ? Q2 : Q1;
        const int r = 16 * wq + (lane & 15);
        const uint32_t rb = (uint32_t)r * 128;
        const uint32_t msk = (uint32_t)((r & 7) << 4);
        const uint32_t cbq = (uint32_t)(lane >> 4) * 16;
#pragma unroll
        for (int kk = 0; kk < 4; ++kk)
            ldsm4(qh[kk], QT + rb + ((cbq + kk * 32) ^ msk));
    }

    float o[16][4];
#pragma unroll
    for (int i = 0; i < 16; i++)
#pragma unroll
        for (int j = 0; j < 4; j++) o[i][j] = 0.f;
    float m0 = -1e30f, m1 = -1e30f, l0 = 0.f, l1 = 0.f;

    uint32_t kRB[4], kMask[4];
#pragma unroll
    for (int g = 0; g < 4; ++g) {
        const int r = 16 * g + (lane & 15);
        kRB[g] = (uint32_t)r * 128;
        kMask[g] = (uint32_t)((r & 7) << 4);
    }
    const uint32_t cb = (uint32_t)(lane >> 4) * 16;
    const uint32_t kOff = (uint32_t)s_id * 8192;      // stream's K tile offset

    for (int kb = 0; kb < 32; ++kb) {
        const int s = kb & 1, u = kb >> 1;
        const uint32_t FULL = s ? MB_F1 : MB_F0;
        const uint32_t EMPTY = s ? MB_E1 : MB_E0;
        const uint32_t ST = ST0 + s * AT_STAGE_BYTES;
        MBARRIER_WAIT_PARITY(FULL, (uint32_t)(u & 1));

        // ---- scores: single-term fp16 MMA (Q * K_s) ----
        float scf[8][4];
#pragma unroll
        for (int t = 0; t < 8; t++)
#pragma unroll
            for (int j = 0; j < 4; j++) scf[t][j] = 0.f;

#pragma unroll
        for (int kk = 0; kk < 4; ++kk) {
            uint32_t kh[4][4];
#pragma unroll
            for (int g = 0; g < 4; ++g) {
                const uint32_t a = cb + kk * 32;
                ldsm4(kh[g], ST + kOff + kRB[g] + (a ^ kMask[g]));
            }
#pragma unroll
            for (int g = 0; g < 4; ++g) {
                mma_fp16(scf[2 * g],     qh[kk], kh[g][0], kh[g][2]);
                mma_fp16(scf[2 * g + 1], qh[kk], kh[g][1], kh[g][3]);
            }
        }

        // ---- mask + dual-row online softmax ----
        const int kbase = kb * 64 + 2 * (lane & 3);
        float nm0 = m0, nm1 = m1;
#pragma unroll
        for (int t = 0; t < 8; ++t) {
            const float mv0 = maskSm[kbase + 8 * t];
            const float mv1 = maskSm[kbase + 8 * t + 1];
            scf[t][0] += mv0; scf[t][1] += mv1;
            scf[t][2] += mv0; scf[t][3] += mv1;
            nm0 = fmaxf(nm0, fmaxf(scf[t][0], scf[t][1]));
            nm1 = fmaxf(nm1, fmaxf(scf[t][2], scf[t][3]));
        }
        nm0 = fmaxf(nm0, __shfl_xor_sync(0xffffffffu, nm0, 1));
        nm0 = fmaxf(nm0, __shfl_xor_sync(0xffffffffu, nm0, 2));
        nm1 = fmaxf(nm1, __shfl_xor_sync(0xffffffffu, nm1, 1));
        nm1 = fmaxf(nm1, __shfl_xor_sync(0xffffffffu, nm1, 2));
        const float a0 = fexp(m0 - nm0), a1 = fexp(m1 - nm1);
        m0 = nm0; m1 = nm1;
#pragma unroll
        for (int nt = 0; nt < 16; ++nt) {
            o[nt][0] *= a0; o[nt][1] *= a0;
            o[nt][2] *= a1; o[nt][3] *= a1;
        }

        uint32_t pha[4][4];
        float rs0 = 0.f, rs1 = 0.f;
#pragma unroll
        for (int t = 0; t < 8; ++t) {
            const float e0 = fexp(scf[t][0] - m0), e1 = fexp(scf[t][1] - m0);
            const float e2 = fexp(scf[t][2] - m1), e3 = fexp(scf[t][3] - m1);
            rs0 += e0 + e1; rs1 += e2 + e3;
            pha[t >> 1][2 * (t & 1)]     = pack2h(e0, e1);
            pha[t >> 1][2 * (t & 1) + 1] = pack2h(e2, e3);
        }
        rs0 += __shfl_xor_sync(0xffffffffu, rs0, 1);
        rs0 += __shfl_xor_sync(0xffffffffu, rs0, 2);
        rs1 += __shfl_xor_sync(0xffffffffu, rs1, 1);
        rs1 += __shfl_xor_sync(0xffffffffu, rs1, 2);
        l0 = l0 * a0 + rs0;
        l1 = l1 * a1 + rs1;

        // ---- PV: single-term fp16 MMA (P * V), V shared between streams ----
#pragma unroll
        for (int kk = 0; kk < 4; ++kk) {
            const int r = 16 * kk + (lane & 15);
            const uint32_t vrb = (uint32_t)r * 128;
            const uint32_t vmsk = (uint32_t)((r & 7) << 4);
#pragma unroll
            for (int g = 0; g < 8; ++g) {
                const uint32_t base = ST + 16384 + ((g >> 2) ? 8192u : 0u);
                const uint32_t a = ((uint32_t)((g & 3) * 32) + cb) ^ vmsk;
                uint32_t vh[4];
                ldsm4t(vh, base + vrb + a);
                mma_fp16(o[2 * g],     pha[kk], vh[0], vh[1]);
                mma_fp16(o[2 * g + 1], pha[kk], vh[2], vh[3]);
            }
        }

        MBARRIER_ARRIVE(EMPTY);

        if (tid == 0 && kb + 2 < 32) {
            const int p = kb + 2;
            MBARRIER_WAIT_PARITY_RELAXED(EMPTY, (uint32_t)((((p >> 1) & 1) ^ 1)));
            MBARRIER_EXPECT_TX(FULL, AT_STAGE_BYTES);
            const int k0 = tokbase + p * 64;
            tma2d(ST,         &tmT, k1col,     k0, FULL);
            tma2d(ST + 8192,  &tmT, k2col,     k0, FULL);
            tma2d(ST + 16384, &tmT, vcol,      k0, FULL);
            tma2d(ST + 24576, &tmT, vcol + 64, k0, FULL);
        }
    }

    // ---- normalize to smem (per stream), then combine o1 - lam*o2 -> fp16 ----
    __syncthreads();    // all warps past the last stage reads; stages reusable
    float* Cb = (float*)(asmem + 32768 + s_id * 32768);   // [64][128] fp32
    {
        const float inv0 = 1.f / l0, inv1 = 1.f / l1;
        const int r0 = 16 * wq + (lane >> 2);
        const int cc = 2 * (lane & 3);
#pragma unroll
        for (int nt = 0; nt < 16; ++nt) {
            Cb[r0 * 128 + 8 * nt + cc]           = o[nt][0] * inv0;
            Cb[r0 * 128 + 8 * nt + cc + 1]       = o[nt][1] * inv0;
            Cb[(r0 + 8) * 128 + 8 * nt + cc]     = o[nt][2] * inv1;
            Cb[(r0 + 8) * 128 + 8 * nt + cc + 1] = o[nt][3] * inv1;
        }
    }
    __syncthreads();

    const float lam = *lambda_p;
    const float* C1b = (const float*)(asmem + 32768);
    const float* C2b = (const float*)(asmem + 65536);
    for (int idx = tid; idx < 64 * 32; idx += 256) {
        const int row = idx >> 5;
        const int c4 = (idx & 31) * 4;
        float4 a = *(const float4*)&C1b[row * 128 + c4];
        float4 c = *(const float4*)&C2b[row * 128 + c4];
        uint2 H;
        H.x = pack2h(a.x - lam * c.x, a.y - lam * c.y);
        H.y = pack2h(a.z - lam * c.z, a.w - lam * c.w);
        *(uint2*)(O16 + (size_t)(tokbase + q0 + row) * DMODEL + h * 128 + c4) = H;
    }
}

// ---------------------------------------------------------------------------
// fp32 -> fp16 single (hidden -> A)
// ---------------------------------------------------------------------------
__global__ __launch_bounds__(256)
void tofp16_kernel(const float4* __restrict__ x, uint2* __restrict__ y, int n4)
{
    int i = blockIdx.x * blockDim.x + threadIdx.x;
    if (i >= n4) return;
    float4 v = x[i];
    uint2 H;
    H.x = pack2h(v.x, v.y);
    H.y = pack2h(v.z, v.w);
    y[i] = H;
}

// fp32 W[K][N] -> transposed fp16 hi/lo: hiT[N][K], loT[N][K]
__global__ __launch_bounds__(256)
void splitT16_kernel(const float* __restrict__ W, __half* __restrict__ hiT,
                     __half* __restrict__ loT, int K, int N)
{
    __shared__ float t[32][33];
    const int tx = threadIdx.x, ty = threadIdx.y;
    const int n0 = blockIdx.x * 32, k0 = blockIdx.y * 32;
#pragma unroll
    for (int r = 0; r < 4; ++r)
        t[ty + 8 * r][tx] = W[(size_t)(k0 + ty + 8 * r) * N + n0 + tx];
    __syncthreads();
#pragma unroll
    for (int r = 0; r < 4; ++r) {
        const int nn = ty + 8 * r;
        float v = t[tx][nn];
        __half hh = __float2half_rn(v);
        __half ll = __float2half_rn(v - __half2float(hh));
        const size_t off = (size_t)(n0 + nn) * K + k0 + tx;
        hiT[off] = hh;
        loT[off] = ll;
    }
}

// ---------------------------------------------------------------------------
// Host side
// ---------------------------------------------------------------------------
typedef CUresult (*PFN_tmEncode)(
    CUtensorMap*, CUtensorMapDataType, cuuint32_t, void*,
    const cuuint64_t*, const cuuint64_t*, const cuuint32_t*, const cuuint32_t*,
    CUtensorMapInterleave, CUtensorMapSwizzle, CUtensorMapL2promotion,
    CUtensorMapFloatOOBfill);

static void make_map(PFN_tmEncode fn, CUtensorMap* m, void* ptr,
                     unsigned long long rows, unsigned long long cols,
                     unsigned box0, unsigned box1)
{
    cuuint64_t dims[2]    = {(cuuint64_t)cols, (cuuint64_t)rows};
    cuuint64_t strides[1] = {(cuuint64_t)cols * 2};
    cuuint32_t box[2]     = {box0, box1};
    cuuint32_t es[2]      = {1u, 1u};
    fn(m, CU_TENSOR_MAP_DATA_TYPE_BFLOAT16, 2, ptr, dims, strides, box, es,
       CU_TENSOR_MAP_INTERLEAVE_NONE, CU_TENSOR_MAP_SWIZZLE_128B,
       CU_TENSOR_MAP_L2_PROMOTION_L2_128B, CU_TENSOR_MAP_FLOAT_OOB_FILL_NONE);
}

extern "C" void kernel_launch(void* const* d_in, const int* in_sizes, int n_in,
                              void* d_out, int out_size)
{
    const float* hidden = (const float*)d_in[0];
    const float* amask  = (const float*)d_in[1];
    const float* W_attn = (const float*)d_in[2];
    const float* b_attn = (const float*)d_in[3];
    const float* W_proj = (const float*)d_in[4];
    const float* b_proj = (const float*)d_in[5];
    const float* lam    = (const float*)d_in[6];
    float* out = (float*)d_out;

    void *qkv16, *A16, *WAh, *WAl, *WPh, *WPl, *O16;
    cudaGetSymbolAddress(&qkv16, g_qkv16);
    cudaGetSymbolAddress(&A16, g_A16);
    cudaGetSymbolAddress(&WAh, g_WAh);   cudaGetSymbolAddress(&WAl, g_WAl);
    cudaGetSymbolAddress(&WPh, g_WPh);   cudaGetSymbolAddress(&WPl, g_WPl);
    cudaGetSymbolAddress(&O16, g_O16);

    void* fnp = nullptr;
    cudaDriverEntryPointQueryResult qres;
    cudaGetDriverEntryPointByVersion("cuTensorMapEncodeTiled", &fnp, 12000,
                                     cudaEnableDefault, &qres);
    PFN_tmEncode enc = (PFN_tmEncode)fnp;

    CUtensorMap tA, tWAh, tWAl, tWPh, tWPl, tO, tT;
    make_map(enc, &tA,   A16,  M_TOK,  KDIM, 64, 128);
    make_map(enc, &tWAh, WAh,  N_QKV,  KDIM, 64, 128);
    make_map(enc, &tWAl, WAl,  N_QKV,  KDIM, 64, 128);
    make_map(enc, &tWPh, WPh,  DMODEL, KDIM, 64, 128);
    make_map(enc, &tWPl, WPl,  DMODEL, KDIM, 64, 128);
    make_map(enc, &tO,   O16,  M_TOK,  KDIM, 64, 128);
    make_map(enc, &tT,   qkv16, M_TOK, N_QKV, 64, 64);   // 64x64 tiles for Q/K/V

    cudaFuncSetAttribute(gemm_fp16x2_kernel<0>,
                         cudaFuncAttributeMaxDynamicSharedMemorySize, GEMM_SMEM);
    cudaFuncSetAttribute(gemm_fp16x2_kernel<1>,
                         cudaFuncAttributeMaxDynamicSharedMemorySize, GEMM_SMEM);
    cudaFuncSetAttribute(diff_attn_fused_kernel,
                         cudaFuncAttributeMaxDynamicSharedMemorySize, AT_SMEM);

    // 1) hidden -> fp16
    {
        int n4 = (M_TOK * KDIM) / 4;
        tofp16_kernel<<<n4 / 256, 256>>>((const float4*)hidden, (uint2*)A16, n4);
    }
    // 2) transpose+split weights (fp16 hi/lo)
    {
        dim3 g(N_QKV / 32, KDIM / 32);
        splitT16_kernel<<<g, dim3(32, 8)>>>(W_attn, (__half*)WAh, (__half*)WAl, KDIM, N_QKV);
    }
    {
        dim3 g(DMODEL / 32, KDIM / 32);
        splitT16_kernel<<<g, dim3(32, 8)>>>(W_proj, (__half*)WPh, (__half*)WPl, KDIM, DMODEL);
    }
    // 3) QKV GEMM (fp16 x2) -> fp16 single (q pre-scaled)
    {
        dim3 g(N_QKV / 128, M_TOK / 128);
        gemm_fp16x2_kernel<1><<<g, 256, GEMM_SMEM>>>(tA, tWAh, tWAl, b_attn,
                                                     nullptr, (unsigned short*)qkv16, N_QKV);
    }
    // 4) fused dual-stream differential attention -> fp16 O16
    {
        dim3 g(S_LEN / 64, B_SZ * NHEAD);   // (32, 32)
        diff_attn_fused_kernel<<<g, 256, AT_SMEM>>>(tT, amask, lam,
                                                    (unsigned short*)O16);
    }
    // 5) output projection (fp16 x2, fp32 out)
    {
        dim3 g(DMODEL / 128, M_TOK / 128);
        gemm_fp16x2_kernel<0><<<g, 256, GEMM_SMEM>>>(tO, tWPh, tWPl, b_proj,
                                                     out, nullptr, DMODEL);
    }
}

// round 13
// speedup vs baseline: 1.9198x; 1.1072x over previous
#include <cuda_runtime.h>
#include <cuda_fp16.h>
#include <cuda.h>
#include <cstdint>

// Problem dims (fixed by setup_inputs)
#define B_SZ   2
#define S_LEN  2048
#define DMODEL 2048
#define NHEAD  16
#define M_TOK  (B_SZ * S_LEN)     // 4096
#define N_QKV  (3 * DMODEL)       // 6144
#define KDIM   DMODEL             // 2048
#define QSCALE 0.0883883476483184f

// ---------------- scratch (static device globals: allocation-free) ----------
__device__ unsigned short g_qkv16[(size_t)M_TOK * N_QKV];  // fp16 qkv
__device__ unsigned short g_A16[(size_t)M_TOK * KDIM];     // fp16 hidden
__device__ unsigned short g_WAh[(size_t)N_QKV * KDIM];     // fp16 W_attn^T hi
__device__ unsigned short g_WAl[(size_t)N_QKV * KDIM];     // fp16 W_attn^T lo
__device__ unsigned short g_WPh[(size_t)DMODEL * KDIM];
__device__ unsigned short g_WPl[(size_t)DMODEL * KDIM];
__device__ unsigned short g_O16[(size_t)M_TOK * KDIM];     // fp16 combined attn out

// ---------------------------------------------------------------------------
// PTX helpers (base sm_90 only — no 'a'-gated instructions)
// ---------------------------------------------------------------------------
__device__ __forceinline__ uint32_t smem_u32(const void* p) {
    uint32_t a;
    asm("{ .reg .u64 t; cvta.to.shared.u64 t, %1; cvt.u32.u64 %0, t; }" : "=r"(a) : "l"(p));
    return a;
}

#define MBARRIER_INIT(addr, cnt) \
    asm volatile("mbarrier.init.shared.b64 [%0], %1;" :: "r"((uint32_t)(addr)), "r"((uint32_t)(cnt)) : "memory")

#define MBARRIER_ARRIVE(addr) \
    asm volatile("mbarrier.arrive.shared.b64 _, [%0];" :: "r"((uint32_t)(addr)) : "memory")

#define MBARRIER_EXPECT_TX(addr, bytes) \
    asm volatile("mbarrier.arrive.expect_tx.shared.b64 _, [%0], %1;" :: "r"((uint32_t)(addr)), "r"((uint32_t)(bytes)) : "memory")

#define MBARRIER_WAIT_PARITY(mbar_smem_addr, phase_parity) do { \
    uint32_t _mbar = (uint32_t)(mbar_smem_addr); \
    uint32_t _parity = (uint32_t)(phase_parity); \
    uint32_t _done; \
    asm volatile( \
        "{\n\t.reg .pred p;\n\t" \
        "mbarrier.try_wait.parity.acquire.cta.shared::cta.b64 p, [%1], %2;\n\t" \
        "selp.b32 %0, 1, 0, p;\n\t}" \
        : "=r"(_done) : "r"(_mbar), "r"(_parity) : "memory"); \
    if (!_done) { \
        asm volatile( \
            "{\n\t.reg .pred P1;\n\t" \
            "WAIT_LOOP_%=:\n\t" \
            "mbarrier.try_wait.parity.acquire.cta.shared::cta.b64 P1, [%0], %1, 0x989680;\n\t" \
            "@P1 bra.uni WAIT_DONE_%=;\n\t" \
            "bra.uni WAIT_LOOP_%=;\n\t" \
            "WAIT_DONE_%=:\n\t}" \
            :: "r"(_mbar), "r"(_parity) : "memory"); \
    } \
} while(0)

#define MBARRIER_WAIT_PARITY_RELAXED(mbar_smem_addr, phase_parity) do { \
    uint32_t _mbar = (uint32_t)(mbar_smem_addr); \
    uint32_t _parity = (uint32_t)(phase_parity); \
    uint32_t _done; \
    asm volatile( \
        "{\n\t.reg .pred p;\n\t" \
        "mbarrier.try_wait.parity.relaxed.cta.shared::cta.b64 p, [%1], %2, 0x989680;\n\t" \
        "selp.b32 %0, 1, 0, p;\n\t}" \
        : "=r"(_done) : "r"(_mbar), "r"(_parity) : "memory"); \
    if (!_done) { \
        asm volatile( \
            "{\n\t.reg .pred P1;\n\t" \
            "WAIT_LOOP_%=:\n\t" \
            "mbarrier.try_wait.parity.relaxed.cta.shared::cta.b64 P1, [%0], %1, 0x989680;\n\t" \
            "@P1 bra.uni WAIT_DONE_%=;\n\t" \
            "bra.uni WAIT_LOOP_%=;\n\t" \
            "WAIT_DONE_%=:\n\t}" \
            :: "r"(_mbar), "r"(_parity) : "memory"); \
    } \
} while(0)

__device__ __forceinline__ void tma2d(uint32_t dst, const void* map, int x, int y, uint32_t mbar) {
    asm volatile(
        "cp.async.bulk.tensor.2d.shared::cta.global.tile.mbarrier::complete_tx::bytes "
        "[%0], [%1, {%2, %3}], [%4];"
        :: "r"(dst), "l"(map), "r"(x), "r"(y), "r"(mbar) : "memory");
}

__device__ __forceinline__ void ldsm4(uint32_t* r, uint32_t addr) {
    asm volatile("ldmatrix.sync.aligned.m8n8.x4.shared.b16 {%0,%1,%2,%3}, [%4];"
                 : "=r"(r[0]), "=r"(r[1]), "=r"(r[2]), "=r"(r[3]) : "r"(addr));
}
__device__ __forceinline__ void ldsm4t(uint32_t* r, uint32_t addr) {
    asm volatile("ldmatrix.sync.aligned.m8n8.x4.trans.shared.b16 {%0,%1,%2,%3}, [%4];"
                 : "=r"(r[0]), "=r"(r[1]), "=r"(r[2]), "=r"(r[3]) : "r"(addr));
}

__device__ __forceinline__ void mma_fp16(float* d, const uint32_t* a, uint32_t b0, uint32_t b1) {
    asm volatile(
        "mma.sync.aligned.m16n8k16.row.col.f32.f16.f16.f32 "
        "{%0,%1,%2,%3}, {%4,%5,%6,%7}, {%8,%9}, {%0,%1,%2,%3};"
        : "+f"(d[0]), "+f"(d[1]), "+f"(d[2]), "+f"(d[3])
        : "r"(a[0]), "r"(a[1]), "r"(a[2]), "r"(a[3]), "r"(b0), "r"(b1));
}

__device__ __forceinline__ uint32_t pack2h(float a, float b) {
    __half2 t = __floats2half2_rn(a, b);
    return *reinterpret_cast<uint32_t*>(&t);
}

// Fast exp on the FMA pipe (no MUFU). Valid for x <= 0 (clamped below -80).
__device__ __forceinline__ float fexp(float x) {
    x = fmaxf(x, -80.0f);
    float t = x * 1.4426950408889634f;
    float z = t + 12582912.0f;
    int n = __float_as_int(z) - 0x4b400000;
    float f = t - (z - 12582912.0f);
    float u = f * 0.6931471805599453f;
    float r = 1.3888889e-3f;
    r = fmaf(r, u, 8.3333338e-3f);
    r = fmaf(r, u, 4.1666668e-2f);
    r = fmaf(r, u, 1.6666667e-1f);
    r = fmaf(r, u, 0.5f);
    r = fmaf(r, u, 1.0f);
    r = fmaf(r, u, 1.0f);
    return r * __int_as_float((n + 127) << 23);
}

// ---------------------------------------------------------------------------
// fp16 mixed-precision GEMM:  C[M,N] = A[M,K] @ B[N,K]^T + bias
// B lo-residual term applied only for output columns >= lo_start (per-CTA
// uniform). lo_start=0 -> always 2 terms. CTA 128x128, 8 warps 4Mx2N,
// K-chunk 64, SW128, 3-stage TMA.
// MODE 0: fp32 out.  MODE 1: fp16 single out, q-cols pre-scaled.
// ---------------------------------------------------------------------------
#define GCHUNKS     32
#define GTILE_BYTES 16384
#define GSTAGE_BYTES (3 * GTILE_BYTES)
#define GSM_DATA    1024
#define GEMM_SMEM   (GSM_DATA + 3 * GSTAGE_BYTES)

template <int MODE>
__global__ __launch_bounds__(256, 1)
void gemm_fp16x2_kernel(const __grid_constant__ CUtensorMap tmA,
                        const __grid_constant__ CUtensorMap tmBh,
                        const __grid_constant__ CUtensorMap tmBl,
                        const float* __restrict__ bias,
                        float* __restrict__ C,
                        unsigned short* __restrict__ Ch,
                        int N, int lo_start)
{
    extern __shared__ __align__(1024) char gsm[];
    const uint32_t sb = smem_u32(gsm);
    const int tid = threadIdx.x;
    const int lane = tid & 31;
    const int wid = tid >> 5;
    const int row0 = blockIdx.y * 128;
    const int col0 = blockIdx.x * 128;
    const int wm = (wid & 3) * 32;
    const int wn = (wid >> 2) * 64;
    const bool use_lo = (col0 >= lo_start);
    const uint32_t stage_tx = use_lo ? (uint32_t)GSTAGE_BYTES : (uint32_t)(2 * GTILE_BYTES);

    if (tid == 0) {
#pragma unroll
        for (int s = 0; s < 3; ++s) {
            MBARRIER_INIT(sb + 8 * s, 1);
            MBARRIER_INIT(sb + 24 + 8 * s, 256);
        }
    }
    __syncthreads();

    if (tid == 0) {
#pragma unroll
        for (int p = 0; p < 3; ++p) {
            const uint32_t st = sb + GSM_DATA + p * GSTAGE_BYTES;
            MBARRIER_EXPECT_TX(sb + 8 * p, stage_tx);
            const int k0 = p * 64;
            tma2d(st,               &tmA,  k0, row0, sb + 8 * p);
            tma2d(st + GTILE_BYTES, &tmBh, k0, col0, sb + 8 * p);
            if (use_lo)
                tma2d(st + 2 * GTILE_BYTES, &tmBl, k0, col0, sb + 8 * p);
        }
    }

    float acc[2][8][4];
#pragma unroll
    for (int i = 0; i < 2; i++)
#pragma unroll
        for (int j = 0; j < 8; j++)
#pragma unroll
            for (int k = 0; k < 4; k++) acc[i][j][k] = 0.f;

    const uint32_t cbase = (lane >> 4) * 16;
    uint32_t aRB[2], aMask[2], bRB[4], bMask[4];
#pragma unroll
    for (int mt = 0; mt < 2; ++mt) {
        const int r = wm + mt * 16 + (lane & 15);
        aRB[mt] = (uint32_t)r * 128;
        aMask[mt] = (uint32_t)((r & 7) << 4);
    }
#pragma unroll
    for (int j = 0; j < 4; ++j) {
        const int r = wn + j * 16 + (lane & 15);
        bRB[j] = (uint32_t)r * 128;
        bMask[j] = (uint32_t)((r & 7) << 4);
    }

    for (int c = 0; c < GCHUNKS; ++c) {
        const int u = c / 3;
        const int s = c - u * 3;
        MBARRIER_WAIT_PARITY(sb + 8 * s, (uint32_t)(u & 1));

        const uint32_t stA  = sb + GSM_DATA + s * GSTAGE_BYTES;
        const uint32_t stBh = stA + GTILE_BYTES;
        const uint32_t stBl = stA + 2 * GTILE_BYTES;

#pragma unroll
        for (int kk = 0; kk < 4; ++kk) {
            const uint32_t kb = cbase + kk * 32;
            uint32_t a[2][4], bh[4][4];
#pragma unroll
            for (int mt = 0; mt < 2; ++mt)
                ldsm4(a[mt], stA + aRB[mt] + (kb ^ aMask[mt]));
#pragma unroll
            for (int j = 0; j < 4; ++j)
                ldsm4(bh[j], stBh + bRB[j] + (kb ^ bMask[j]));
#pragma unroll
            for (int mt = 0; mt < 2; ++mt)
#pragma unroll
                for (int j = 0; j < 4; ++j) {
                    mma_fp16(acc[mt][2 * j],     a[mt], bh[j][0], bh[j][2]);
                    mma_fp16(acc[mt][2 * j + 1], a[mt], bh[j][1], bh[j][3]);
                }
            if (use_lo) {
                uint32_t bl[4][4];
#pragma unroll
                for (int j = 0; j < 4; ++j)
                    ldsm4(bl[j], stBl + bRB[j] + (kb ^ bMask[j]));
#pragma unroll
                for (int mt = 0; mt < 2; ++mt)
#pragma unroll
                    for (int j = 0; j < 4; ++j) {
                        mma_fp16(acc[mt][2 * j],     a[mt], bl[j][0], bl[j][2]);
                        mma_fp16(acc[mt][2 * j + 1], a[mt], bl[j][1], bl[j][3]);
                    }
            }
        }

        MBARRIER_ARRIVE(sb + 24 + 8 * s);

        const int p = c + 3;
        if (tid == 0 && p < GCHUNKS) {
            const int up = p / 3;
            MBARRIER_WAIT_PARITY_RELAXED(sb + 24 + 8 * s, (uint32_t)((up & 1) ^ 1));
            const uint32_t st = sb + GSM_DATA + s * GSTAGE_BYTES;
            MBARRIER_EXPECT_TX(sb + 8 * s, stage_tx);
            const int k0 = p * 64;
            tma2d(st,               &tmA,  k0, row0, sb + 8 * s);
            tma2d(st + GTILE_BYTES, &tmBh, k0, col0, sb + 8 * s);
            if (use_lo)
                tma2d(st + 2 * GTILE_BYTES, &tmBl, k0, col0, sb + 8 * s);
        }
    }

    // Epilogue
    const int rr = lane >> 2;
    const int cc = (lane & 3) * 2;
#pragma unroll
    for (int mt = 0; mt < 2; ++mt) {
        const int mrow = row0 + wm + mt * 16 + rr;
#pragma unroll
        for (int nt = 0; nt < 8; ++nt) {
            const int n = col0 + wn + nt * 8 + cc;
            const float2 bb = *(const float2*)(bias + n);
            float v00 = acc[mt][nt][0] + bb.x, v01 = acc[mt][nt][1] + bb.y;
            float v10 = acc[mt][nt][2] + bb.x, v11 = acc[mt][nt][3] + bb.y;
            if (MODE == 0) {
                *(float2*)(C + (size_t)mrow * N + n) = make_float2(v00, v01);
                *(float2*)(C + (size_t)(mrow + 8) * N + n) = make_float2(v10, v11);
            } else {
                const float sc = (n < 2048) ? QSCALE : 1.0f;
                *(uint32_t*)(Ch + (size_t)mrow * N + n)       = pack2h(v00 * sc, v01 * sc);
                *(uint32_t*)(Ch + (size_t)(mrow + 8) * N + n) = pack2h(v10 * sc, v11 * sc);
            }
        }
    }
}

// ---------------------------------------------------------------------------
// Fused dual-stream differential flash attention (unchanged from R12).
// ---------------------------------------------------------------------------
#define AT_STAGE_BYTES 32768           // K1 8K | K2 8K | V 16K
#define AT_SMEM (32768 + 2 * AT_STAGE_BYTES)   // 98304

__global__ __launch_bounds__(256, 1)
void diff_attn_fused_kernel(const __grid_constant__ CUtensorMap tmT,
                            const float* __restrict__ amask,
                            const float* __restrict__ lambda_p,
                            unsigned short* __restrict__ O16)
{
    extern __shared__ __align__(1024) char asmem[];
    const uint32_t sb = smem_u32(asmem);
    const int tid = threadIdx.x, lane = tid & 31, w = tid >> 5;
    const int s_id = w >> 2;
    const int wq = w & 3;
    const int qb = blockIdx.x, bh = blockIdx.y;
    const int b = bh >> 4, h = bh & 15;
    const int q0 = qb * 64;
    const int tokbase = b * S_LEN;

    const uint32_t MB_Q = sb, MB_F0 = sb + 8, MB_F1 = sb + 16, MB_E0 = sb + 24, MB_E1 = sb + 32;
    float* maskSm = (float*)(asmem + 64);
    const uint32_t Q1 = sb + 16384;
    const uint32_t Q2 = sb + 24576;
    const uint32_t ST0 = sb + 32768;

    if (tid == 0) {
        MBARRIER_INIT(MB_Q, 1);
        MBARRIER_INIT(MB_F0, 1); MBARRIER_INIT(MB_F1, 1);
        MBARRIER_INIT(MB_E0, 256); MBARRIER_INIT(MB_E1, 256);
    }
    {
        const float4* mp = (const float4*)(amask + tokbase);
        float4* ms = (float4*)maskSm;
#pragma unroll
        for (int i = tid; i < 512; i += 256) {
            float4 v = mp[i];
            v.x = (1.f - v.x) * -10000.f;
            v.y = (1.f - v.y) * -10000.f;
            v.z = (1.f - v.z) * -10000.f;
            v.w = (1.f - v.w) * -10000.f;
            ms[i] = v;
        }
    }
    __syncthreads();

    const int q1col = h * 64;
    const int q2col = 1024 + h * 64;
    const int k1col = 2048 + h * 64;
    const int k2col = 3072 + h * 64;
    const int vcol  = 4096 + h * 128;

    if (tid == 0) {
        MBARRIER_EXPECT_TX(MB_Q, 16384);
        tma2d(Q1, &tmT, q1col, tokbase + q0, MB_Q);
        tma2d(Q2, &tmT, q2col, tokbase + q0, MB_Q);
#pragma unroll
        for (int s = 0; s < 2; ++s) {
            const uint32_t st = ST0 + s * AT_STAGE_BYTES;
            const uint32_t fb = s ? MB_F1 : MB_F0;
            MBARRIER_EXPECT_TX(fb, AT_STAGE_BYTES);
            const int k0 = tokbase + s * 64;
            tma2d(st,         &tmT, k1col,     k0, fb);
            tma2d(st + 8192,  &tmT, k2col,     k0, fb);
            tma2d(st + 16384, &tmT, vcol,      k0, fb);
            tma2d(st + 24576, &tmT, vcol + 64, k0, fb);
        }
    }

    MBARRIER_WAIT_PARITY(MB_Q, 0);
    uint32_t qh[4][4];
    {
        const uint32_t QT = s_id ? Q2 : Q1;
        const int r = 16 * wq + (lane & 15);
        const uint32_t rb = (uint32_t)r * 128;
        const uint32_t msk = (uint32_t)((r & 7) << 4);
        const uint32_t cbq = (uint32_t)(lane >> 4) * 16;
#pragma unroll
        for (int kk = 0; kk < 4; ++kk)
            ldsm4(qh[kk], QT + rb + ((cbq + kk * 32) ^ msk));
    }

    float o[16][4];
#pragma unroll
    for (int i = 0; i < 16; i++)
#pragma unroll
        for (int j = 0; j < 4; j++) o[i][j] = 0.f;
    float m0 = -1e30f, m1 = -1e30f, l0 = 0.f, l1 = 0.f;

    uint32_t kRB[4], kMask[4];
#pragma unroll
    for (int g = 0; g < 4; ++g) {
        const int r = 16 * g + (lane & 15);
        kRB[g] = (uint32_t)r * 128;
        kMask[g] = (uint32_t)((r & 7) << 4);
    }
    const uint32_t cb = (uint32_t)(lane >> 4) * 16;
    const uint32_t kOff = (uint32_t)s_id * 8192;

    for (int kb = 0; kb < 32; ++kb) {
        const int s = kb & 1, u = kb >> 1;
        const uint32_t FULL = s ? MB_F1 : MB_F0;
        const uint32_t EMPTY = s ? MB_E1 : MB_E0;
        const uint32_t ST = ST0 + s * AT_STAGE_BYTES;
        MBARRIER_WAIT_PARITY(FULL, (uint32_t)(u & 1));

        float scf[8][4];
#pragma unroll
        for (int t = 0; t < 8; t++)
#pragma unroll
            for (int j = 0; j < 4; j++) scf[t][j] = 0.f;

#pragma unroll
        for (int kk = 0; kk < 4; ++kk) {
            uint32_t kh[4][4];
#pragma unroll
            for (int g = 0; g < 4; ++g) {
                const uint32_t a = cb + kk * 32;
                ldsm4(kh[g], ST + kOff + kRB[g] + (a ^ kMask[g]));
            }
#pragma unroll
            for (int g = 0; g < 4; ++g) {
                mma_fp16(scf[2 * g],     qh[kk], kh[g][0], kh[g][2]);
                mma_fp16(scf[2 * g + 1], qh[kk], kh[g][1], kh[g][3]);
            }
        }

        const int kbase = kb * 64 + 2 * (lane & 3);
        float nm0 = m0, nm1 = m1;
#pragma unroll
        for (int t = 0; t < 8; ++t) {
            const float mv0 = maskSm[kbase + 8 * t];
            const float mv1 = maskSm[kbase + 8 * t + 1];
            scf[t][0] += mv0; scf[t][1] += mv1;
            scf[t][2] += mv0; scf[t][3] += mv1;
            nm0 = fmaxf(nm0, fmaxf(scf[t][0], scf[t][1]));
            nm1 = fmaxf(nm1, fmaxf(scf[t][2], scf[t][3]));
        }
        nm0 = fmaxf(nm0, __shfl_xor_sync(0xffffffffu, nm0, 1));
        nm0 = fmaxf(nm0, __shfl_xor_sync(0xffffffffu, nm0, 2));
        nm1 = fmaxf(nm1, __shfl_xor_sync(0xffffffffu, nm1, 1));
        nm1 = fmaxf(nm1, __shfl_xor_sync(0xffffffffu, nm1, 2));
        const float a0 = fexp(m0 - nm0), a1 = fexp(m1 - nm1);
        m0 = nm0; m1 = nm1;
#pragma unroll
        for (int nt = 0; nt < 16; ++nt) {
            o[nt][0] *= a0; o[nt][1] *= a0;
            o[nt][2] *= a1; o[nt][3] *= a1;
        }

        uint32_t pha[4][4];
        float rs0 = 0.f, rs1 = 0.f;
#pragma unroll
        for (int t = 0; t < 8; ++t) {
            const float e0 = fexp(scf[t][0] - m0), e1 = fexp(scf[t][1] - m0);
            const float e2 = fexp(scf[t][2] - m1), e3 = fexp(scf[t][3] - m1);
            rs0 += e0 + e1; rs1 += e2 + e3;
            pha[t >> 1][2 * (t & 1)]     = pack2h(e0, e1);
            pha[t >> 1][2 * (t & 1) + 1] = pack2h(e2, e3);
        }
        rs0 += __shfl_xor_sync(0xffffffffu, rs0, 1);
        rs0 += __shfl_xor_sync(0xffffffffu, rs0, 2);
        rs1 += __shfl_xor_sync(0xffffffffu, rs1, 1);
        rs1 += __shfl_xor_sync(0xffffffffu, rs1, 2);
        l0 = l0 * a0 + rs0;
        l1 = l1 * a1 + rs1;

#pragma unroll
        for (int kk = 0; kk < 4; ++kk) {
            const int r = 16 * kk + (lane & 15);
            const uint32_t vrb = (uint32_t)r * 128;
            const uint32_t vmsk = (uint32_t)((r & 7) << 4);
#pragma unroll
            for (int g = 0; g < 8; ++g) {
                const uint32_t base = ST + 16384 + ((g >> 2) ? 8192u : 0u);
                const uint32_t a = ((uint32_t)((g & 3) * 32) + cb) ^ vmsk;
                uint32_t vh[4];
                ldsm4t(vh, base + vrb + a);
                mma_fp16(o[2 * g],     pha[kk], vh[0], vh[1]);
                mma_fp16(o[2 * g + 1], pha[kk], vh[2], vh[3]);
            }
        }

        MBARRIER_ARRIVE(EMPTY);

        if (tid == 0 && kb + 2 < 32) {
            const int p = kb + 2;
            MBARRIER_WAIT_PARITY_RELAXED(EMPTY, (uint32_t)((((p >> 1) & 1) ^ 1)));
            MBARRIER_EXPECT_TX(FULL, AT_STAGE_BYTES);
            const int k0 = tokbase + p * 64;
            tma2d(ST,         &tmT, k1col,     k0, FULL);
            tma2d(ST + 8192,  &tmT, k2col,     k0, FULL);
            tma2d(ST + 16384, &tmT, vcol,      k0, FULL);
            tma2d(ST + 24576, &tmT, vcol + 64, k0, FULL);
        }
    }

    __syncthreads();
    float* Cb = (float*)(asmem + 32768 + s_id * 32768);
    {
        const float inv0 = 1.f / l0, inv1 = 1.f / l1;
        const int r0 = 16 * wq + (lane >> 2);
        const int cc = 2 * (lane & 3);
#pragma unroll
        for (int nt = 0; nt < 16; ++nt) {
            Cb[r0 * 128 + 8 * nt + cc]           = o[nt][0] * inv0;
            Cb[r0 * 128 + 8 * nt + cc + 1]       = o[nt][1] * inv0;
            Cb[(r0 + 8) * 128 + 8 * nt + cc]     = o[nt][2] * inv1;
            Cb[(r0 + 8) * 128 + 8 * nt + cc + 1] = o[nt][3] * inv1;
        }
    }
    __syncthreads();

    const float lam = *lambda_p;
    const float* C1b = (const float*)(asmem + 32768);
    const float* C2b = (const float*)(asmem + 65536);
    for (int idx = tid; idx < 64 * 32; idx += 256) {
        const int row = idx >> 5;
        const int c4 = (idx & 31) * 4;
        float4 a = *(const float4*)&C1b[row * 128 + c4];
        float4 c = *(const float4*)&C2b[row * 128 + c4];
        uint2 H;
        H.x = pack2h(a.x - lam * c.x, a.y - lam * c.y);
        H.y = pack2h(a.z - lam * c.z, a.w - lam * c.w);
        *(uint2*)(O16 + (size_t)(tokbase + q0 + row) * DMODEL + h * 128 + c4) = H;
    }
}

// ---------------------------------------------------------------------------
// fp32 -> fp16 single (hidden -> A)
// ---------------------------------------------------------------------------
__global__ __launch_bounds__(256)
void tofp16_kernel(const float4* __restrict__ x, uint2* __restrict__ y, int n4)
{
    int i = blockIdx.x * blockDim.x + threadIdx.x;
    if (i >= n4) return;
    float4 v = x[i];
    uint2 H;
    H.x = pack2h(v.x, v.y);
    H.y = pack2h(v.z, v.w);
    y[i] = H;
}

// fp32 W[K][N] -> transposed fp16 hi/lo: hiT[N][K], loT[N][K]
__global__ __launch_bounds__(256)
void splitT16_kernel(const float* __restrict__ W, __half* __restrict__ hiT,
                     __half* __restrict__ loT, int K, int N)
{
    __shared__ float t[32][33];
    const int tx = threadIdx.x, ty = threadIdx.y;
    const int n0 = blockIdx.x * 32, k0 = blockIdx.y * 32;
#pragma unroll
    for (int r = 0; r < 4; ++r)
        t[ty + 8 * r][tx] = W[(size_t)(k0 + ty + 8 * r) * N + n0 + tx];
    __syncthreads();
#pragma unroll
    for (int r = 0; r < 4; ++r) {
        const int nn = ty + 8 * r;
        float v = t[tx][nn];
        __half hh = __float2half_rn(v);
        __half ll = __float2half_rn(v - __half2float(hh));
        const size_t off = (size_t)(n0 + nn) * K + k0 + tx;
        hiT[off] = hh;
        loT[off] = ll;
    }
}

// ---------------------------------------------------------------------------
// Host side
// ---------------------------------------------------------------------------
typedef CUresult (*PFN_tmEncode)(
    CUtensorMap*, CUtensorMapDataType, cuuint32_t, void*,
    const cuuint64_t*, const cuuint64_t*, const cuuint32_t*, const cuuint32_t*,
    CUtensorMapInterleave, CUtensorMapSwizzle, CUtensorMapL2promotion,
    CUtensorMapFloatOOBfill);

static void make_map(PFN_tmEncode fn, CUtensorMap* m, void* ptr,
                     unsigned long long rows, unsigned long long cols,
                     unsigned box0, unsigned box1)
{
    cuuint64_t dims[2]    = {(cuuint64_t)cols, (cuuint64_t)rows};
    cuuint64_t strides[1] = {(cuuint64_t)cols * 2};
    cuuint32_t box[2]     = {box0, box1};
    cuuint32_t es[2]      = {1u, 1u};
    fn(m, CU_TENSOR_MAP_DATA_TYPE_BFLOAT16, 2, ptr, dims, strides, box, es,
       CU_TENSOR_MAP_INTERLEAVE_NONE, CU_TENSOR_MAP_SWIZZLE_128B,
       CU_TENSOR_MAP_L2_PROMOTION_L2_128B, CU_TENSOR_MAP_FLOAT_OOB_FILL_NONE);
}

extern "C" void kernel_launch(void* const* d_in, const int* in_sizes, int n_in,
                              void* d_out, int out_size)
{
    const float* hidden = (const float*)d_in[0];
    const float* amask  = (const float*)d_in[1];
    const float* W_attn = (const float*)d_in[2];
    const float* b_attn = (const float*)d_in[3];
    const float* W_proj = (const float*)d_in[4];
    const float* b_proj = (const float*)d_in[5];
    const float* lam    = (const float*)d_in[6];
    float* out = (float*)d_out;

    void *qkv16, *A16, *WAh, *WAl, *WPh, *WPl, *O16;
    cudaGetSymbolAddress(&qkv16, g_qkv16);
    cudaGetSymbolAddress(&A16, g_A16);
    cudaGetSymbolAddress(&WAh, g_WAh);   cudaGetSymbolAddress(&WAl, g_WAl);
    cudaGetSymbolAddress(&WPh, g_WPh);   cudaGetSymbolAddress(&WPl, g_WPl);
    cudaGetSymbolAddress(&O16, g_O16);

    void* fnp = nullptr;
    cudaDriverEntryPointQueryResult qres;
    cudaGetDriverEntryPointByVersion("cuTensorMapEncodeTiled", &fnp, 12000,
                                     cudaEnableDefault, &qres);
    PFN_tmEncode enc = (PFN_tmEncode)fnp;

    CUtensorMap tA, tWAh, tWAl, tWPh, tWPl, tO, tT;
    make_map(enc, &tA,   A16,  M_TOK,  KDIM, 64, 128);
    make_map(enc, &tWAh, WAh,  N_QKV,  KDIM, 64, 128);
    make_map(enc, &tWAl, WAl,  N_QKV,  KDIM, 64, 128);
    make_map(enc, &tWPh, WPh,  DMODEL, KDIM, 64, 128);
    make_map(enc, &tWPl, WPl,  DMODEL, KDIM, 64, 128);
    make_map(enc, &tO,   O16,  M_TOK,  KDIM, 64, 128);
    make_map(enc, &tT,   qkv16, M_TOK, N_QKV, 64, 64);

    cudaFuncSetAttribute(gemm_fp16x2_kernel<0>,
                         cudaFuncAttributeMaxDynamicSharedMemorySize, GEMM_SMEM);
    cudaFuncSetAttribute(gemm_fp16x2_kernel<1>,
                         cudaFuncAttributeMaxDynamicSharedMemorySize, GEMM_SMEM);
    cudaFuncSetAttribute(diff_attn_fused_kernel,
                         cudaFuncAttributeMaxDynamicSharedMemorySize, AT_SMEM);

    // 1) hidden -> fp16
    {
        int n4 = (M_TOK * KDIM) / 4;
        tofp16_kernel<<<n4 / 256, 256>>>((const float4*)hidden, (uint2*)A16, n4);
    }
    // 2) transpose+split weights (fp16 hi/lo)
    {
        dim3 g(N_QKV / 32, KDIM / 32);
        splitT16_kernel<<<g, dim3(32, 8)>>>(W_attn, (__half*)WAh, (__half*)WAl, KDIM, N_QKV);
    }
    {
        dim3 g(DMODEL / 32, KDIM / 32);
        splitT16_kernel<<<g, dim3(32, 8)>>>(W_proj, (__half*)WPh, (__half*)WPl, KDIM, DMODEL);
    }
    // 3) QKV GEMM: 1-term for q/k columns (<4096), 2-term for v columns
    {
        dim3 g(N_QKV / 128, M_TOK / 128);
        gemm_fp16x2_kernel<1><<<g, 256, GEMM_SMEM>>>(tA, tWAh, tWAl, b_attn,
                                                     nullptr, (unsigned short*)qkv16,
                                                     N_QKV, 4096);
    }
    // 4) fused dual-stream differential attention -> fp16 O16
    {
        dim3 g(S_LEN / 64, B_SZ * NHEAD);
        diff_attn_fused_kernel<<<g, 256, AT_SMEM>>>(tT, amask, lam,
                                                    (unsigned short*)O16);
    }
    // 5) output projection (fp16 x2 everywhere, fp32 out)
    {
        dim3 g(DMODEL / 128, M_TOK / 128);
        gemm_fp16x2_kernel<0><<<g, 256, GEMM_SMEM>>>(tO, tWPh, tWPl, b_proj,
                                                     out, nullptr, DMODEL, 0);
    }
}

// round 14
// speedup vs baseline: 1.9237x; 1.0020x over previous
#include <cuda_runtime.h>
#include <cuda_fp16.h>
#include <cuda.h>
#include <cstdint>

// Problem dims (fixed by setup_inputs)
#define B_SZ   2
#define S_LEN  2048
#define DMODEL 2048
#define NHEAD  16
#define M_TOK  (B_SZ * S_LEN)     // 4096
#define N_QKV  (3 * DMODEL)       // 6144
#define KDIM   DMODEL             // 2048
#define QSCALE 0.0883883476483184f

// ---------------- scratch (static device globals: allocation-free) ----------
__device__ unsigned short g_qkv16[(size_t)M_TOK * N_QKV];
__device__ unsigned short g_A16[(size_t)M_TOK * KDIM];
__device__ unsigned short g_WAh[(size_t)N_QKV * KDIM];
__device__ unsigned short g_WAl[(size_t)N_QKV * KDIM];
__device__ unsigned short g_WPh[(size_t)DMODEL * KDIM];
__device__ unsigned short g_WPl[(size_t)DMODEL * KDIM];
__device__ unsigned short g_O16[(size_t)M_TOK * KDIM];

// ---------------------------------------------------------------------------
// PTX helpers (base sm_90 only)
// ---------------------------------------------------------------------------
__device__ __forceinline__ uint32_t smem_u32(const void* p) {
    uint32_t a;
    asm("{ .reg .u64 t; cvta.to.shared.u64 t, %1; cvt.u32.u64 %0, t; }" : "=r"(a) : "l"(p));
    return a;
}

#define MBARRIER_INIT(addr, cnt) \
    asm volatile("mbarrier.init.shared.b64 [%0], %1;" :: "r"((uint32_t)(addr)), "r"((uint32_t)(cnt)) : "memory")

#define MBARRIER_ARRIVE(addr) \
    asm volatile("mbarrier.arrive.shared.b64 _, [%0];" :: "r"((uint32_t)(addr)) : "memory")

#define MBARRIER_EXPECT_TX(addr, bytes) \
    asm volatile("mbarrier.arrive.expect_tx.shared.b64 _, [%0], %1;" :: "r"((uint32_t)(addr)), "r"((uint32_t)(bytes)) : "memory")

#define MBARRIER_WAIT_PARITY(mbar_smem_addr, phase_parity) do { \
    uint32_t _mbar = (uint32_t)(mbar_smem_addr); \
    uint32_t _parity = (uint32_t)(phase_parity); \
    uint32_t _done; \
    asm volatile( \
        "{\n\t.reg .pred p;\n\t" \
        "mbarrier.try_wait.parity.acquire.cta.shared::cta.b64 p, [%1], %2;\n\t" \
        "selp.b32 %0, 1, 0, p;\n\t}" \
        : "=r"(_done) : "r"(_mbar), "r"(_parity) : "memory"); \
    if (!_done) { \
        asm volatile( \
            "{\n\t.reg .pred P1;\n\t" \
            "WAIT_LOOP_%=:\n\t" \
            "mbarrier.try_wait.parity.acquire.cta.shared::cta.b64 P1, [%0], %1, 0x989680;\n\t" \
            "@P1 bra.uni WAIT_DONE_%=;\n\t" \
            "bra.uni WAIT_LOOP_%=;\n\t" \
            "WAIT_DONE_%=:\n\t}" \
            :: "r"(_mbar), "r"(_parity) : "memory"); \
    } \
} while(0)

#define MBARRIER_WAIT_PARITY_RELAXED(mbar_smem_addr, phase_parity) do { \
    uint32_t _mbar = (uint32_t)(mbar_smem_addr); \
    uint32_t _parity = (uint32_t)(phase_parity); \
    uint32_t _done; \
    asm volatile( \
        "{\n\t.reg .pred p;\n\t" \
        "mbarrier.try_wait.parity.relaxed.cta.shared::cta.b64 p, [%1], %2, 0x989680;\n\t" \
        "selp.b32 %0, 1, 0, p;\n\t}" \
        : "=r"(_done) : "r"(_mbar), "r"(_parity) : "memory"); \
    if (!_done) { \
        asm volatile( \
            "{\n\t.reg .pred P1;\n\t" \
            "WAIT_LOOP_%=:\n\t" \
            "mbarrier.try_wait.parity.relaxed.cta.shared::cta.b64 P1, [%0], %1, 0x989680;\n\t" \
            "@P1 bra.uni WAIT_DONE_%=;\n\t" \
            "bra.uni WAIT_LOOP_%=;\n\t" \
            "WAIT_DONE_%=:\n\t}" \
            :: "r"(_mbar), "r"(_parity) : "memory"); \
    } \
} while(0)

__device__ __forceinline__ void tma2d(uint32_t dst, const void* map, int x, int y, uint32_t mbar) {
    asm volatile(
        "cp.async.bulk.tensor.2d.shared::cta.global.tile.mbarrier::complete_tx::bytes "
        "[%0], [%1, {%2, %3}], [%4];"
        :: "r"(dst), "l"(map), "r"(x), "r"(y), "r"(mbar) : "memory");
}

__device__ __forceinline__ void ldsm4(uint32_t* r, uint32_t addr) {
    asm volatile("ldmatrix.sync.aligned.m8n8.x4.shared.b16 {%0,%1,%2,%3}, [%4];"
                 : "=r"(r[0]), "=r"(r[1]), "=r"(r[2]), "=r"(r[3]) : "r"(addr));
}
__device__ __forceinline__ void ldsm4t(uint32_t* r, uint32_t addr) {
    asm volatile("ldmatrix.sync.aligned.m8n8.x4.trans.shared.b16 {%0,%1,%2,%3}, [%4];"
                 : "=r"(r[0]), "=r"(r[1]), "=r"(r[2]), "=r"(r[3]) : "r"(addr));
}

__device__ __forceinline__ void mma_fp16(float* d, const uint32_t* a, uint32_t b0, uint32_t b1) {
    asm volatile(
        "mma.sync.aligned.m16n8k16.row.col.f32.f16.f16.f32 "
        "{%0,%1,%2,%3}, {%4,%5,%6,%7}, {%8,%9}, {%0,%1,%2,%3};"
        : "+f"(d[0]), "+f"(d[1]), "+f"(d[2]), "+f"(d[3])
        : "r"(a[0]), "r"(a[1]), "r"(a[2]), "r"(a[3]), "r"(b0), "r"(b1));
}

__device__ __forceinline__ uint32_t pack2h(float a, float b) {
    __half2 t = __floats2half2_rn(a, b);
    return *reinterpret_cast<uint32_t*>(&t);
}

// Fast exp on the FMA pipe. Valid for x <= 0 (clamped below -80).
__device__ __forceinline__ float fexp(float x) {
    x = fmaxf(x, -80.0f);
    float t = x * 1.4426950408889634f;
    float z = t + 12582912.0f;
    int n = __float_as_int(z) - 0x4b400000;
    float f = t - (z - 12582912.0f);
    float u = f * 0.6931471805599453f;
    float r = 1.3888889e-3f;
    r = fmaf(r, u, 8.3333338e-3f);
    r = fmaf(r, u, 4.1666668e-2f);
    r = fmaf(r, u, 1.6666667e-1f);
    r = fmaf(r, u, 0.5f);
    r = fmaf(r, u, 1.0f);
    r = fmaf(r, u, 1.0f);
    return r * __int_as_float((n + 127) << 23);
}

// ---------------------------------------------------------------------------
// fp16 mixed-precision GEMM:  C[M,N] = A[M,K] @ B[N,K]^T + bias
// B lo-residual only for output columns >= lo_start. col_shift rotates the
// column-block schedule so heavy (2-term) CTAs launch first.
// MODE 0: fp32 out.  MODE 1: fp16 single out, q-cols pre-scaled.
// ---------------------------------------------------------------------------
#define GCHUNKS     32
#define GTILE_BYTES 16384
#define GSTAGE_BYTES (3 * GTILE_BYTES)
#define GSM_DATA    1024
#define GEMM_SMEM   (GSM_DATA + 3 * GSTAGE_BYTES)

template <int MODE>
__global__ __launch_bounds__(256, 1)
void gemm_fp16x2_kernel(const __grid_constant__ CUtensorMap tmA,
                        const __grid_constant__ CUtensorMap tmBh,
                        const __grid_constant__ CUtensorMap tmBl,
                        const float* __restrict__ bias,
                        float* __restrict__ C,
                        unsigned short* __restrict__ Ch,
                        int N, int lo_start, int col_shift)
{
    extern __shared__ __align__(1024) char gsm[];
    const uint32_t sb = smem_u32(gsm);
    const int tid = threadIdx.x;
    const int lane = tid & 31;
    const int wid = tid >> 5;
    const int row0 = blockIdx.y * 128;
    const int cidx = ((int)blockIdx.x + col_shift) % (int)gridDim.x;
    const int col0 = cidx * 128;
    const int wm = (wid & 3) * 32;
    const int wn = (wid >> 2) * 64;
    const bool use_lo = (col0 >= lo_start);
    const uint32_t stage_tx = use_lo ? (uint32_t)GSTAGE_BYTES : (uint32_t)(2 * GTILE_BYTES);

    if (tid == 0) {
#pragma unroll
        for (int s = 0; s < 3; ++s) {
            MBARRIER_INIT(sb + 8 * s, 1);
            MBARRIER_INIT(sb + 24 + 8 * s, 256);
        }
    }
    __syncthreads();

    if (tid == 0) {
#pragma unroll
        for (int p = 0; p < 3; ++p) {
            const uint32_t st = sb + GSM_DATA + p * GSTAGE_BYTES;
            MBARRIER_EXPECT_TX(sb + 8 * p, stage_tx);
            const int k0 = p * 64;
            tma2d(st,               &tmA,  k0, row0, sb + 8 * p);
            tma2d(st + GTILE_BYTES, &tmBh, k0, col0, sb + 8 * p);
            if (use_lo)
                tma2d(st + 2 * GTILE_BYTES, &tmBl, k0, col0, sb + 8 * p);
        }
    }

    float acc[2][8][4];
#pragma unroll
    for (int i = 0; i < 2; i++)
#pragma unroll
        for (int j = 0; j < 8; j++)
#pragma unroll
            for (int k = 0; k < 4; k++) acc[i][j][k] = 0.f;

    const uint32_t cbase = (lane >> 4) * 16;
    uint32_t aRB[2], aMask[2], bRB[4], bMask[4];
#pragma unroll
    for (int mt = 0; mt < 2; ++mt) {
        const int r = wm + mt * 16 + (lane & 15);
        aRB[mt] = (uint32_t)r * 128;
        aMask[mt] = (uint32_t)((r & 7) << 4);
    }
#pragma unroll
    for (int j = 0; j < 4; ++j) {
        const int r = wn + j * 16 + (lane & 15);
        bRB[j] = (uint32_t)r * 128;
        bMask[j] = (uint32_t)((r & 7) << 4);
    }

    for (int c = 0; c < GCHUNKS; ++c) {
        const int u = c / 3;
        const int s = c - u * 3;
        MBARRIER_WAIT_PARITY(sb + 8 * s, (uint32_t)(u & 1));

        const uint32_t stA  = sb + GSM_DATA + s * GSTAGE_BYTES;
        const uint32_t stBh = stA + GTILE_BYTES;
        const uint32_t stBl = stA + 2 * GTILE_BYTES;

#pragma unroll
        for (int kk = 0; kk < 4; ++kk) {
            const uint32_t kb = cbase + kk * 32;
            uint32_t a[2][4], bh[4][4];
#pragma unroll
            for (int mt = 0; mt < 2; ++mt)
                ldsm4(a[mt], stA + aRB[mt] + (kb ^ aMask[mt]));
#pragma unroll
            for (int j = 0; j < 4; ++j)
                ldsm4(bh[j], stBh + bRB[j] + (kb ^ bMask[j]));
#pragma unroll
            for (int mt = 0; mt < 2; ++mt)
#pragma unroll
                for (int j = 0; j < 4; ++j) {
                    mma_fp16(acc[mt][2 * j],     a[mt], bh[j][0], bh[j][2]);
                    mma_fp16(acc[mt][2 * j + 1], a[mt], bh[j][1], bh[j][3]);
                }
            if (use_lo) {
                uint32_t bl[4][4];
#pragma unroll
                for (int j = 0; j < 4; ++j)
                    ldsm4(bl[j], stBl + bRB[j] + (kb ^ bMask[j]));
#pragma unroll
                for (int mt = 0; mt < 2; ++mt)
#pragma unroll
                    for (int j = 0; j < 4; ++j) {
                        mma_fp16(acc[mt][2 * j],     a[mt], bl[j][0], bl[j][2]);
                        mma_fp16(acc[mt][2 * j + 1], a[mt], bl[j][1], bl[j][3]);
                    }
            }
        }

        MBARRIER_ARRIVE(sb + 24 + 8 * s);

        const int p = c + 3;
        if (tid == 0 && p < GCHUNKS) {
            const int up = p / 3;
            MBARRIER_WAIT_PARITY_RELAXED(sb + 24 + 8 * s, (uint32_t)((up & 1) ^ 1));
            const uint32_t st = sb + GSM_DATA + s * GSTAGE_BYTES;
            MBARRIER_EXPECT_TX(sb + 8 * s, stage_tx);
            const int k0 = p * 64;
            tma2d(st,               &tmA,  k0, row0, sb + 8 * s);
            tma2d(st + GTILE_BYTES, &tmBh, k0, col0, sb + 8 * s);
            if (use_lo)
                tma2d(st + 2 * GTILE_BYTES, &tmBl, k0, col0, sb + 8 * s);
        }
    }

    // Epilogue
    const int rr = lane >> 2;
    const int cc = (lane & 3) * 2;
#pragma unroll
    for (int mt = 0; mt < 2; ++mt) {
        const int mrow = row0 + wm + mt * 16 + rr;
#pragma unroll
        for (int nt = 0; nt < 8; ++nt) {
            const int n = col0 + wn + nt * 8 + cc;
            const float2 bb = *(const float2*)(bias + n);
            float v00 = acc[mt][nt][0] + bb.x, v01 = acc[mt][nt][1] + bb.y;
            float v10 = acc[mt][nt][2] + bb.x, v11 = acc[mt][nt][3] + bb.y;
            if (MODE == 0) {
                *(float2*)(C + (size_t)mrow * N + n) = make_float2(v00, v01);
                *(float2*)(C + (size_t)(mrow + 8) * N + n) = make_float2(v10, v11);
            } else {
                const float sc = (n < 2048) ? QSCALE : 1.0f;
                *(uint32_t*)(Ch + (size_t)mrow * N + n)       = pack2h(v00 * sc, v01 * sc);
                *(uint32_t*)(Ch + (size_t)(mrow + 8) * N + n) = pack2h(v10 * sc, v11 * sc);
            }
        }
    }
}

// ---------------------------------------------------------------------------
// Fused dual-stream differential flash attention, single-term fp16,
// 3-stage TMA pipeline. CTA = 64 q-rows x both streams.
// ---------------------------------------------------------------------------
#define AT_NSTG 3
#define AT_STAGE_BYTES 32768           // K1 8K | K2 8K | V 16K
#define AT_SMEM (32768 + AT_NSTG * AT_STAGE_BYTES)   // 131072

__global__ __launch_bounds__(256, 1)
void diff_attn_fused_kernel(const __grid_constant__ CUtensorMap tmT,
                            const float* __restrict__ amask,
                            const float* __restrict__ lambda_p,
                            unsigned short* __restrict__ O16)
{
    extern __shared__ __align__(1024) char asmem[];
    const uint32_t sb = smem_u32(asmem);
    const int tid = threadIdx.x, lane = tid & 31, w = tid >> 5;
    const int s_id = w >> 2;
    const int wq = w & 3;
    const int qb = blockIdx.x, bh = blockIdx.y;
    const int b = bh >> 4, h = bh & 15;
    const int q0 = qb * 64;
    const int tokbase = b * S_LEN;

    const uint32_t MB_Q = sb;
    // full[s] = sb+8+8s, empty[s] = sb+32+8s  (s = 0..2)
    float* maskSm = (float*)(asmem + 64);
    const uint32_t Q1 = sb + 16384;
    const uint32_t Q2 = sb + 24576;
    const uint32_t ST0 = sb + 32768;

    if (tid == 0) {
        MBARRIER_INIT(MB_Q, 1);
#pragma unroll
        for (int s = 0; s < AT_NSTG; ++s) {
            MBARRIER_INIT(sb + 8 + 8 * s, 1);
            MBARRIER_INIT(sb + 32 + 8 * s, 256);
        }
    }
    {
        const float4* mp = (const float4*)(amask + tokbase);
        float4* ms = (float4*)maskSm;
#pragma unroll
        for (int i = tid; i < 512; i += 256) {
            float4 v = mp[i];
            v.x = (1.f - v.x) * -10000.f;
            v.y = (1.f - v.y) * -10000.f;
            v.z = (1.f - v.z) * -10000.f;
            v.w = (1.f - v.w) * -10000.f;
            ms[i] = v;
        }
    }
    __syncthreads();

    const int q1col = h * 64;
    const int q2col = 1024 + h * 64;
    const int k1col = 2048 + h * 64;
    const int k2col = 3072 + h * 64;
    const int vcol  = 4096 + h * 128;

    if (tid == 0) {
        MBARRIER_EXPECT_TX(MB_Q, 16384);
        tma2d(Q1, &tmT, q1col, tokbase + q0, MB_Q);
        tma2d(Q2, &tmT, q2col, tokbase + q0, MB_Q);
#pragma unroll
        for (int s = 0; s < AT_NSTG; ++s) {
            const uint32_t st = ST0 + s * AT_STAGE_BYTES;
            const uint32_t fb = sb + 8 + 8 * s;
            MBARRIER_EXPECT_TX(fb, AT_STAGE_BYTES);
            const int k0 = tokbase + s * 64;
            tma2d(st,         &tmT, k1col,     k0, fb);
            tma2d(st + 8192,  &tmT, k2col,     k0, fb);
            tma2d(st + 16384, &tmT, vcol,      k0, fb);
            tma2d(st + 24576, &tmT, vcol + 64, k0, fb);
        }
    }

    MBARRIER_WAIT_PARITY(MB_Q, 0);
    uint32_t qh[4][4];
    {
        const uint32_t QT = s_id ? Q2 : Q1;
        const int r = 16 * wq + (lane & 15);
        const uint32_t rb = (uint32_t)r * 128;
        const uint32_t msk = (uint32_t)((r & 7) << 4);
        const uint32_t cbq = (uint32_t)(lane >> 4) * 16;
#pragma unroll
        for (int kk = 0; kk < 4; ++kk)
            ldsm4(qh[kk], QT + rb + ((cbq + kk * 32) ^ msk));
    }

    float o[16][4];
#pragma unroll
    for (int i = 0; i < 16; i++)
#pragma unroll
        for (int j = 0; j < 4; j++) o[i][j] = 0.f;
    float m0 = -1e30f, m1 = -1e30f, l0 = 0.f, l1 = 0.f;

    uint32_t kRB[4], kMask[4];
#pragma unroll
    for (int g = 0; g < 4; ++g) {
        const int r = 16 * g + (lane & 15);
        kRB[g] = (uint32_t)r * 128;
        kMask[g] = (uint32_t)((r & 7) << 4);
    }
    const uint32_t cb = (uint32_t)(lane >> 4) * 16;
    const uint32_t kOff = (uint32_t)s_id * 8192;

    for (int kb = 0; kb < 32; ++kb) {
        const int u = kb / 3;
        const int s = kb - u * 3;
        const uint32_t FULL = sb + 8 + 8 * s;
        const uint32_t EMPTY = sb + 32 + 8 * s;
        const uint32_t ST = ST0 + s * AT_STAGE_BYTES;
        MBARRIER_WAIT_PARITY(FULL, (uint32_t)(u & 1));

        // ---- scores: single-term fp16 MMA (Q * K_s) ----
        float scf[8][4];
#pragma unroll
        for (int t = 0; t < 8; t++)
#pragma unroll
            for (int j = 0; j < 4; j++) scf[t][j] = 0.f;

#pragma unroll
        for (int kk = 0; kk < 4; ++kk) {
            uint32_t kh[4][4];
#pragma unroll
            for (int g = 0; g < 4; ++g) {
                const uint32_t a = cb + kk * 32;
                ldsm4(kh[g], ST + kOff + kRB[g] + (a ^ kMask[g]));
            }
#pragma unroll
            for (int g = 0; g < 4; ++g) {
                mma_fp16(scf[2 * g],     qh[kk], kh[g][0], kh[g][2]);
                mma_fp16(scf[2 * g + 1], qh[kk], kh[g][1], kh[g][3]);
            }
        }

        // ---- mask + dual-row online softmax ----
        const int kbase = kb * 64 + 2 * (lane & 3);
        float nm0 = m0, nm1 = m1;
#pragma unroll
        for (int t = 0; t < 8; ++t) {
            const float mv0 = maskSm[kbase + 8 * t];
            const float mv1 = maskSm[kbase + 8 * t + 1];
            scf[t][0] += mv0; scf[t][1] += mv1;
            scf[t][2] += mv0; scf[t][3] += mv1;
            nm0 = fmaxf(nm0, fmaxf(scf[t][0], scf[t][1]));
            nm1 = fmaxf(nm1, fmaxf(scf[t][2], scf[t][3]));
        }
        nm0 = fmaxf(nm0, __shfl_xor_sync(0xffffffffu, nm0, 1));
        nm0 = fmaxf(nm0, __shfl_xor_sync(0xffffffffu, nm0, 2));
        nm1 = fmaxf(nm1, __shfl_xor_sync(0xffffffffu, nm1, 1));
        nm1 = fmaxf(nm1, __shfl_xor_sync(0xffffffffu, nm1, 2));
        const float a0 = fexp(m0 - nm0), a1 = fexp(m1 - nm1);
        m0 = nm0; m1 = nm1;
#pragma unroll
        for (int nt = 0; nt < 16; ++nt) {
            o[nt][0] *= a0; o[nt][1] *= a0;
            o[nt][2] *= a1; o[nt][3] *= a1;
        }

        uint32_t pha[4][4];
        float rs0 = 0.f, rs1 = 0.f;
#pragma unroll
        for (int t = 0; t < 8; ++t) {
            const float e0 = fexp(scf[t][0] - m0), e1 = fexp(scf[t][1] - m0);
            const float e2 = fexp(scf[t][2] - m1), e3 = fexp(scf[t][3] - m1);
            rs0 += e0 + e1; rs1 += e2 + e3;
            pha[t >> 1][2 * (t & 1)]     = pack2h(e0, e1);
            pha[t >> 1][2 * (t & 1) + 1] = pack2h(e2, e3);
        }
        rs0 += __shfl_xor_sync(0xffffffffu, rs0, 1);
        rs0 += __shfl_xor_sync(0xffffffffu, rs0, 2);
        rs1 += __shfl_xor_sync(0xffffffffu, rs1, 1);
        rs1 += __shfl_xor_sync(0xffffffffu, rs1, 2);
        l0 = l0 * a0 + rs0;
        l1 = l1 * a1 + rs1;

        // ---- PV: single-term fp16 MMA (P * V), V shared between streams ----
#pragma unroll
        for (int kk = 0; kk < 4; ++kk) {
            const int r = 16 * kk + (lane & 15);
            const uint32_t vrb = (uint32_t)r * 128;
            const uint32_t vmsk = (uint32_t)((r & 7) << 4);
#pragma unroll
            for (int g = 0; g < 8; ++g) {
                const uint32_t base = ST + 16384 + ((g >> 2) ? 8192u : 0u);
                const uint32_t a = ((uint32_t)((g & 3) * 32) + cb) ^ vmsk;
                uint32_t vh[4];
                ldsm4t(vh, base + vrb + a);
                mma_fp16(o[2 * g],     pha[kk], vh[0], vh[1]);
                mma_fp16(o[2 * g + 1], pha[kk], vh[2], vh[3]);
            }
        }

        MBARRIER_ARRIVE(EMPTY);

        const int p = kb + AT_NSTG;
        if (tid == 0 && p < 32) {
            const int up = p / 3;
            MBARRIER_WAIT_PARITY_RELAXED(EMPTY, (uint32_t)((up & 1) ^ 1));
            MBARRIER_EXPECT_TX(FULL, AT_STAGE_BYTES);
            const int k0 = tokbase + p * 64;
            tma2d(ST,         &tmT, k1col,     k0, FULL);
            tma2d(ST + 8192,  &tmT, k2col,     k0, FULL);
            tma2d(ST + 16384, &tmT, vcol,      k0, FULL);
            tma2d(ST + 24576, &tmT, vcol + 64, k0, FULL);
        }
    }

    // ---- normalize to smem (per stream), combine o1 - lam*o2 -> fp16 ----
    __syncthreads();
    float* Cb = (float*)(asmem + 32768 + s_id * 32768);
    {
        const float inv0 = 1.f / l0, inv1 = 1.f / l1;
        const int r0 = 16 * wq + (lane >> 2);
        const int cc = 2 * (lane & 3);
#pragma unroll
        for (int nt = 0; nt < 16; ++nt) {
            Cb[r0 * 128 + 8 * nt + cc]           = o[nt][0] * inv0;
            Cb[r0 * 128 + 8 * nt + cc + 1]       = o[nt][1] * inv0;
            Cb[(r0 + 8) * 128 + 8 * nt + cc]     = o[nt][2] * inv1;
            Cb[(r0 + 8) * 128 + 8 * nt + cc + 1] = o[nt][3] * inv1;
        }
    }
    __syncthreads();

    const float lam = *lambda_p;
    const float* C1b = (const float*)(asmem + 32768);
    const float* C2b = (const float*)(asmem + 65536);
    for (int idx = tid; idx < 64 * 32; idx += 256) {
        const int row = idx >> 5;
        const int c4 = (idx & 31) * 4;
        float4 a = *(const float4*)&C1b[row * 128 + c4];
        float4 c = *(const float4*)&C2b[row * 128 + c4];
        uint2 H;
        H.x = pack2h(a.x - lam * c.x, a.y - lam * c.y);
        H.y = pack2h(a.z - lam * c.z, a.w - lam * c.w);
        *(uint2*)(O16 + (size_t)(tokbase + q0 + row) * DMODEL + h * 128 + c4) = H;
    }
}

// ---------------------------------------------------------------------------
// fp32 -> fp16 single (hidden -> A)
// ---------------------------------------------------------------------------
__global__ __launch_bounds__(256)
void tofp16_kernel(const float4* __restrict__ x, uint2* __restrict__ y, int n4)
{
    int i = blockIdx.x * blockDim.x + threadIdx.x;
    if (i >= n4) return;
    float4 v = x[i];
    uint2 H;
    H.x = pack2h(v.x, v.y);
    H.y = pack2h(v.z, v.w);
    y[i] = H;
}

// fp32 W[K][N] -> transposed fp16 hi/lo: hiT[N][K], loT[N][K]
__global__ __launch_bounds__(256)
void splitT16_kernel(const float* __restrict__ W, __half* __restrict__ hiT,
                     __half* __restrict__ loT, int K, int N)
{
    __shared__ float t[32][33];
    const int tx = threadIdx.x, ty = threadIdx.y;
    const int n0 = blockIdx.x * 32, k0 = blockIdx.y * 32;
#pragma unroll
    for (int r = 0; r < 4; ++r)
        t[ty + 8 * r][tx] = W[(size_t)(k0 + ty + 8 * r) * N + n0 + tx];
    __syncthreads();
#pragma unroll
    for (int r = 0; r < 4; ++r) {
        const int nn = ty + 8 * r;
        float v = t[tx][nn];
        __half hh = __float2half_rn(v);
        __half ll = __float2half_rn(v - __half2float(hh));
        const size_t off = (size_t)(n0 + nn) * K + k0 + tx;
        hiT[off] = hh;
        loT[off] = ll;
    }
}

// ---------------------------------------------------------------------------
// Host side
// ---------------------------------------------------------------------------
typedef CUresult (*PFN_tmEncode)(
    CUtensorMap*, CUtensorMapDataType, cuuint32_t, void*,
    const cuuint64_t*, const cuuint64_t*, const cuuint32_t*, const cuuint32_t*,
    CUtensorMapInterleave, CUtensorMapSwizzle, CUtensorMapL2promotion,
    CUtensorMapFloatOOBfill);

static void make_map(PFN_tmEncode fn, CUtensorMap* m, void* ptr,
                     unsigned long long rows, unsigned long long cols,
                     unsigned box0, unsigned box1)
{
    cuuint64_t dims[2]    = {(cuuint64_t)cols, (cuuint64_t)rows};
    cuuint64_t strides[1] = {(cuuint64_t)cols * 2};
    cuuint32_t box[2]     = {box0, box1};
    cuuint32_t es[2]      = {1u, 1u};
    fn(m, CU_TENSOR_MAP_DATA_TYPE_BFLOAT16, 2, ptr, dims, strides, box, es,
       CU_TENSOR_MAP_INTERLEAVE_NONE, CU_TENSOR_MAP_SWIZZLE_128B,
       CU_TENSOR_MAP_L2_PROMOTION_L2_128B, CU_TENSOR_MAP_FLOAT_OOB_FILL_NONE);
}

extern "C" void kernel_launch(void* const* d_in, const int* in_sizes, int n_in,
                              void* d_out, int out_size)
{
    const float* hidden = (const float*)d_in[0];
    const float* amask  = (const float*)d_in[1];
    const float* W_attn = (const float*)d_in[2];
    const float* b_attn = (const float*)d_in[3];
    const float* W_proj = (const float*)d_in[4];
    const float* b_proj = (const float*)d_in[5];
    const float* lam    = (const float*)d_in[6];
    float* out = (float*)d_out;

    void *qkv16, *A16, *WAh, *WAl, *WPh, *WPl, *O16;
    cudaGetSymbolAddress(&qkv16, g_qkv16);
    cudaGetSymbolAddress(&A16, g_A16);
    cudaGetSymbolAddress(&WAh, g_WAh);   cudaGetSymbolAddress(&WAl, g_WAl);
    cudaGetSymbolAddress(&WPh, g_WPh);   cudaGetSymbolAddress(&WPl, g_WPl);
    cudaGetSymbolAddress(&O16, g_O16);

    void* fnp = nullptr;
    cudaDriverEntryPointQueryResult qres;
    cudaGetDriverEntryPointByVersion("cuTensorMapEncodeTiled", &fnp, 12000,
                                     cudaEnableDefault, &qres);
    PFN_tmEncode enc = (PFN_tmEncode)fnp;

    CUtensorMap tA, tWAh, tWAl, tWPh, tWPl, tO, tT;
    make_map(enc, &tA,   A16,  M_TOK,  KDIM, 64, 128);
    make_map(enc, &tWAh, WAh,  N_QKV,  KDIM, 64, 128);
    make_map(enc, &tWAl, WAl,  N_QKV,  KDIM, 64, 128);
    make_map(enc, &tWPh, WPh,  DMODEL, KDIM, 64, 128);
    make_map(enc, &tWPl, WPl,  DMODEL, KDIM, 64, 128);
    make_map(enc, &tO,   O16,  M_TOK,  KDIM, 64, 128);
    make_map(enc, &tT,   qkv16, M_TOK, N_QKV, 64, 64);

    cudaFuncSetAttribute(gemm_fp16x2_kernel<0>,
                         cudaFuncAttributeMaxDynamicSharedMemorySize, GEMM_SMEM);
    cudaFuncSetAttribute(gemm_fp16x2_kernel<1>,
                         cudaFuncAttributeMaxDynamicSharedMemorySize, GEMM_SMEM);
    cudaFuncSetAttribute(diff_attn_fused_kernel,
                         cudaFuncAttributeMaxDynamicSharedMemorySize, AT_SMEM);

    // 1) hidden -> fp16
    {
        int n4 = (M_TOK * KDIM) / 4;
        tofp16_kernel<<<n4 / 256, 256>>>((const float4*)hidden, (uint2*)A16, n4);
    }
    // 2) transpose+split weights (fp16 hi/lo)
    {
        dim3 g(N_QKV / 32, KDIM / 32);
        splitT16_kernel<<<g, dim3(32, 8)>>>(W_attn, (__half*)WAh, (__half*)WAl, KDIM, N_QKV);
    }
    {
        dim3 g(DMODEL / 32, KDIM / 32);
        splitT16_kernel<<<g, dim3(32, 8)>>>(W_proj, (__half*)WPh, (__half*)WPl, KDIM, DMODEL);
    }
    // 3) QKV GEMM: 1-term q/k, 2-term v; heavy v-CTAs scheduled first
    {
        dim3 g(N_QKV / 128, M_TOK / 128);
        gemm_fp16x2_kernel<1><<<g, 256, GEMM_SMEM>>>(tA, tWAh, tWAl, b_attn,
                                                     nullptr, (unsigned short*)qkv16,
                                                     N_QKV, 4096, 32);
    }
    // 4) fused dual-stream differential attention -> fp16 O16
    {
        dim3 g(S_LEN / 64, B_SZ * NHEAD);
        diff_attn_fused_kernel<<<g, 256, AT_SMEM>>>(tT, amask, lam,
                                                    (unsigned short*)O16);
    }
    // 5) output projection (fp16 x2, fp32 out)
    {
        dim3 g(DMODEL / 128, M_TOK / 128);
        gemm_fp16x2_kernel<0><<<g, 256, GEMM_SMEM>>>(tO, tWPh, tWPl, b_proj,
                                                     out, nullptr, DMODEL, 0, 0);
    }
}

// round 15
// speedup vs baseline: 1.9429x; 1.0100x over previous
#include <cuda_runtime.h>
#include <cuda_fp16.h>
#include <cuda.h>
#include <cstdint>

// Problem dims (fixed by setup_inputs)
#define B_SZ   2
#define S_LEN  2048
#define DMODEL 2048
#define NHEAD  16
#define M_TOK  (B_SZ * S_LEN)     // 4096
#define N_QKV  (3 * DMODEL)       // 6144
#define KDIM   DMODEL             // 2048
#define QSCALE 0.0883883476483184f

// ---------------- scratch (static device globals: allocation-free) ----------
__device__ unsigned short g_qkv16[(size_t)M_TOK * N_QKV];
__device__ unsigned short g_A16[(size_t)M_TOK * KDIM];
__device__ unsigned short g_WAh[(size_t)N_QKV * KDIM];
__device__ unsigned short g_WAl[(size_t)N_QKV * KDIM];
__device__ unsigned short g_WPh[(size_t)DMODEL * KDIM];
__device__ unsigned short g_WPl[(size_t)DMODEL * KDIM];
__device__ unsigned short g_O16[(size_t)M_TOK * KDIM];

// ---------------------------------------------------------------------------
// PTX helpers (base sm_90 only)
// ---------------------------------------------------------------------------
__device__ __forceinline__ uint32_t smem_u32(const void* p) {
    uint32_t a;
    asm("{ .reg .u64 t; cvta.to.shared.u64 t, %1; cvt.u32.u64 %0, t; }" : "=r"(a) : "l"(p));
    return a;
}

#define MBARRIER_INIT(addr, cnt) \
    asm volatile("mbarrier.init.shared.b64 [%0], %1;" :: "r"((uint32_t)(addr)), "r"((uint32_t)(cnt)) : "memory")

#define MBARRIER_ARRIVE(addr) \
    asm volatile("mbarrier.arrive.shared.b64 _, [%0];" :: "r"((uint32_t)(addr)) : "memory")

#define MBARRIER_EXPECT_TX(addr, bytes) \
    asm volatile("mbarrier.arrive.expect_tx.shared.b64 _, [%0], %1;" :: "r"((uint32_t)(addr)), "r"((uint32_t)(bytes)) : "memory")

#define MBARRIER_WAIT_PARITY(mbar_smem_addr, phase_parity) do { \
    uint32_t _mbar = (uint32_t)(mbar_smem_addr); \
    uint32_t _parity = (uint32_t)(phase_parity); \
    uint32_t _done; \
    asm volatile( \
        "{\n\t.reg .pred p;\n\t" \
        "mbarrier.try_wait.parity.acquire.cta.shared::cta.b64 p, [%1], %2;\n\t" \
        "selp.b32 %0, 1, 0, p;\n\t}" \
        : "=r"(_done) : "r"(_mbar), "r"(_parity) : "memory"); \
    if (!_done) { \
        asm volatile( \
            "{\n\t.reg .pred P1;\n\t" \
            "WAIT_LOOP_%=:\n\t" \
            "mbarrier.try_wait.parity.acquire.cta.shared::cta.b64 P1, [%0], %1, 0x989680;\n\t" \
            "@P1 bra.uni WAIT_DONE_%=;\n\t" \
            "bra.uni WAIT_LOOP_%=;\n\t" \
            "WAIT_DONE_%=:\n\t}" \
            :: "r"(_mbar), "r"(_parity) : "memory"); \
    } \
} while(0)

#define MBARRIER_WAIT_PARITY_RELAXED(mbar_smem_addr, phase_parity) do { \
    uint32_t _mbar = (uint32_t)(mbar_smem_addr); \
    uint32_t _parity = (uint32_t)(phase_parity); \
    uint32_t _done; \
    asm volatile( \
        "{\n\t.reg .pred p;\n\t" \
        "mbarrier.try_wait.parity.relaxed.cta.shared::cta.b64 p, [%1], %2, 0x989680;\n\t" \
        "selp.b32 %0, 1, 0, p;\n\t}" \
        : "=r"(_done) : "r"(_mbar), "r"(_parity) : "memory"); \
    if (!_done) { \
        asm volatile( \
            "{\n\t.reg .pred P1;\n\t" \
            "WAIT_LOOP_%=:\n\t" \
            "mbarrier.try_wait.parity.relaxed.cta.shared::cta.b64 P1, [%0], %1, 0x989680;\n\t" \
            "@P1 bra.uni WAIT_DONE_%=;\n\t" \
            "bra.uni WAIT_LOOP_%=;\n\t" \
            "WAIT_DONE_%=:\n\t}" \
            :: "r"(_mbar), "r"(_parity) : "memory"); \
    } \
} while(0)

__device__ __forceinline__ void tma2d(uint32_t dst, const void* map, int x, int y, uint32_t mbar) {
    asm volatile(
        "cp.async.bulk.tensor.2d.shared::cta.global.tile.mbarrier::complete_tx::bytes "
        "[%0], [%1, {%2, %3}], [%4];"
        :: "r"(dst), "l"(map), "r"(x), "r"(y), "r"(mbar) : "memory");
}

__device__ __forceinline__ void ldsm4(uint32_t* r, uint32_t addr) {
    asm volatile("ldmatrix.sync.aligned.m8n8.x4.shared.b16 {%0,%1,%2,%3}, [%4];"
                 : "=r"(r[0]), "=r"(r[1]), "=r"(r[2]), "=r"(r[3]) : "r"(addr));
}
__device__ __forceinline__ void ldsm4t(uint32_t* r, uint32_t addr) {
    asm volatile("ldmatrix.sync.aligned.m8n8.x4.trans.shared.b16 {%0,%1,%2,%3}, [%4];"
                 : "=r"(r[0]), "=r"(r[1]), "=r"(r[2]), "=r"(r[3]) : "r"(addr));
}

__device__ __forceinline__ void mma_fp16(float* d, const uint32_t* a, uint32_t b0, uint32_t b1) {
    asm volatile(
        "mma.sync.aligned.m16n8k16.row.col.f32.f16.f16.f32 "
        "{%0,%1,%2,%3}, {%4,%5,%6,%7}, {%8,%9}, {%0,%1,%2,%3};"
        : "+f"(d[0]), "+f"(d[1]), "+f"(d[2]), "+f"(d[3])
        : "r"(a[0]), "r"(a[1]), "r"(a[2]), "r"(a[3]), "r"(b0), "r"(b1));
}

__device__ __forceinline__ uint32_t pack2h(float a, float b) {
    __half2 t = __floats2half2_rn(a, b);
    return *reinterpret_cast<uint32_t*>(&t);
}

// Fast exp on the FMA pipe. Valid for x <= 0 (clamped below -80).
__device__ __forceinline__ float fexp(float x) {
    x = fmaxf(x, -80.0f);
    float t = x * 1.4426950408889634f;
    float z = t + 12582912.0f;
    int n = __float_as_int(z) - 0x4b400000;
    float f = t - (z - 12582912.0f);
    float u = f * 0.6931471805599453f;
    float r = 1.3888889e-3f;
    r = fmaf(r, u, 8.3333338e-3f);
    r = fmaf(r, u, 4.1666668e-2f);
    r = fmaf(r, u, 1.6666667e-1f);
    r = fmaf(r, u, 0.5f);
    r = fmaf(r, u, 1.0f);
    r = fmaf(r, u, 1.0f);
    return r * __int_as_float((n + 127) << 23);
}

// ---------------------------------------------------------------------------
// fp16 mixed-precision GEMM (unchanged from R14)
// ---------------------------------------------------------------------------
#define GCHUNKS     32
#define GTILE_BYTES 16384
#define GSTAGE_BYTES (3 * GTILE_BYTES)
#define GSM_DATA    1024
#define GEMM_SMEM   (GSM_DATA + 3 * GSTAGE_BYTES)

template <int MODE>
__global__ __launch_bounds__(256, 1)
void gemm_fp16x2_kernel(const __grid_constant__ CUtensorMap tmA,
                        const __grid_constant__ CUtensorMap tmBh,
                        const __grid_constant__ CUtensorMap tmBl,
                        const float* __restrict__ bias,
                        float* __restrict__ C,
                        unsigned short* __restrict__ Ch,
                        int N, int lo_start, int col_shift)
{
    extern __shared__ __align__(1024) char gsm[];
    const uint32_t sb = smem_u32(gsm);
    const int tid = threadIdx.x;
    const int lane = tid & 31;
    const int wid = tid >> 5;
    const int row0 = blockIdx.y * 128;
    const int cidx = ((int)blockIdx.x + col_shift) % (int)gridDim.x;
    const int col0 = cidx * 128;
    const int wm = (wid & 3) * 32;
    const int wn = (wid >> 2) * 64;
    const bool use_lo = (col0 >= lo_start);
    const uint32_t stage_tx = use_lo ? (uint32_t)GSTAGE_BYTES : (uint32_t)(2 * GTILE_BYTES);

    if (tid == 0) {
#pragma unroll
        for (int s = 0; s < 3; ++s) {
            MBARRIER_INIT(sb + 8 * s, 1);
            MBARRIER_INIT(sb + 24 + 8 * s, 256);
        }
    }
    __syncthreads();

    if (tid == 0) {
#pragma unroll
        for (int p = 0; p < 3; ++p) {
            const uint32_t st = sb + GSM_DATA + p * GSTAGE_BYTES;
            MBARRIER_EXPECT_TX(sb + 8 * p, stage_tx);
            const int k0 = p * 64;
            tma2d(st,               &tmA,  k0, row0, sb + 8 * p);
            tma2d(st + GTILE_BYTES, &tmBh, k0, col0, sb + 8 * p);
            if (use_lo)
                tma2d(st + 2 * GTILE_BYTES, &tmBl, k0, col0, sb + 8 * p);
        }
    }

    float acc[2][8][4];
#pragma unroll
    for (int i = 0; i < 2; i++)
#pragma unroll
        for (int j = 0; j < 8; j++)
#pragma unroll
            for (int k = 0; k < 4; k++) acc[i][j][k] = 0.f;

    const uint32_t cbase = (lane >> 4) * 16;
    uint32_t aRB[2], aMask[2], bRB[4], bMask[4];
#pragma unroll
    for (int mt = 0; mt < 2; ++mt) {
        const int r = wm + mt * 16 + (lane & 15);
        aRB[mt] = (uint32_t)r * 128;
        aMask[mt] = (uint32_t)((r & 7) << 4);
    }
#pragma unroll
    for (int j = 0; j < 4; ++j) {
        const int r = wn + j * 16 + (lane & 15);
        bRB[j] = (uint32_t)r * 128;
        bMask[j] = (uint32_t)((r & 7) << 4);
    }

    for (int c = 0; c < GCHUNKS; ++c) {
        const int u = c / 3;
        const int s = c - u * 3;
        MBARRIER_WAIT_PARITY(sb + 8 * s, (uint32_t)(u & 1));

        const uint32_t stA  = sb + GSM_DATA + s * GSTAGE_BYTES;
        const uint32_t stBh = stA + GTILE_BYTES;
        const uint32_t stBl = stA + 2 * GTILE_BYTES;

#pragma unroll
        for (int kk = 0; kk < 4; ++kk) {
            const uint32_t kb = cbase + kk * 32;
            uint32_t a[2][4], bh[4][4];
#pragma unroll
            for (int mt = 0; mt < 2; ++mt)
                ldsm4(a[mt], stA + aRB[mt] + (kb ^ aMask[mt]));
#pragma unroll
            for (int j = 0; j < 4; ++j)
                ldsm4(bh[j], stBh + bRB[j] + (kb ^ bMask[j]));
#pragma unroll
            for (int mt = 0; mt < 2; ++mt)
#pragma unroll
                for (int j = 0; j < 4; ++j) {
                    mma_fp16(acc[mt][2 * j],     a[mt], bh[j][0], bh[j][2]);
                    mma_fp16(acc[mt][2 * j + 1], a[mt], bh[j][1], bh[j][3]);
                }
            if (use_lo) {
                uint32_t bl[4][4];
#pragma unroll
                for (int j = 0; j < 4; ++j)
                    ldsm4(bl[j], stBl + bRB[j] + (kb ^ bMask[j]));
#pragma unroll
                for (int mt = 0; mt < 2; ++mt)
#pragma unroll
                    for (int j = 0; j < 4; ++j) {
                        mma_fp16(acc[mt][2 * j],     a[mt], bl[j][0], bl[j][2]);
                        mma_fp16(acc[mt][2 * j + 1], a[mt], bl[j][1], bl[j][3]);
                    }
            }
        }

        MBARRIER_ARRIVE(sb + 24 + 8 * s);

        const int p = c + 3;
        if (tid == 0 && p < GCHUNKS) {
            const int up = p / 3;
            MBARRIER_WAIT_PARITY_RELAXED(sb + 24 + 8 * s, (uint32_t)((up & 1) ^ 1));
            const uint32_t st = sb + GSM_DATA + s * GSTAGE_BYTES;
            MBARRIER_EXPECT_TX(sb + 8 * s, stage_tx);
            const int k0 = p * 64;
            tma2d(st,               &tmA,  k0, row0, sb + 8 * s);
            tma2d(st + GTILE_BYTES, &tmBh, k0, col0, sb + 8 * s);
            if (use_lo)
                tma2d(st + 2 * GTILE_BYTES, &tmBl, k0, col0, sb + 8 * s);
        }
    }

    // Epilogue
    const int rr = lane >> 2;
    const int cc = (lane & 3) * 2;
#pragma unroll
    for (int mt = 0; mt < 2; ++mt) {
        const int mrow = row0 + wm + mt * 16 + rr;
#pragma unroll
        for (int nt = 0; nt < 8; ++nt) {
            const int n = col0 + wn + nt * 8 + cc;
            const float2 bb = *(const float2*)(bias + n);
            float v00 = acc[mt][nt][0] + bb.x, v01 = acc[mt][nt][1] + bb.y;
            float v10 = acc[mt][nt][2] + bb.x, v11 = acc[mt][nt][3] + bb.y;
            if (MODE == 0) {
                *(float2*)(C + (size_t)mrow * N + n) = make_float2(v00, v01);
                *(float2*)(C + (size_t)(mrow + 8) * N + n) = make_float2(v10, v11);
            } else {
                const float sc = (n < 2048) ? QSCALE : 1.0f;
                *(uint32_t*)(Ch + (size_t)mrow * N + n)       = pack2h(v00 * sc, v01 * sc);
                *(uint32_t*)(Ch + (size_t)(mrow + 8) * N + n) = pack2h(v10 * sc, v11 * sc);
            }
        }
    }
}

// ---------------------------------------------------------------------------
// Fused dual-stream differential flash attention (unchanged from R14).
// ---------------------------------------------------------------------------
#define AT_NSTG 3
#define AT_STAGE_BYTES 32768
#define AT_SMEM (32768 + AT_NSTG * AT_STAGE_BYTES)

__global__ __launch_bounds__(256, 1)
void diff_attn_fused_kernel(const __grid_constant__ CUtensorMap tmT,
                            const float* __restrict__ amask,
                            const float* __restrict__ lambda_p,
                            unsigned short* __restrict__ O16)
{
    extern __shared__ __align__(1024) char asmem[];
    const uint32_t sb = smem_u32(asmem);
    const int tid = threadIdx.x, lane = tid & 31, w = tid >> 5;
    const int s_id = w >> 2;
    const int wq = w & 3;
    const int qb = blockIdx.x, bh = blockIdx.y;
    const int b = bh >> 4, h = bh & 15;
    const int q0 = qb * 64;
    const int tokbase = b * S_LEN;

    const uint32_t MB_Q = sb;
    float* maskSm = (float*)(asmem + 64);
    const uint32_t Q1 = sb + 16384;
    const uint32_t Q2 = sb + 24576;
    const uint32_t ST0 = sb + 32768;

    if (tid == 0) {
        MBARRIER_INIT(MB_Q, 1);
#pragma unroll
        for (int s = 0; s < AT_NSTG; ++s) {
            MBARRIER_INIT(sb + 8 + 8 * s, 1);
            MBARRIER_INIT(sb + 32 + 8 * s, 256);
        }
    }
    {
        const float4* mp = (const float4*)(amask + tokbase);
        float4* ms = (float4*)maskSm;
#pragma unroll
        for (int i = tid; i < 512; i += 256) {
            float4 v = mp[i];
            v.x = (1.f - v.x) * -10000.f;
            v.y = (1.f - v.y) * -10000.f;
            v.z = (1.f - v.z) * -10000.f;
            v.w = (1.f - v.w) * -10000.f;
            ms[i] = v;
        }
    }
    __syncthreads();

    const int q1col = h * 64;
    const int q2col = 1024 + h * 64;
    const int k1col = 2048 + h * 64;
    const int k2col = 3072 + h * 64;
    const int vcol  = 4096 + h * 128;

    if (tid == 0) {
        MBARRIER_EXPECT_TX(MB_Q, 16384);
        tma2d(Q1, &tmT, q1col, tokbase + q0, MB_Q);
        tma2d(Q2, &tmT, q2col, tokbase + q0, MB_Q);
#pragma unroll
        for (int s = 0; s < AT_NSTG; ++s) {
            const uint32_t st = ST0 + s * AT_STAGE_BYTES;
            const uint32_t fb = sb + 8 + 8 * s;
            MBARRIER_EXPECT_TX(fb, AT_STAGE_BYTES);
            const int k0 = tokbase + s * 64;
            tma2d(st,         &tmT, k1col,     k0, fb);
            tma2d(st + 8192,  &tmT, k2col,     k0, fb);
            tma2d(st + 16384, &tmT, vcol,      k0, fb);
            tma2d(st + 24576, &tmT, vcol + 64, k0, fb);
        }
    }

    MBARRIER_WAIT_PARITY(MB_Q, 0);
    uint32_t qh[4][4];
    {
        const uint32_t QT = s_id ? Q2 : Q1;
        const int r = 16 * wq + (lane & 15);
        const uint32_t rb = (uint32_t)r * 128;
        const uint32_t msk = (uint32_t)((r & 7) << 4);
        const uint32_t cbq = (uint32_t)(lane >> 4) * 16;
#pragma unroll
        for (int kk = 0; kk < 4; ++kk)
            ldsm4(qh[kk], QT + rb + ((cbq + kk * 32) ^ msk));
    }

    float o[16][4];
#pragma unroll
    for (int i = 0; i < 16; i++)
#pragma unroll
        for (int j = 0; j < 4; j++) o[i][j] = 0.f;
    float m0 = -1e30f, m1 = -1e30f, l0 = 0.f, l1 = 0.f;

    uint32_t kRB[4], kMask[4];
#pragma unroll
    for (int g = 0; g < 4; ++g) {
        const int r = 16 * g + (lane & 15);
        kRB[g] = (uint32_t)r * 128;
        kMask[g] = (uint32_t)((r & 7) << 4);
    }
    const uint32_t cb = (uint32_t)(lane >> 4) * 16;
    const uint32_t kOff = (uint32_t)s_id * 8192;

    for (int kb = 0; kb < 32; ++kb) {
        const int u = kb / 3;
        const int s = kb - u * 3;
        const uint32_t FULL = sb + 8 + 8 * s;
        const uint32_t EMPTY = sb + 32 + 8 * s;
        const uint32_t ST = ST0 + s * AT_STAGE_BYTES;
        MBARRIER_WAIT_PARITY(FULL, (uint32_t)(u & 1));

        float scf[8][4];
#pragma unroll
        for (int t = 0; t < 8; t++)
#pragma unroll
            for (int j = 0; j < 4; j++) scf[t][j] = 0.f;

#pragma unroll
        for (int kk = 0; kk < 4; ++kk) {
            uint32_t kh[4][4];
#pragma unroll
            for (int g = 0; g < 4; ++g) {
                const uint32_t a = cb + kk * 32;
                ldsm4(kh[g], ST + kOff + kRB[g] + (a ^ kMask[g]));
            }
#pragma unroll
            for (int g = 0; g < 4; ++g) {
                mma_fp16(scf[2 * g],     qh[kk], kh[g][0], kh[g][2]);
                mma_fp16(scf[2 * g + 1], qh[kk], kh[g][1], kh[g][3]);
            }
        }

        const int kbase = kb * 64 + 2 * (lane & 3);
        float nm0 = m0, nm1 = m1;
#pragma unroll
        for (int t = 0; t < 8; ++t) {
            const float mv0 = maskSm[kbase + 8 * t];
            const float mv1 = maskSm[kbase + 8 * t + 1];
            scf[t][0] += mv0; scf[t][1] += mv1;
            scf[t][2] += mv0; scf[t][3] += mv1;
            nm0 = fmaxf(nm0, fmaxf(scf[t][0], scf[t][1]));
            nm1 = fmaxf(nm1, fmaxf(scf[t][2], scf[t][3]));
        }
        nm0 = fmaxf(nm0, __shfl_xor_sync(0xffffffffu, nm0, 1));
        nm0 = fmaxf(nm0, __shfl_xor_sync(0xffffffffu, nm0, 2));
        nm1 = fmaxf(nm1, __shfl_xor_sync(0xffffffffu, nm1, 1));
        nm1 = fmaxf(nm1, __shfl_xor_sync(0xffffffffu, nm1, 2));
        const float a0 = fexp(m0 - nm0), a1 = fexp(m1 - nm1);
        m0 = nm0; m1 = nm1;
#pragma unroll
        for (int nt = 0; nt < 16; ++nt) {
            o[nt][0] *= a0; o[nt][1] *= a0;
            o[nt][2] *= a1; o[nt][3] *= a1;
        }

        uint32_t pha[4][4];
        float rs0 = 0.f, rs1 = 0.f;
#pragma unroll
        for (int t = 0; t < 8; ++t) {
            const float e0 = fexp(scf[t][0] - m0), e1 = fexp(scf[t][1] - m0);
            const float e2 = fexp(scf[t][2] - m1), e3 = fexp(scf[t][3] - m1);
            rs0 += e0 + e1; rs1 += e2 + e3;
            pha[t >> 1][2 * (t & 1)]     = pack2h(e0, e1);
            pha[t >> 1][2 * (t & 1) + 1] = pack2h(e2, e3);
        }
        rs0 += __shfl_xor_sync(0xffffffffu, rs0, 1);
        rs0 += __shfl_xor_sync(0xffffffffu, rs0, 2);
        rs1 += __shfl_xor_sync(0xffffffffu, rs1, 1);
        rs1 += __shfl_xor_sync(0xffffffffu, rs1, 2);
        l0 = l0 * a0 + rs0;
        l1 = l1 * a1 + rs1;

#pragma unroll
        for (int kk = 0; kk < 4; ++kk) {
            const int r = 16 * kk + (lane & 15);
            const uint32_t vrb = (uint32_t)r * 128;
            const uint32_t vmsk = (uint32_t)((r & 7) << 4);
#pragma unroll
            for (int g = 0; g < 8; ++g) {
                const uint32_t base = ST + 16384 + ((g >> 2) ? 8192u : 0u);
                const uint32_t a = ((uint32_t)((g & 3) * 32) + cb) ^ vmsk;
                uint32_t vh[4];
                ldsm4t(vh, base + vrb + a);
                mma_fp16(o[2 * g],     pha[kk], vh[0], vh[1]);
                mma_fp16(o[2 * g + 1], pha[kk], vh[2], vh[3]);
            }
        }

        MBARRIER_ARRIVE(EMPTY);

        const int p = kb + AT_NSTG;
        if (tid == 0 && p < 32) {
            const int up = p / 3;
            MBARRIER_WAIT_PARITY_RELAXED(EMPTY, (uint32_t)((up & 1) ^ 1));
            MBARRIER_EXPECT_TX(FULL, AT_STAGE_BYTES);
            const int k0 = tokbase + p * 64;
            tma2d(ST,         &tmT, k1col,     k0, FULL);
            tma2d(ST + 8192,  &tmT, k2col,     k0, FULL);
            tma2d(ST + 16384, &tmT, vcol,      k0, FULL);
            tma2d(ST + 24576, &tmT, vcol + 64, k0, FULL);
        }
    }

    __syncthreads();
    float* Cb = (float*)(asmem + 32768 + s_id * 32768);
    {
        const float inv0 = 1.f / l0, inv1 = 1.f / l1;
        const int r0 = 16 * wq + (lane >> 2);
        const int cc = 2 * (lane & 3);
#pragma unroll
        for (int nt = 0; nt < 16; ++nt) {
            Cb[r0 * 128 + 8 * nt + cc]           = o[nt][0] * inv0;
            Cb[r0 * 128 + 8 * nt + cc + 1]       = o[nt][1] * inv0;
            Cb[(r0 + 8) * 128 + 8 * nt + cc]     = o[nt][2] * inv1;
            Cb[(r0 + 8) * 128 + 8 * nt + cc + 1] = o[nt][3] * inv1;
        }
    }
    __syncthreads();

    const float lam = *lambda_p;
    const float* C1b = (const float*)(asmem + 32768);
    const float* C2b = (const float*)(asmem + 65536);
    for (int idx = tid; idx < 64 * 32; idx += 256) {
        const int row = idx >> 5;
        const int c4 = (idx & 31) * 4;
        float4 a = *(const float4*)&C1b[row * 128 + c4];
        float4 c = *(const float4*)&C2b[row * 128 + c4];
        uint2 H;
        H.x = pack2h(a.x - lam * c.x, a.y - lam * c.y);
        H.y = pack2h(a.z - lam * c.z, a.w - lam * c.w);
        *(uint2*)(O16 + (size_t)(tokbase + q0 + row) * DMODEL + h * 128 + c4) = H;
    }
}

// ---------------------------------------------------------------------------
// Merged preprocessing: one launch covers
//   task A: hidden fp32 -> fp16 (8192 blocks)
//   task B: W_attn split+transpose (12288 blocks; lo skipped for q/k cols)
//   task C: W_proj split+transpose (4096 blocks)
// ---------------------------------------------------------------------------
#define PREP_A_BLOCKS 8192
#define PREP_B_BLOCKS 12288    // (6144/32) * (2048/32)
#define PREP_C_BLOCKS 4096     // (2048/32) * (2048/32)
#define PREP_BLOCKS (PREP_A_BLOCKS + PREP_B_BLOCKS + PREP_C_BLOCKS)

__global__ __launch_bounds__(256)
void prep_kernel(const float4* __restrict__ hidden,
                 const float* __restrict__ W_attn,
                 const float* __restrict__ W_proj,
                 uint2* __restrict__ A16,
                 __half* __restrict__ WAh, __half* __restrict__ WAl,
                 __half* __restrict__ WPh, __half* __restrict__ WPl)
{
    __shared__ float t[32][33];
    const int bid = blockIdx.x;
    const int tid = threadIdx.x;

    if (bid < PREP_A_BLOCKS) {
        // task A: tofp16 (2M float4 elements)
        const int i = bid * 256 + tid;
        float4 v = hidden[i];
        uint2 H;
        H.x = pack2h(v.x, v.y);
        H.y = pack2h(v.z, v.w);
        A16[i] = H;
        return;
    }

    const int tx = tid & 31, ty = tid >> 5;
    if (bid < PREP_A_BLOCKS + PREP_B_BLOCKS) {
        // task B: W_attn [K=2048][N=6144] -> WAh/WAl [N][K]
        const int local = bid - PREP_A_BLOCKS;
        const int n0 = (local % 192) * 32;
        const int k0 = (local / 192) * 32;
#pragma unroll
        for (int r = 0; r < 4; ++r)
            t[ty + 8 * r][tx] = W_attn[(size_t)(k0 + ty + 8 * r) * N_QKV + n0 + tx];
        __syncthreads();
        const bool write_lo = (n0 >= 4096);   // q/k cols never read lo
#pragma unroll
        for (int r = 0; r < 4; ++r) {
            const int nn = ty + 8 * r;
            float v = t[tx][nn];
            __half hh = __float2half_rn(v);
            const size_t off = (size_t)(n0 + nn) * KDIM + k0 + tx;
            WAh[off] = hh;
            if (write_lo)
                WAl[off] = __float2half_rn(v - __half2float(hh));
        }
        return;
    }

    // task C: W_proj [K=2048][N=2048] -> WPh/WPl [N][K]
    const int local = bid - PREP_A_BLOCKS - PREP_B_BLOCKS;
    const int n0 = (local % 64) * 32;
    const int k0 = (local / 64) * 32;
#pragma unroll
    for (int r = 0; r < 4; ++r)
        t[ty + 8 * r][tx] = W_proj[(size_t)(k0 + ty + 8 * r) * DMODEL + n0 + tx];
    __syncthreads();
#pragma unroll
    for (int r = 0; r < 4; ++r) {
        const int nn = ty + 8 * r;
        float v = t[tx][nn];
        __half hh = __float2half_rn(v);
        const size_t off = (size_t)(n0 + nn) * KDIM + k0 + tx;
        WPh[off] = hh;
        WPl[off] = __float2half_rn(v - __half2float(hh));
    }
}

// ---------------------------------------------------------------------------
// Host side
// ---------------------------------------------------------------------------
typedef CUresult (*PFN_tmEncode)(
    CUtensorMap*, CUtensorMapDataType, cuuint32_t, void*,
    const cuuint64_t*, const cuuint64_t*, const cuuint32_t*, const cuuint32_t*,
    CUtensorMapInterleave, CUtensorMapSwizzle, CUtensorMapL2promotion,
    CUtensorMapFloatOOBfill);

static void make_map(PFN_tmEncode fn, CUtensorMap* m, void* ptr,
                     unsigned long long rows, unsigned long long cols,
                     unsigned box0, unsigned box1)
{
    cuuint64_t dims[2]    = {(cuuint64_t)cols, (cuuint64_t)rows};
    cuuint64_t strides[1] = {(cuuint64_t)cols * 2};
    cuuint32_t box[2]     = {box0, box1};
    cuuint32_t es[2]      = {1u, 1u};
    fn(m, CU_TENSOR_MAP_DATA_TYPE_BFLOAT16, 2, ptr, dims, strides, box, es,
       CU_TENSOR_MAP_INTERLEAVE_NONE, CU_TENSOR_MAP_SWIZZLE_128B,
       CU_TENSOR_MAP_L2_PROMOTION_L2_128B, CU_TENSOR_MAP_FLOAT_OOB_FILL_NONE);
}

extern "C" void kernel_launch(void* const* d_in, const int* in_sizes, int n_in,
                              void* d_out, int out_size)
{
    const float* hidden = (const float*)d_in[0];
    const float* amask  = (const float*)d_in[1];
    const float* W_attn = (const float*)d_in[2];
    const float* b_attn = (const float*)d_in[3];
    const float* W_proj = (const float*)d_in[4];
    const float* b_proj = (const float*)d_in[5];
    const float* lam    = (const float*)d_in[6];
    float* out = (float*)d_out;

    void *qkv16, *A16, *WAh, *WAl, *WPh, *WPl, *O16;
    cudaGetSymbolAddress(&qkv16, g_qkv16);
    cudaGetSymbolAddress(&A16, g_A16);
    cudaGetSymbolAddress(&WAh, g_WAh);   cudaGetSymbolAddress(&WAl, g_WAl);
    cudaGetSymbolAddress(&WPh, g_WPh);   cudaGetSymbolAddress(&WPl, g_WPl);
    cudaGetSymbolAddress(&O16, g_O16);

    void* fnp = nullptr;
    cudaDriverEntryPointQueryResult qres;
    cudaGetDriverEntryPointByVersion("cuTensorMapEncodeTiled", &fnp, 12000,
                                     cudaEnableDefault, &qres);
    PFN_tmEncode enc = (PFN_tmEncode)fnp;

    CUtensorMap tA, tWAh, tWAl, tWPh, tWPl, tO, tT;
    make_map(enc, &tA,   A16,  M_TOK,  KDIM, 64, 128);
    make_map(enc, &tWAh, WAh,  N_QKV,  KDIM, 64, 128);
    make_map(enc, &tWAl, WAl,  N_QKV,  KDIM, 64, 128);
    make_map(enc, &tWPh, WPh,  DMODEL, KDIM, 64, 128);
    make_map(enc, &tWPl, WPl,  DMODEL, KDIM, 64, 128);
    make_map(enc, &tO,   O16,  M_TOK,  KDIM, 64, 128);
    make_map(enc, &tT,   qkv16, M_TOK, N_QKV, 64, 64);

    cudaFuncSetAttribute(gemm_fp16x2_kernel<0>,
                         cudaFuncAttributeMaxDynamicSharedMemorySize, GEMM_SMEM);
    cudaFuncSetAttribute(gemm_fp16x2_kernel<1>,
                         cudaFuncAttributeMaxDynamicSharedMemorySize, GEMM_SMEM);
    cudaFuncSetAttribute(diff_attn_fused_kernel,
                         cudaFuncAttributeMaxDynamicSharedMemorySize, AT_SMEM);

    // 1) merged preprocessing (single launch)
    prep_kernel<<<PREP_BLOCKS, 256>>>((const float4*)hidden, W_attn, W_proj,
                                      (uint2*)A16,
                                      (__half*)WAh, (__half*)WAl,
                                      (__half*)WPh, (__half*)WPl);
    // 2) QKV GEMM: 1-term q/k, 2-term v; heavy v-CTAs first
    {
        dim3 g(N_QKV / 128, M_TOK / 128);
        gemm_fp16x2_kernel<1><<<g, 256, GEMM_SMEM>>>(tA, tWAh, tWAl, b_attn,
                                                     nullptr, (unsigned short*)qkv16,
                                                     N_QKV, 4096, 32);
    }
    // 3) fused dual-stream differential attention -> fp16 O16
    {
        dim3 g(S_LEN / 64, B_SZ * NHEAD);
        diff_attn_fused_kernel<<<g, 256, AT_SMEM>>>(tT, amask, lam,
                                                    (unsigned short*)O16);
    }
    // 4) output projection (fp16 x2, fp32 out)
    {
        dim3 g(DMODEL / 128, M_TOK / 128);
        gemm_fp16x2_kernel<0><<<g, 256, GEMM_SMEM>>>(tO, tWPh, tWPl, b_proj,
                                                     out, nullptr, DMODEL, 0, 0);
    }
}

// round 16
// speedup vs baseline: 2.0621x; 1.0614x over previous
#include <cuda_runtime.h>
#include <cuda_fp16.h>
#include <cuda.h>
#include <cstdint>

// Problem dims (fixed by setup_inputs)
#define B_SZ   2
#define S_LEN  2048
#define DMODEL 2048
#define NHEAD  16
#define M_TOK  (B_SZ * S_LEN)     // 4096
#define N_QKV  (3 * DMODEL)       // 6144
#define KDIM   DMODEL             // 2048
#define QSCALE 0.0883883476483184f

// ---------------- scratch (static device globals: allocation-free) ----------
__device__ unsigned short g_qkv16[(size_t)M_TOK * N_QKV];
__device__ unsigned short g_A16[(size_t)M_TOK * KDIM];
__device__ unsigned short g_WAh[(size_t)N_QKV * KDIM];
__device__ unsigned short g_WAl[(size_t)N_QKV * KDIM];
__device__ unsigned short g_WPh[(size_t)DMODEL * KDIM];
__device__ unsigned short g_WPl[(size_t)DMODEL * KDIM];
__device__ unsigned short g_O16[(size_t)M_TOK * KDIM];

// ---------------------------------------------------------------------------
// PTX helpers (base sm_90 only)
// ---------------------------------------------------------------------------
__device__ __forceinline__ uint32_t smem_u32(const void* p) {
    uint32_t a;
    asm("{ .reg .u64 t; cvta.to.shared.u64 t, %1; cvt.u32.u64 %0, t; }" : "=r"(a) : "l"(p));
    return a;
}

#define MBARRIER_INIT(addr, cnt) \
    asm volatile("mbarrier.init.shared.b64 [%0], %1;" :: "r"((uint32_t)(addr)), "r"((uint32_t)(cnt)) : "memory")

#define MBARRIER_ARRIVE(addr) \
    asm volatile("mbarrier.arrive.shared.b64 _, [%0];" :: "r"((uint32_t)(addr)) : "memory")

#define MBARRIER_EXPECT_TX(addr, bytes) \
    asm volatile("mbarrier.arrive.expect_tx.shared.b64 _, [%0], %1;" :: "r"((uint32_t)(addr)), "r"((uint32_t)(bytes)) : "memory")

#define MBARRIER_WAIT_PARITY(mbar_smem_addr, phase_parity) do { \
    uint32_t _mbar = (uint32_t)(mbar_smem_addr); \
    uint32_t _parity = (uint32_t)(phase_parity); \
    uint32_t _done; \
    asm volatile( \
        "{\n\t.reg .pred p;\n\t" \
        "mbarrier.try_wait.parity.acquire.cta.shared::cta.b64 p, [%1], %2;\n\t" \
        "selp.b32 %0, 1, 0, p;\n\t}" \
        : "=r"(_done) : "r"(_mbar), "r"(_parity) : "memory"); \
    if (!_done) { \
        asm volatile( \
            "{\n\t.reg .pred P1;\n\t" \
            "WAIT_LOOP_%=:\n\t" \
            "mbarrier.try_wait.parity.acquire.cta.shared::cta.b64 P1, [%0], %1, 0x989680;\n\t" \
            "@P1 bra.uni WAIT_DONE_%=;\n\t" \
            "bra.uni WAIT_LOOP_%=;\n\t" \
            "WAIT_DONE_%=:\n\t}" \
            :: "r"(_mbar), "r"(_parity) : "memory"); \
    } \
} while(0)

#define MBARRIER_WAIT_PARITY_RELAXED(mbar_smem_addr, phase_parity) do { \
    uint32_t _mbar = (uint32_t)(mbar_smem_addr); \
    uint32_t _parity = (uint32_t)(phase_parity); \
    uint32_t _done; \
    asm volatile( \
        "{\n\t.reg .pred p;\n\t" \
        "mbarrier.try_wait.parity.relaxed.cta.shared::cta.b64 p, [%1], %2, 0x989680;\n\t" \
        "selp.b32 %0, 1, 0, p;\n\t}" \
        : "=r"(_done) : "r"(_mbar), "r"(_parity) : "memory"); \
    if (!_done) { \
        asm volatile( \
            "{\n\t.reg .pred P1;\n\t" \
            "WAIT_LOOP_%=:\n\t" \
            "mbarrier.try_wait.parity.relaxed.cta.shared::cta.b64 P1, [%0], %1, 0x989680;\n\t" \
            "@P1 bra.uni WAIT_DONE_%=;\n\t" \
            "bra.uni WAIT_LOOP_%=;\n\t" \
            "WAIT_DONE_%=:\n\t}" \
            :: "r"(_mbar), "r"(_parity) : "memory"); \
    } \
} while(0)

__device__ __forceinline__ void tma2d(uint32_t dst, const void* map, int x, int y, uint32_t mbar) {
    asm volatile(
        "cp.async.bulk.tensor.2d.shared::cta.global.tile.mbarrier::complete_tx::bytes "
        "[%0], [%1, {%2, %3}], [%4];"
        :: "r"(dst), "l"(map), "r"(x), "r"(y), "r"(mbar) : "memory");
}

__device__ __forceinline__ void ldsm4(uint32_t* r, uint32_t addr) {
    asm volatile("ldmatrix.sync.aligned.m8n8.x4.shared.b16 {%0,%1,%2,%3}, [%4];"
                 : "=r"(r[0]), "=r"(r[1]), "=r"(r[2]), "=r"(r[3]) : "r"(addr));
}
__device__ __forceinline__ void ldsm4t(uint32_t* r, uint32_t addr) {
    asm volatile("ldmatrix.sync.aligned.m8n8.x4.trans.shared.b16 {%0,%1,%2,%3}, [%4];"
                 : "=r"(r[0]), "=r"(r[1]), "=r"(r[2]), "=r"(r[3]) : "r"(addr));
}

__device__ __forceinline__ void mma_fp16(float* d, const uint32_t* a, uint32_t b0, uint32_t b1) {
    asm volatile(
        "mma.sync.aligned.m16n8k16.row.col.f32.f16.f16.f32 "
        "{%0,%1,%2,%3}, {%4,%5,%6,%7}, {%8,%9}, {%0,%1,%2,%3};"
        : "+f"(d[0]), "+f"(d[1]), "+f"(d[2]), "+f"(d[3])
        : "r"(a[0]), "r"(a[1]), "r"(a[2]), "r"(a[3]), "r"(b0), "r"(b1));
}

__device__ __forceinline__ uint32_t pack2h(float a, float b) {
    __half2 t = __floats2half2_rn(a, b);
    return *reinterpret_cast<uint32_t*>(&t);
}

// Fast exp on the FMA pipe. Valid for x <= 0 (clamped below -80).
__device__ __forceinline__ float fexp(float x) {
    x = fmaxf(x, -80.0f);
    float t = x * 1.4426950408889634f;
    float z = t + 12582912.0f;
    int n = __float_as_int(z) - 0x4b400000;
    float f = t - (z - 12582912.0f);
    float u = f * 0.6931471805599453f;
    float r = 1.3888889e-3f;
    r = fmaf(r, u, 8.3333338e-3f);
    r = fmaf(r, u, 4.1666668e-2f);
    r = fmaf(r, u, 1.6666667e-1f);
    r = fmaf(r, u, 0.5f);
    r = fmaf(r, u, 1.0f);
    r = fmaf(r, u, 1.0f);
    return r * __int_as_float((n + 127) << 23);
}

// ---------------------------------------------------------------------------
// fp16 mixed-precision GEMM, CTA tile 128(M) x 64(N) for wave-quantization fit.
// 8 warps = 4M x 2N, warp tile 32x32. K-chunk 64, SW128, 3-stage TMA.
// B lo-residual only for output columns >= lo_start (per-CTA uniform).
// MODE 0: fp32 out.  MODE 1: fp16 single out, q-cols pre-scaled.
// ---------------------------------------------------------------------------
#define GCHUNKS     32
#define GTILE_A     16384              // 128 rows x 64 halves
#define GTILE_B     8192               // 64 rows x 64 halves
#define GSTAGE_BYTES (GTILE_A + 2 * GTILE_B)   // 32768
#define GSM_DATA    1024
#define GEMM_SMEM   (GSM_DATA + 3 * GSTAGE_BYTES)   // 99328

template <int MODE>
__global__ __launch_bounds__(256, 1)
void gemm_fp16x2_kernel(const __grid_constant__ CUtensorMap tmA,
                        const __grid_constant__ CUtensorMap tmBh,
                        const __grid_constant__ CUtensorMap tmBl,
                        const float* __restrict__ bias,
                        float* __restrict__ C,
                        unsigned short* __restrict__ Ch,
                        int N, int lo_start, int col_shift)
{
    extern __shared__ __align__(1024) char gsm[];
    const uint32_t sb = smem_u32(gsm);
    const int tid = threadIdx.x;
    const int lane = tid & 31;
    const int wid = tid >> 5;
    const int row0 = blockIdx.y * 128;
    const int cidx = ((int)blockIdx.x + col_shift) % (int)gridDim.x;
    const int col0 = cidx * 64;
    const int wm = (wid & 3) * 32;
    const int wn = (wid >> 2) * 32;
    const bool use_lo = (col0 >= lo_start);
    const uint32_t stage_tx = use_lo ? (uint32_t)GSTAGE_BYTES
                                     : (uint32_t)(GTILE_A + GTILE_B);

    if (tid == 0) {
#pragma unroll
        for (int s = 0; s < 3; ++s) {
            MBARRIER_INIT(sb + 8 * s, 1);
            MBARRIER_INIT(sb + 24 + 8 * s, 256);
        }
    }
    __syncthreads();

    if (tid == 0) {
#pragma unroll
        for (int p = 0; p < 3; ++p) {
            const uint32_t st = sb + GSM_DATA + p * GSTAGE_BYTES;
            MBARRIER_EXPECT_TX(sb + 8 * p, stage_tx);
            const int k0 = p * 64;
            tma2d(st,           &tmA,  k0, row0, sb + 8 * p);
            tma2d(st + GTILE_A, &tmBh, k0, col0, sb + 8 * p);
            if (use_lo)
                tma2d(st + GTILE_A + GTILE_B, &tmBl, k0, col0, sb + 8 * p);
        }
    }

    float acc[2][4][4];
#pragma unroll
    for (int i = 0; i < 2; i++)
#pragma unroll
        for (int j = 0; j < 4; j++)
#pragma unroll
            for (int k = 0; k < 4; k++) acc[i][j][k] = 0.f;

    const uint32_t cbase = (lane >> 4) * 16;
    uint32_t aRB[2], aMask[2], bRB[2], bMask[2];
#pragma unroll
    for (int mt = 0; mt < 2; ++mt) {
        const int r = wm + mt * 16 + (lane & 15);
        aRB[mt] = (uint32_t)r * 128;
        aMask[mt] = (uint32_t)((r & 7) << 4);
    }
#pragma unroll
    for (int j = 0; j < 2; ++j) {
        const int r = wn + j * 16 + (lane & 15);
        bRB[j] = (uint32_t)r * 128;
        bMask[j] = (uint32_t)((r & 7) << 4);
    }

    for (int c = 0; c < GCHUNKS; ++c) {
        const int u = c / 3;
        const int s = c - u * 3;
        MBARRIER_WAIT_PARITY(sb + 8 * s, (uint32_t)(u & 1));

        const uint32_t stA  = sb + GSM_DATA + s * GSTAGE_BYTES;
        const uint32_t stBh = stA + GTILE_A;
        const uint32_t stBl = stBh + GTILE_B;

#pragma unroll
        for (int kk = 0; kk < 4; ++kk) {
            const uint32_t kb = cbase + kk * 32;
            uint32_t a[2][4], bh[2][4];
#pragma unroll
            for (int mt = 0; mt < 2; ++mt)
                ldsm4(a[mt], stA + aRB[mt] + (kb ^ aMask[mt]));
#pragma unroll
            for (int j = 0; j < 2; ++j)
                ldsm4(bh[j], stBh + bRB[j] + (kb ^ bMask[j]));
#pragma unroll
            for (int mt = 0; mt < 2; ++mt)
#pragma unroll
                for (int j = 0; j < 2; ++j) {
                    mma_fp16(acc[mt][2 * j],     a[mt], bh[j][0], bh[j][2]);
                    mma_fp16(acc[mt][2 * j + 1], a[mt], bh[j][1], bh[j][3]);
                }
            if (use_lo) {
                uint32_t bl[2][4];
#pragma unroll
                for (int j = 0; j < 2; ++j)
                    ldsm4(bl[j], stBl + bRB[j] + (kb ^ bMask[j]));
#pragma unroll
                for (int mt = 0; mt < 2; ++mt)
#pragma unroll
                    for (int j = 0; j < 2; ++j) {
                        mma_fp16(acc[mt][2 * j],     a[mt], bl[j][0], bl[j][2]);
                        mma_fp16(acc[mt][2 * j + 1], a[mt], bl[j][1], bl[j][3]);
                    }
            }
        }

        MBARRIER_ARRIVE(sb + 24 + 8 * s);

        const int p = c + 3;
        if (tid == 0 && p < GCHUNKS) {
            const int up = p / 3;
            MBARRIER_WAIT_PARITY_RELAXED(sb + 24 + 8 * s, (uint32_t)((up & 1) ^ 1));
            const uint32_t st = sb + GSM_DATA + s * GSTAGE_BYTES;
            MBARRIER_EXPECT_TX(sb + 8 * s, stage_tx);
            const int k0 = p * 64;
            tma2d(st,           &tmA,  k0, row0, sb + 8 * s);
            tma2d(st + GTILE_A, &tmBh, k0, col0, sb + 8 * s);
            if (use_lo)
                tma2d(st + GTILE_A + GTILE_B, &tmBl, k0, col0, sb + 8 * s);
        }
    }

    // Epilogue
    const int rr = lane >> 2;
    const int cc = (lane & 3) * 2;
#pragma unroll
    for (int mt = 0; mt < 2; ++mt) {
        const int mrow = row0 + wm + mt * 16 + rr;
#pragma unroll
        for (int nt = 0; nt < 4; ++nt) {
            const int n = col0 + wn + nt * 8 + cc;
            const float2 bb = *(const float2*)(bias + n);
            float v00 = acc[mt][nt][0] + bb.x, v01 = acc[mt][nt][1] + bb.y;
            float v10 = acc[mt][nt][2] + bb.x, v11 = acc[mt][nt][3] + bb.y;
            if (MODE == 0) {
                *(float2*)(C + (size_t)mrow * N + n) = make_float2(v00, v01);
                *(float2*)(C + (size_t)(mrow + 8) * N + n) = make_float2(v10, v11);
            } else {
                const float sc = (n < 2048) ? QSCALE : 1.0f;
                *(uint32_t*)(Ch + (size_t)mrow * N + n)       = pack2h(v00 * sc, v01 * sc);
                *(uint32_t*)(Ch + (size_t)(mrow + 8) * N + n) = pack2h(v10 * sc, v11 * sc);
            }
        }
    }
}

// ---------------------------------------------------------------------------
// Fused dual-stream differential flash attention (unchanged from R14/R15).
// ---------------------------------------------------------------------------
#define AT_NSTG 3
#define AT_STAGE_BYTES 32768
#define AT_SMEM (32768 + AT_NSTG * AT_STAGE_BYTES)

__global__ __launch_bounds__(256, 1)
void diff_attn_fused_kernel(const __grid_constant__ CUtensorMap tmT,
                            const float* __restrict__ amask,
                            const float* __restrict__ lambda_p,
                            unsigned short* __restrict__ O16)
{
    extern __shared__ __align__(1024) char asmem[];
    const uint32_t sb = smem_u32(asmem);
    const int tid = threadIdx.x, lane = tid & 31, w = tid >> 5;
    const int s_id = w >> 2;
    const int wq = w & 3;
    const int qb = blockIdx.x, bh = blockIdx.y;
    const int b = bh >> 4, h = bh & 15;
    const int q0 = qb * 64;
    const int tokbase = b * S_LEN;

    const uint32_t MB_Q = sb;
    float* maskSm = (float*)(asmem + 64);
    const uint32_t Q1 = sb + 16384;
    const uint32_t Q2 = sb + 24576;
    const uint32_t ST0 = sb + 32768;

    if (tid == 0) {
        MBARRIER_INIT(MB_Q, 1);
#pragma unroll
        for (int s = 0; s < AT_NSTG; ++s) {
            MBARRIER_INIT(sb + 8 + 8 * s, 1);
            MBARRIER_INIT(sb + 32 + 8 * s, 256);
        }
    }
    {
        const float4* mp = (const float4*)(amask + tokbase);
        float4* ms = (float4*)maskSm;
#pragma unroll
        for (int i = tid; i < 512; i += 256) {
            float4 v = mp[i];
            v.x = (1.f - v.x) * -10000.f;
            v.y = (1.f - v.y) * -10000.f;
            v.z = (1.f - v.z) * -10000.f;
            v.w = (1.f - v.w) * -10000.f;
            ms[i] = v;
        }
    }
    __syncthreads();

    const int q1col = h * 64;
    const int q2col = 1024 + h * 64;
    const int k1col = 2048 + h * 64;
    const int k2col = 3072 + h * 64;
    const int vcol  = 4096 + h * 128;

    if (tid == 0) {
        MBARRIER_EXPECT_TX(MB_Q, 16384);
        tma2d(Q1, &tmT, q1col, tokbase + q0, MB_Q);
        tma2d(Q2, &tmT, q2col, tokbase + q0, MB_Q);
#pragma unroll
        for (int s = 0; s < AT_NSTG; ++s) {
            const uint32_t st = ST0 + s * AT_STAGE_BYTES;
            const uint32_t fb = sb + 8 + 8 * s;
            MBARRIER_EXPECT_TX(fb, AT_STAGE_BYTES);
            const int k0 = tokbase + s * 64;
            tma2d(st,         &tmT, k1col,     k0, fb);
            tma2d(st + 8192,  &tmT, k2col,     k0, fb);
            tma2d(st + 16384, &tmT, vcol,      k0, fb);
            tma2d(st + 24576, &tmT, vcol + 64, k0, fb);
        }
    }

    MBARRIER_WAIT_PARITY(MB_Q, 0);
    uint32_t qh[4][4];
    {
        const uint32_t QT = s_id ? Q2 : Q1;
        const int r = 16 * wq + (lane & 15);
        const uint32_t rb = (uint32_t)r * 128;
        const uint32_t msk = (uint32_t)((r & 7) << 4);
        const uint32_t cbq = (uint32_t)(lane >> 4) * 16;
#pragma unroll
        for (int kk = 0; kk < 4; ++kk)
            ldsm4(qh[kk], QT + rb + ((cbq + kk * 32) ^ msk));
    }

    float o[16][4];
#pragma unroll
    for (int i = 0; i < 16; i++)
#pragma unroll
        for (int j = 0; j < 4; j++) o[i][j] = 0.f;
    float m0 = -1e30f, m1 = -1e30f, l0 = 0.f, l1 = 0.f;

    uint32_t kRB[4], kMask[4];
#pragma unroll
    for (int g = 0; g < 4; ++g) {
        const int r = 16 * g + (lane & 15);
        kRB[g] = (uint32_t)r * 128;
        kMask[g] = (uint32_t)((r & 7) << 4);
    }
    const uint32_t cb = (uint32_t)(lane >> 4) * 16;
    const uint32_t kOff = (uint32_t)s_id * 8192;

    for (int kb = 0; kb < 32; ++kb) {
        const int u = kb / 3;
        const int s = kb - u * 3;
        const uint32_t FULL = sb + 8 + 8 * s;
        const uint32_t EMPTY = sb + 32 + 8 * s;
        const uint32_t ST = ST0 + s * AT_STAGE_BYTES;
        MBARRIER_WAIT_PARITY(FULL, (uint32_t)(u & 1));

        float scf[8][4];
#pragma unroll
        for (int t = 0; t < 8; t++)
#pragma unroll
            for (int j = 0; j < 4; j++) scf[t][j] = 0.f;

#pragma unroll
        for (int kk = 0; kk < 4; ++kk) {
            uint32_t kh[4][4];
#pragma unroll
            for (int g = 0; g < 4; ++g) {
                const uint32_t a = cb + kk * 32;
                ldsm4(kh[g], ST + kOff + kRB[g] + (a ^ kMask[g]));
            }
#pragma unroll
            for (int g = 0; g < 4; ++g) {
                mma_fp16(scf[2 * g],     qh[kk], kh[g][0], kh[g][2]);
                mma_fp16(scf[2 * g + 1], qh[kk], kh[g][1], kh[g][3]);
            }
        }

        const int kbase = kb * 64 + 2 * (lane & 3);
        float nm0 = m0, nm1 = m1;
#pragma unroll
        for (int t = 0; t < 8; ++t) {
            const float mv0 = maskSm[kbase + 8 * t];
            const float mv1 = maskSm[kbase + 8 * t + 1];
            scf[t][0] += mv0; scf[t][1] += mv1;
            scf[t][2] += mv0; scf[t][3] += mv1;
            nm0 = fmaxf(nm0, fmaxf(scf[t][0], scf[t][1]));
            nm1 = fmaxf(nm1, fmaxf(scf[t][2], scf[t][3]));
        }
        nm0 = fmaxf(nm0, __shfl_xor_sync(0xffffffffu, nm0, 1));
        nm0 = fmaxf(nm0, __shfl_xor_sync(0xffffffffu, nm0, 2));
        nm1 = fmaxf(nm1, __shfl_xor_sync(0xffffffffu, nm1, 1));
        nm1 = fmaxf(nm1, __shfl_xor_sync(0xffffffffu, nm1, 2));
        const float a0 = fexp(m0 - nm0), a1 = fexp(m1 - nm1);
        m0 = nm0; m1 = nm1;
#pragma unroll
        for (int nt = 0; nt < 16; ++nt) {
            o[nt][0] *= a0; o[nt][1] *= a0;
            o[nt][2] *= a1; o[nt][3] *= a1;
        }

        uint32_t pha[4][4];
        float rs0 = 0.f, rs1 = 0.f;
#pragma unroll
        for (int t = 0; t < 8; ++t) {
            const float e0 = fexp(scf[t][0] - m0), e1 = fexp(scf[t][1] - m0);
            const float e2 = fexp(scf[t][2] - m1), e3 = fexp(scf[t][3] - m1);
            rs0 += e0 + e1; rs1 += e2 + e3;
            pha[t >> 1][2 * (t & 1)]     = pack2h(e0, e1);
            pha[t >> 1][2 * (t & 1) + 1] = pack2h(e2, e3);
        }
        rs0 += __shfl_xor_sync(0xffffffffu, rs0, 1);
        rs0 += __shfl_xor_sync(0xffffffffu, rs0, 2);
        rs1 += __shfl_xor_sync(0xffffffffu, rs1, 1);
        rs1 += __shfl_xor_sync(0xffffffffu, rs1, 2);
        l0 = l0 * a0 + rs0;
        l1 = l1 * a1 + rs1;

#pragma unroll
        for (int kk = 0; kk < 4; ++kk) {
            const int r = 16 * kk + (lane & 15);
            const uint32_t vrb = (uint32_t)r * 128;
            const uint32_t vmsk = (uint32_t)((r & 7) << 4);
#pragma unroll
            for (int g = 0; g < 8; ++g) {
                const uint32_t base = ST + 16384 + ((g >> 2) ? 8192u : 0u);
                const uint32_t a = ((uint32_t)((g & 3) * 32) + cb) ^ vmsk;
                uint32_t vh[4];
                ldsm4t(vh, base + vrb + a);
                mma_fp16(o[2 * g],     pha[kk], vh[0], vh[1]);
                mma_fp16(o[2 * g + 1], pha[kk], vh[2], vh[3]);
            }
        }

        MBARRIER_ARRIVE(EMPTY);

        const int p = kb + AT_NSTG;
        if (tid == 0 && p < 32) {
            const int up = p / 3;
            MBARRIER_WAIT_PARITY_RELAXED(EMPTY, (uint32_t)((up & 1) ^ 1));
            MBARRIER_EXPECT_TX(FULL, AT_STAGE_BYTES);
            const int k0 = tokbase + p * 64;
            tma2d(ST,         &tmT, k1col,     k0, FULL);
            tma2d(ST + 8192,  &tmT, k2col,     k0, FULL);
            tma2d(ST + 16384, &tmT, vcol,      k0, FULL);
            tma2d(ST + 24576, &tmT, vcol + 64, k0, FULL);
        }
    }

    __syncthreads();
    float* Cb = (float*)(asmem + 32768 + s_id * 32768);
    {
        const float inv0 = 1.f / l0, inv1 = 1.f / l1;
        const int r0 = 16 * wq + (lane >> 2);
        const int cc = 2 * (lane & 3);
#pragma unroll
        for (int nt = 0; nt < 16; ++nt) {
            Cb[r0 * 128 + 8 * nt + cc]           = o[nt][0] * inv0;
            Cb[r0 * 128 + 8 * nt + cc + 1]       = o[nt][1] * inv0;
            Cb[(r0 + 8) * 128 + 8 * nt + cc]     = o[nt][2] * inv1;
            Cb[(r0 + 8) * 128 + 8 * nt + cc + 1] = o[nt][3] * inv1;
        }
    }
    __syncthreads();

    const float lam = *lambda_p;
    const float* C1b = (const float*)(asmem + 32768);
    const float* C2b = (const float*)(asmem + 65536);
    for (int idx = tid; idx < 64 * 32; idx += 256) {
        const int row = idx >> 5;
        const int c4 = (idx & 31) * 4;
        float4 a = *(const float4*)&C1b[row * 128 + c4];
        float4 c = *(const float4*)&C2b[row * 128 + c4];
        uint2 H;
        H.x = pack2h(a.x - lam * c.x, a.y - lam * c.y);
        H.y = pack2h(a.z - lam * c.z, a.w - lam * c.w);
        *(uint2*)(O16 + (size_t)(tokbase + q0 + row) * DMODEL + h * 128 + c4) = H;
    }
}

// ---------------------------------------------------------------------------
// Merged preprocessing (unchanged from R15)
// ---------------------------------------------------------------------------
#define PREP_A_BLOCKS 8192
#define PREP_B_BLOCKS 12288
#define PREP_C_BLOCKS 4096
#define PREP_BLOCKS (PREP_A_BLOCKS + PREP_B_BLOCKS + PREP_C_BLOCKS)

__global__ __launch_bounds__(256)
void prep_kernel(const float4* __restrict__ hidden,
                 const float* __restrict__ W_attn,
                 const float* __restrict__ W_proj,
                 uint2* __restrict__ A16,
                 __half* __restrict__ WAh, __half* __restrict__ WAl,
                 __half* __restrict__ WPh, __half* __restrict__ WPl)
{
    __shared__ float t[32][33];
    const int bid = blockIdx.x;
    const int tid = threadIdx.x;

    if (bid < PREP_A_BLOCKS) {
        const int i = bid * 256 + tid;
        float4 v = hidden[i];
        uint2 H;
        H.x = pack2h(v.x, v.y);
        H.y = pack2h(v.z, v.w);
        A16[i] = H;
        return;
    }

    const int tx = tid & 31, ty = tid >> 5;
    if (bid < PREP_A_BLOCKS + PREP_B_BLOCKS) {
        const int local = bid - PREP_A_BLOCKS;
        const int n0 = (local % 192) * 32;
        const int k0 = (local / 192) * 32;
#pragma unroll
        for (int r = 0; r < 4; ++r)
            t[ty + 8 * r][tx] = W_attn[(size_t)(k0 + ty + 8 * r) * N_QKV + n0 + tx];
        __syncthreads();
        const bool write_lo = (n0 >= 4096);
#pragma unroll
        for (int r = 0; r < 4; ++r) {
            const int nn = ty + 8 * r;
            float v = t[tx][nn];
            __half hh = __float2half_rn(v);
            const size_t off = (size_t)(n0 + nn) * KDIM + k0 + tx;
            WAh[off] = hh;
            if (write_lo)
                WAl[off] = __float2half_rn(v - __half2float(hh));
        }
        return;
    }

    const int local = bid - PREP_A_BLOCKS - PREP_B_BLOCKS;
    const int n0 = (local % 64) * 32;
    const int k0 = (local / 64) * 32;
#pragma unroll
    for (int r = 0; r < 4; ++r)
        t[ty + 8 * r][tx] = W_proj[(size_t)(k0 + ty + 8 * r) * DMODEL + n0 + tx];
    __syncthreads();
#pragma unroll
    for (int r = 0; r < 4; ++r) {
        const int nn = ty + 8 * r;
        float v = t[tx][nn];
        __half hh = __float2half_rn(v);
        const size_t off = (size_t)(n0 + nn) * KDIM + k0 + tx;
        WPh[off] = hh;
        WPl[off] = __float2half_rn(v - __half2float(hh));
    }
}

// ---------------------------------------------------------------------------
// Host side
// ---------------------------------------------------------------------------
typedef CUresult (*PFN_tmEncode)(
    CUtensorMap*, CUtensorMapDataType, cuuint32_t, void*,
    const cuuint64_t*, const cuuint64_t*, const cuuint32_t*, const cuuint32_t*,
    CUtensorMapInterleave, CUtensorMapSwizzle, CUtensorMapL2promotion,
    CUtensorMapFloatOOBfill);

static void make_map(PFN_tmEncode fn, CUtensorMap* m, void* ptr,
                     unsigned long long rows, unsigned long long cols,
                     unsigned box0, unsigned box1)
{
    cuuint64_t dims[2]    = {(cuuint64_t)cols, (cuuint64_t)rows};
    cuuint64_t strides[1] = {(cuuint64_t)cols * 2};
    cuuint32_t box[2]     = {box0, box1};
    cuuint32_t es[2]      = {1u, 1u};
    fn(m, CU_TENSOR_MAP_DATA_TYPE_BFLOAT16, 2, ptr, dims, strides, box, es,
       CU_TENSOR_MAP_INTERLEAVE_NONE, CU_TENSOR_MAP_SWIZZLE_128B,
       CU_TENSOR_MAP_L2_PROMOTION_L2_128B, CU_TENSOR_MAP_FLOAT_OOB_FILL_NONE);
}

extern "C" void kernel_launch(void* const* d_in, const int* in_sizes, int n_in,
                              void* d_out, int out_size)
{
    const float* hidden = (const float*)d_in[0];
    const float* amask  = (const float*)d_in[1];
    const float* W_attn = (const float*)d_in[2];
    const float* b_attn = (const float*)d_in[3];
    const float* W_proj = (const float*)d_in[4];
    const float* b_proj = (const float*)d_in[5];
    const float* lam    = (const float*)d_in[6];
    float* out = (float*)d_out;

    void *qkv16, *A16, *WAh, *WAl, *WPh, *WPl, *O16;
    cudaGetSymbolAddress(&qkv16, g_qkv16);
    cudaGetSymbolAddress(&A16, g_A16);
    cudaGetSymbolAddress(&WAh, g_WAh);   cudaGetSymbolAddress(&WAl, g_WAl);
    cudaGetSymbolAddress(&WPh, g_WPh);   cudaGetSymbolAddress(&WPl, g_WPl);
    cudaGetSymbolAddress(&O16, g_O16);

    void* fnp = nullptr;
    cudaDriverEntryPointQueryResult qres;
    cudaGetDriverEntryPointByVersion("cuTensorMapEncodeTiled", &fnp, 12000,
                                     cudaEnableDefault, &qres);
    PFN_tmEncode enc = (PFN_tmEncode)fnp;

    CUtensorMap tA, tWAh, tWAl, tWPh, tWPl, tO, tT;
    make_map(enc, &tA,   A16,  M_TOK,  KDIM, 64, 128);
    make_map(enc, &tWAh, WAh,  N_QKV,  KDIM, 64, 64);
    make_map(enc, &tWAl, WAl,  N_QKV,  KDIM, 64, 64);
    make_map(enc, &tWPh, WPh,  DMODEL, KDIM, 64, 64);
    make_map(enc, &tWPl, WPl,  DMODEL, KDIM, 64, 64);
    make_map(enc, &tO,   O16,  M_TOK,  KDIM, 64, 128);
    make_map(enc, &tT,   qkv16, M_TOK, N_QKV, 64, 64);

    cudaFuncSetAttribute(gemm_fp16x2_kernel<0>,
                         cudaFuncAttributeMaxDynamicSharedMemorySize, GEMM_SMEM);
    cudaFuncSetAttribute(gemm_fp16x2_kernel<1>,
                         cudaFuncAttributeMaxDynamicSharedMemorySize, GEMM_SMEM);
    cudaFuncSetAttribute(diff_attn_fused_kernel,
                         cudaFuncAttributeMaxDynamicSharedMemorySize, AT_SMEM);

    // 1) merged preprocessing
    prep_kernel<<<PREP_BLOCKS, 256>>>((const float4*)hidden, W_attn, W_proj,
                                      (uint2*)A16,
                                      (__half*)WAh, (__half*)WAl,
                                      (__half*)WPh, (__half*)WPl);
    // 2) QKV GEMM: N-tile 64; 1-term q/k (col<4096), 2-term v; heavy CTAs first
    {
        dim3 g(N_QKV / 64, M_TOK / 128);   // (96, 32)
        gemm_fp16x2_kernel<1><<<g, 256, GEMM_SMEM>>>(tA, tWAh, tWAl, b_attn,
                                                     nullptr, (unsigned short*)qkv16,
                                                     N_QKV, 4096, 64);
    }
    // 3) fused dual-stream differential attention -> fp16 O16
    {
        dim3 g(S_LEN / 64, B_SZ * NHEAD);
        diff_attn_fused_kernel<<<g, 256, AT_SMEM>>>(tT, amask, lam,
                                                    (unsigned short*)O16);
    }
    // 4) output projection (N-tile 64, fp16 x2, fp32 out)
    {
        dim3 g(DMODEL / 64, M_TOK / 128);  // (32, 32)
        gemm_fp16x2_kernel<0><<<g, 256, GEMM_SMEM>>>(tO, tWPh, tWPl, b_proj,
                                                     out, nullptr, DMODEL, 0, 0);
    }
}

// round 17
// speedup vs baseline: 2.1155x; 1.0259x over previous
#include <cuda_runtime.h>
#include <cuda_fp16.h>
#include <cuda.h>
#include <cstdint>

// Problem dims (fixed by setup_inputs)
#define B_SZ   2
#define S_LEN  2048
#define DMODEL 2048
#define NHEAD  16
#define M_TOK  (B_SZ * S_LEN)     // 4096
#define N_QKV  (3 * DMODEL)       // 6144
#define KDIM   DMODEL             // 2048
#define QSCALE 0.0883883476483184f

// ---------------- scratch (static device globals: allocation-free) ----------
__device__ unsigned short g_qkv16[(size_t)M_TOK * N_QKV];
__device__ unsigned short g_A16[(size_t)M_TOK * KDIM];
__device__ unsigned short g_WAh[(size_t)N_QKV * KDIM];
__device__ unsigned short g_WAl[(size_t)N_QKV * KDIM];
__device__ unsigned short g_WPh[(size_t)DMODEL * KDIM];
__device__ unsigned short g_WPl[(size_t)DMODEL * KDIM];
__device__ unsigned short g_O16[(size_t)M_TOK * KDIM];

// ---------------------------------------------------------------------------
// PTX helpers (base sm_90 only)
// ---------------------------------------------------------------------------
__device__ __forceinline__ uint32_t smem_u32(const void* p) {
    uint32_t a;
    asm("{ .reg .u64 t; cvta.to.shared.u64 t, %1; cvt.u32.u64 %0, t; }" : "=r"(a) : "l"(p));
    return a;
}

#define MBARRIER_INIT(addr, cnt) \
    asm volatile("mbarrier.init.shared.b64 [%0], %1;" :: "r"((uint32_t)(addr)), "r"((uint32_t)(cnt)) : "memory")

#define MBARRIER_ARRIVE(addr) \
    asm volatile("mbarrier.arrive.shared.b64 _, [%0];" :: "r"((uint32_t)(addr)) : "memory")

#define MBARRIER_EXPECT_TX(addr, bytes) \
    asm volatile("mbarrier.arrive.expect_tx.shared.b64 _, [%0], %1;" :: "r"((uint32_t)(addr)), "r"((uint32_t)(bytes)) : "memory")

#define MBARRIER_WAIT_PARITY(mbar_smem_addr, phase_parity) do { \
    uint32_t _mbar = (uint32_t)(mbar_smem_addr); \
    uint32_t _parity = (uint32_t)(phase_parity); \
    uint32_t _done; \
    asm volatile( \
        "{\n\t.reg .pred p;\n\t" \
        "mbarrier.try_wait.parity.acquire.cta.shared::cta.b64 p, [%1], %2;\n\t" \
        "selp.b32 %0, 1, 0, p;\n\t}" \
        : "=r"(_done) : "r"(_mbar), "r"(_parity) : "memory"); \
    if (!_done) { \
        asm volatile( \
            "{\n\t.reg .pred P1;\n\t" \
            "WAIT_LOOP_%=:\n\t" \
            "mbarrier.try_wait.parity.acquire.cta.shared::cta.b64 P1, [%0], %1, 0x989680;\n\t" \
            "@P1 bra.uni WAIT_DONE_%=;\n\t" \
            "bra.uni WAIT_LOOP_%=;\n\t" \
            "WAIT_DONE_%=:\n\t}" \
            :: "r"(_mbar), "r"(_parity) : "memory"); \
    } \
} while(0)

#define MBARRIER_WAIT_PARITY_RELAXED(mbar_smem_addr, phase_parity) do { \
    uint32_t _mbar = (uint32_t)(mbar_smem_addr); \
    uint32_t _parity = (uint32_t)(phase_parity); \
    uint32_t _done; \
    asm volatile( \
        "{\n\t.reg .pred p;\n\t" \
        "mbarrier.try_wait.parity.relaxed.cta.shared::cta.b64 p, [%1], %2, 0x989680;\n\t" \
        "selp.b32 %0, 1, 0, p;\n\t}" \
        : "=r"(_done) : "r"(_mbar), "r"(_parity) : "memory"); \
    if (!_done) { \
        asm volatile( \
            "{\n\t.reg .pred P1;\n\t" \
            "WAIT_LOOP_%=:\n\t" \
            "mbarrier.try_wait.parity.relaxed.cta.shared::cta.b64 P1, [%0], %1, 0x989680;\n\t" \
            "@P1 bra.uni WAIT_DONE_%=;\n\t" \
            "bra.uni WAIT_LOOP_%=;\n\t" \
            "WAIT_DONE_%=:\n\t}" \
            :: "r"(_mbar), "r"(_parity) : "memory"); \
    } \
} while(0)

__device__ __forceinline__ void tma2d(uint32_t dst, const void* map, int x, int y, uint32_t mbar) {
    asm volatile(
        "cp.async.bulk.tensor.2d.shared::cta.global.tile.mbarrier::complete_tx::bytes "
        "[%0], [%1, {%2, %3}], [%4];"
        :: "r"(dst), "l"(map), "r"(x), "r"(y), "r"(mbar) : "memory");
}

__device__ __forceinline__ void ldsm4(uint32_t* r, uint32_t addr) {
    asm volatile("ldmatrix.sync.aligned.m8n8.x4.shared.b16 {%0,%1,%2,%3}, [%4];"
                 : "=r"(r[0]), "=r"(r[1]), "=r"(r[2]), "=r"(r[3]) : "r"(addr));
}
__device__ __forceinline__ void ldsm4t(uint32_t* r, uint32_t addr) {
    asm volatile("ldmatrix.sync.aligned.m8n8.x4.trans.shared.b16 {%0,%1,%2,%3}, [%4];"
                 : "=r"(r[0]), "=r"(r[1]), "=r"(r[2]), "=r"(r[3]) : "r"(addr));
}

__device__ __forceinline__ void mma_fp16(float* d, const uint32_t* a, uint32_t b0, uint32_t b1) {
    asm volatile(
        "mma.sync.aligned.m16n8k16.row.col.f32.f16.f16.f32 "
        "{%0,%1,%2,%3}, {%4,%5,%6,%7}, {%8,%9}, {%0,%1,%2,%3};"
        : "+f"(d[0]), "+f"(d[1]), "+f"(d[2]), "+f"(d[3])
        : "r"(a[0]), "r"(a[1]), "r"(a[2]), "r"(a[3]), "r"(b0), "r"(b1));
}

__device__ __forceinline__ uint32_t pack2h(float a, float b) {
    __half2 t = __floats2half2_rn(a, b);
    return *reinterpret_cast<uint32_t*>(&t);
}

// Fast exp on the FMA pipe. Valid for x <= 0 (clamped below -80).
__device__ __forceinline__ float fexp(float x) {
    x = fmaxf(x, -80.0f);
    float t = x * 1.4426950408889634f;
    float z = t + 12582912.0f;
    int n = __float_as_int(z) - 0x4b400000;
    float f = t - (z - 12582912.0f);
    float u = f * 0.6931471805599453f;
    float r = 1.3888889e-3f;
    r = fmaf(r, u, 8.3333338e-3f);
    r = fmaf(r, u, 4.1666668e-2f);
    r = fmaf(r, u, 1.6666667e-1f);
    r = fmaf(r, u, 0.5f);
    r = fmaf(r, u, 1.0f);
    r = fmaf(r, u, 1.0f);
    return r * __int_as_float((n + 127) << 23);
}

// ---------------------------------------------------------------------------
// fp16 mixed-precision GEMM, CTA tile 128(M) x 64(N).
// B lo-residual applied only for output cols >= lo_start AND k-chunks < lo_kmax.
// 8 warps = 4M x 2N, warp tile 32x32. K-chunk 64, SW128, 3-stage TMA.
// MODE 0: fp32 out.  MODE 1: fp16 single out, q-cols pre-scaled.
// ---------------------------------------------------------------------------
#define GCHUNKS     32
#define GTILE_A     16384              // 128 rows x 64 halves
#define GTILE_B     8192               // 64 rows x 64 halves
#define GSTAGE_BYTES (GTILE_A + 2 * GTILE_B)   // 32768
#define GSM_DATA    1024
#define GEMM_SMEM   (GSM_DATA + 3 * GSTAGE_BYTES)   // 99328

template <int MODE>
__global__ __launch_bounds__(256, 1)
void gemm_fp16x2_kernel(const __grid_constant__ CUtensorMap tmA,
                        const __grid_constant__ CUtensorMap tmBh,
                        const __grid_constant__ CUtensorMap tmBl,
                        const float* __restrict__ bias,
                        float* __restrict__ C,
                        unsigned short* __restrict__ Ch,
                        int N, int lo_start, int lo_kmax, int col_shift)
{
    extern __shared__ __align__(1024) char gsm[];
    const uint32_t sb = smem_u32(gsm);
    const int tid = threadIdx.x;
    const int lane = tid & 31;
    const int wid = tid >> 5;
    const int row0 = blockIdx.y * 128;
    const int cidx = ((int)blockIdx.x + col_shift) % (int)gridDim.x;
    const int col0 = cidx * 64;
    const int wm = (wid & 3) * 32;
    const int wn = (wid >> 2) * 32;
    const bool use_lo = (col0 >= lo_start);

    if (tid == 0) {
#pragma unroll
        for (int s = 0; s < 3; ++s) {
            MBARRIER_INIT(sb + 8 * s, 1);
            MBARRIER_INIT(sb + 24 + 8 * s, 256);
        }
    }
    __syncthreads();

    if (tid == 0) {
#pragma unroll
        for (int p = 0; p < 3; ++p) {
            const bool lo_p = use_lo && (p < lo_kmax);
            const uint32_t st = sb + GSM_DATA + p * GSTAGE_BYTES;
            MBARRIER_EXPECT_TX(sb + 8 * p,
                               lo_p ? (uint32_t)GSTAGE_BYTES
                                    : (uint32_t)(GTILE_A + GTILE_B));
            const int k0 = p * 64;
            tma2d(st,           &tmA,  k0, row0, sb + 8 * p);
            tma2d(st + GTILE_A, &tmBh, k0, col0, sb + 8 * p);
            if (lo_p)
                tma2d(st + GTILE_A + GTILE_B, &tmBl, k0, col0, sb + 8 * p);
        }
    }

    float acc[2][4][4];
#pragma unroll
    for (int i = 0; i < 2; i++)
#pragma unroll
        for (int j = 0; j < 4; j++)
#pragma unroll
            for (int k = 0; k < 4; k++) acc[i][j][k] = 0.f;

    const uint32_t cbase = (lane >> 4) * 16;
    uint32_t aRB[2], aMask[2], bRB[2], bMask[2];
#pragma unroll
    for (int mt = 0; mt < 2; ++mt) {
        const int r = wm + mt * 16 + (lane & 15);
        aRB[mt] = (uint32_t)r * 128;
        aMask[mt] = (uint32_t)((r & 7) << 4);
    }
#pragma unroll
    for (int j = 0; j < 2; ++j) {
        const int r = wn + j * 16 + (lane & 15);
        bRB[j] = (uint32_t)r * 128;
        bMask[j] = (uint32_t)((r & 7) << 4);
    }

    for (int c = 0; c < GCHUNKS; ++c) {
        const int u = c / 3;
        const int s = c - u * 3;
        MBARRIER_WAIT_PARITY(sb + 8 * s, (uint32_t)(u & 1));

        const uint32_t stA  = sb + GSM_DATA + s * GSTAGE_BYTES;
        const uint32_t stBh = stA + GTILE_A;
        const uint32_t stBl = stBh + GTILE_B;
        const bool do_lo = use_lo && (c < lo_kmax);

#pragma unroll
        for (int kk = 0; kk < 4; ++kk) {
            const uint32_t kb = cbase + kk * 32;
            uint32_t a[2][4], bh[2][4];
#pragma unroll
            for (int mt = 0; mt < 2; ++mt)
                ldsm4(a[mt], stA + aRB[mt] + (kb ^ aMask[mt]));
#pragma unroll
            for (int j = 0; j < 2; ++j)
                ldsm4(bh[j], stBh + bRB[j] + (kb ^ bMask[j]));
#pragma unroll
            for (int mt = 0; mt < 2; ++mt)
#pragma unroll
                for (int j = 0; j < 2; ++j) {
                    mma_fp16(acc[mt][2 * j],     a[mt], bh[j][0], bh[j][2]);
                    mma_fp16(acc[mt][2 * j + 1], a[mt], bh[j][1], bh[j][3]);
                }
            if (do_lo) {
                uint32_t bl[2][4];
#pragma unroll
                for (int j = 0; j < 2; ++j)
                    ldsm4(bl[j], stBl + bRB[j] + (kb ^ bMask[j]));
#pragma unroll
                for (int mt = 0; mt < 2; ++mt)
#pragma unroll
                    for (int j = 0; j < 2; ++j) {
                        mma_fp16(acc[mt][2 * j],     a[mt], bl[j][0], bl[j][2]);
                        mma_fp16(acc[mt][2 * j + 1], a[mt], bl[j][1], bl[j][3]);
                    }
            }
        }

        MBARRIER_ARRIVE(sb + 24 + 8 * s);

        const int p = c + 3;
        if (tid == 0 && p < GCHUNKS) {
            const int up = p / 3;
            MBARRIER_WAIT_PARITY_RELAXED(sb + 24 + 8 * s, (uint32_t)((up & 1) ^ 1));
            const bool lo_p = use_lo && (p < lo_kmax);
            const uint32_t st = sb + GSM_DATA + s * GSTAGE_BYTES;
            MBARRIER_EXPECT_TX(sb + 8 * s,
                               lo_p ? (uint32_t)GSTAGE_BYTES
                                    : (uint32_t)(GTILE_A + GTILE_B));
            const int k0 = p * 64;
            tma2d(st,           &tmA,  k0, row0, sb + 8 * s);
            tma2d(st + GTILE_A, &tmBh, k0, col0, sb + 8 * s);
            if (lo_p)
                tma2d(st + GTILE_A + GTILE_B, &tmBl, k0, col0, sb + 8 * s);
        }
    }

    // Epilogue
    const int rr = lane >> 2;
    const int cc = (lane & 3) * 2;
#pragma unroll
    for (int mt = 0; mt < 2; ++mt) {
        const int mrow = row0 + wm + mt * 16 + rr;
#pragma unroll
        for (int nt = 0; nt < 4; ++nt) {
            const int n = col0 + wn + nt * 8 + cc;
            const float2 bb = *(const float2*)(bias + n);
            float v00 = acc[mt][nt][0] + bb.x, v01 = acc[mt][nt][1] + bb.y;
            float v10 = acc[mt][nt][2] + bb.x, v11 = acc[mt][nt][3] + bb.y;
            if (MODE == 0) {
                *(float2*)(C + (size_t)mrow * N + n) = make_float2(v00, v01);
                *(float2*)(C + (size_t)(mrow + 8) * N + n) = make_float2(v10, v11);
            } else {
                const float sc = (n < 2048) ? QSCALE : 1.0f;
                *(uint32_t*)(Ch + (size_t)mrow * N + n)       = pack2h(v00 * sc, v01 * sc);
                *(uint32_t*)(Ch + (size_t)(mrow + 8) * N + n) = pack2h(v10 * sc, v11 * sc);
            }
        }
    }
}

// ---------------------------------------------------------------------------
// Fused dual-stream differential flash attention (unchanged from R16).
// ---------------------------------------------------------------------------
#define AT_NSTG 3
#define AT_STAGE_BYTES 32768
#define AT_SMEM (32768 + AT_NSTG * AT_STAGE_BYTES)

__global__ __launch_bounds__(256, 1)
void diff_attn_fused_kernel(const __grid_constant__ CUtensorMap tmT,
                            const float* __restrict__ amask,
                            const float* __restrict__ lambda_p,
                            unsigned short* __restrict__ O16)
{
    extern __shared__ __align__(1024) char asmem[];
    const uint32_t sb = smem_u32(asmem);
    const int tid = threadIdx.x, lane = tid & 31, w = tid >> 5;
    const int s_id = w >> 2;
    const int wq = w & 3;
    const int qb = blockIdx.x, bh = blockIdx.y;
    const int b = bh >> 4, h = bh & 15;
    const int q0 = qb * 64;
    const int tokbase = b * S_LEN;

    const uint32_t MB_Q = sb;
    float* maskSm = (float*)(asmem + 64);
    const uint32_t Q1 = sb + 16384;
    const uint32_t Q2 = sb + 24576;
    const uint32_t ST0 = sb + 32768;

    if (tid == 0) {
        MBARRIER_INIT(MB_Q, 1);
#pragma unroll
        for (int s = 0; s < AT_NSTG; ++s) {
            MBARRIER_INIT(sb + 8 + 8 * s, 1);
            MBARRIER_INIT(sb + 32 + 8 * s, 256);
        }
    }
    {
        const float4* mp = (const float4*)(amask + tokbase);
        float4* ms = (float4*)maskSm;
#pragma unroll
        for (int i = tid; i < 512; i += 256) {
            float4 v = mp[i];
            v.x = (1.f - v.x) * -10000.f;
            v.y = (1.f - v.y) * -10000.f;
            v.z = (1.f - v.z) * -10000.f;
            v.w = (1.f - v.w) * -10000.f;
            ms[i] = v;
        }
    }
    __syncthreads();

    const int q1col = h * 64;
    const int q2col = 1024 + h * 64;
    const int k1col = 2048 + h * 64;
    const int k2col = 3072 + h * 64;
    const int vcol  = 4096 + h * 128;

    if (tid == 0) {
        MBARRIER_EXPECT_TX(MB_Q, 16384);
        tma2d(Q1, &tmT, q1col, tokbase + q0, MB_Q);
        tma2d(Q2, &tmT, q2col, tokbase + q0, MB_Q);
#pragma unroll
        for (int s = 0; s < AT_NSTG; ++s) {
            const uint32_t st = ST0 + s * AT_STAGE_BYTES;
            const uint32_t fb = sb + 8 + 8 * s;
            MBARRIER_EXPECT_TX(fb, AT_STAGE_BYTES);
            const int k0 = tokbase + s * 64;
            tma2d(st,         &tmT, k1col,     k0, fb);
            tma2d(st + 8192,  &tmT, k2col,     k0, fb);
            tma2d(st + 16384, &tmT, vcol,      k0, fb);
            tma2d(st + 24576, &tmT, vcol + 64, k0, fb);
        }
    }

    MBARRIER_WAIT_PARITY(MB_Q, 0);
    uint32_t qh[4][4];
    {
        const uint32_t QT = s_id ? Q2 : Q1;
        const int r = 16 * wq + (lane & 15);
        const uint32_t rb = (uint32_t)r * 128;
        const uint32_t msk = (uint32_t)((r & 7) << 4);
        const uint32_t cbq = (uint32_t)(lane >> 4) * 16;
#pragma unroll
        for (int kk = 0; kk < 4; ++kk)
            ldsm4(qh[kk], QT + rb + ((cbq + kk * 32) ^ msk));
    }

    float o[16][4];
#pragma unroll
    for (int i = 0; i < 16; i++)
#pragma unroll
        for (int j = 0; j < 4; j++) o[i][j] = 0.f;
    float m0 = -1e30f, m1 = -1e30f, l0 = 0.f, l1 = 0.f;

    uint32_t kRB[4], kMask[4];
#pragma unroll
    for (int g = 0; g < 4; ++g) {
        const int r = 16 * g + (lane & 15);
        kRB[g] = (uint32_t)r * 128;
        kMask[g] = (uint32_t)((r & 7) << 4);
    }
    const uint32_t cb = (uint32_t)(lane >> 4) * 16;
    const uint32_t kOff = (uint32_t)s_id * 8192;

    for (int kb = 0; kb < 32; ++kb) {
        const int u = kb / 3;
        const int s = kb - u * 3;
        const uint32_t FULL = sb + 8 + 8 * s;
        const uint32_t EMPTY = sb + 32 + 8 * s;
        const uint32_t ST = ST0 + s * AT_STAGE_BYTES;
        MBARRIER_WAIT_PARITY(FULL, (uint32_t)(u & 1));

        float scf[8][4];
#pragma unroll
        for (int t = 0; t < 8; t++)
#pragma unroll
            for (int j = 0; j < 4; j++) scf[t][j] = 0.f;

#pragma unroll
        for (int kk = 0; kk < 4; ++kk) {
            uint32_t kh[4][4];
#pragma unroll
            for (int g = 0; g < 4; ++g) {
                const uint32_t a = cb + kk * 32;
                ldsm4(kh[g], ST + kOff + kRB[g] + (a ^ kMask[g]));
            }
#pragma unroll
            for (int g = 0; g < 4; ++g) {
                mma_fp16(scf[2 * g],     qh[kk], kh[g][0], kh[g][2]);
                mma_fp16(scf[2 * g + 1], qh[kk], kh[g][1], kh[g][3]);
            }
        }

        const int kbase = kb * 64 + 2 * (lane & 3);
        float nm0 = m0, nm1 = m1;
#pragma unroll
        for (int t = 0; t < 8; ++t) {
            const float mv0 = maskSm[kbase + 8 * t];
            const float mv1 = maskSm[kbase + 8 * t + 1];
            scf[t][0] += mv0; scf[t][1] += mv1;
            scf[t][2] += mv0; scf[t][3] += mv1;
            nm0 = fmaxf(nm0, fmaxf(scf[t][0], scf[t][1]));
            nm1 = fmaxf(nm1, fmaxf(scf[t][2], scf[t][3]));
        }
        nm0 = fmaxf(nm0, __shfl_xor_sync(0xffffffffu, nm0, 1));
        nm0 = fmaxf(nm0, __shfl_xor_sync(0xffffffffu, nm0, 2));
        nm1 = fmaxf(nm1, __shfl_xor_sync(0xffffffffu, nm1, 1));
        nm1 = fmaxf(nm1, __shfl_xor_sync(0xffffffffu, nm1, 2));
        const float a0 = fexp(m0 - nm0), a1 = fexp(m1 - nm1);
        m0 = nm0; m1 = nm1;
#pragma unroll
        for (int nt = 0; nt < 16; ++nt) {
            o[nt][0] *= a0; o[nt][1] *= a0;
            o[nt][2] *= a1; o[nt][3] *= a1;
        }

        uint32_t pha[4][4];
        float rs0 = 0.f, rs1 = 0.f;
#pragma unroll
        for (int t = 0; t < 8; ++t) {
            const float e0 = fexp(scf[t][0] - m0), e1 = fexp(scf[t][1] - m0);
            const float e2 = fexp(scf[t][2] - m1), e3 = fexp(scf[t][3] - m1);
            rs0 += e0 + e1; rs1 += e2 + e3;
            pha[t >> 1][2 * (t & 1)]     = pack2h(e0, e1);
            pha[t >> 1][2 * (t & 1) + 1] = pack2h(e2, e3);
        }
        rs0 += __shfl_xor_sync(0xffffffffu, rs0, 1);
        rs0 += __shfl_xor_sync(0xffffffffu, rs0, 2);
        rs1 += __shfl_xor_sync(0xffffffffu, rs1, 1);
        rs1 += __shfl_xor_sync(0xffffffffu, rs1, 2);
        l0 = l0 * a0 + rs0;
        l1 = l1 * a1 + rs1;

#pragma unroll
        for (int kk = 0; kk < 4; ++kk) {
            const int r = 16 * kk + (lane & 15);
            const uint32_t vrb = (uint32_t)r * 128;
            const uint32_t vmsk = (uint32_t)((r & 7) << 4);
#pragma unroll
            for (int g = 0; g < 8; ++g) {
                const uint32_t base = ST + 16384 + ((g >> 2) ? 8192u : 0u);
                const uint32_t a = ((uint32_t)((g & 3) * 32) + cb) ^ vmsk;
                uint32_t vh[4];
                ldsm4t(vh, base + vrb + a);
                mma_fp16(o[2 * g],     pha[kk], vh[0], vh[1]);
                mma_fp16(o[2 * g + 1], pha[kk], vh[2], vh[3]);
            }
        }

        MBARRIER_ARRIVE(EMPTY);

        const int p = kb + AT_NSTG;
        if (tid == 0 && p < 32) {
            const int up = p / 3;
            MBARRIER_WAIT_PARITY_RELAXED(EMPTY, (uint32_t)((up & 1) ^ 1));
            MBARRIER_EXPECT_TX(FULL, AT_STAGE_BYTES);
            const int k0 = tokbase + p * 64;
            tma2d(ST,         &tmT, k1col,     k0, FULL);
            tma2d(ST + 8192,  &tmT, k2col,     k0, FULL);
            tma2d(ST + 16384, &tmT, vcol,      k0, FULL);
            tma2d(ST + 24576, &tmT, vcol + 64, k0, FULL);
        }
    }

    __syncthreads();
    float* Cb = (float*)(asmem + 32768 + s_id * 32768);
    {
        const float inv0 = 1.f / l0, inv1 = 1.f / l1;
        const int r0 = 16 * wq + (lane >> 2);
        const int cc = 2 * (lane & 3);
#pragma unroll
        for (int nt = 0; nt < 16; ++nt) {
            Cb[r0 * 128 + 8 * nt + cc]           = o[nt][0] * inv0;
            Cb[r0 * 128 + 8 * nt + cc + 1]       = o[nt][1] * inv0;
            Cb[(r0 + 8) * 128 + 8 * nt + cc]     = o[nt][2] * inv1;
            Cb[(r0 + 8) * 128 + 8 * nt + cc + 1] = o[nt][3] * inv1;
        }
    }
    __syncthreads();

    const float lam = *lambda_p;
    const float* C1b = (const float*)(asmem + 32768);
    const float* C2b = (const float*)(asmem + 65536);
    for (int idx = tid; idx < 64 * 32; idx += 256) {
        const int row = idx >> 5;
        const int c4 = (idx & 31) * 4;
        float4 a = *(const float4*)&C1b[row * 128 + c4];
        float4 c = *(const float4*)&C2b[row * 128 + c4];
        uint2 H;
        H.x = pack2h(a.x - lam * c.x, a.y - lam * c.y);
        H.y = pack2h(a.z - lam * c.z, a.w - lam * c.w);
        *(uint2*)(O16 + (size_t)(tokbase + q0 + row) * DMODEL + h * 128 + c4) = H;
    }
}

// ---------------------------------------------------------------------------
// Merged preprocessing (unchanged from R15/R16)
// ---------------------------------------------------------------------------
#define PREP_A_BLOCKS 8192
#define PREP_B_BLOCKS 12288
#define PREP_C_BLOCKS 4096
#define PREP_BLOCKS (PREP_A_BLOCKS + PREP_B_BLOCKS + PREP_C_BLOCKS)

__global__ __launch_bounds__(256)
void prep_kernel(const float4* __restrict__ hidden,
                 const float* __restrict__ W_attn,
                 const float* __restrict__ W_proj,
                 uint2* __restrict__ A16,
                 __half* __restrict__ WAh, __half* __restrict__ WAl,
                 __half* __restrict__ WPh, __half* __restrict__ WPl)
{
    __shared__ float t[32][33];
    const int bid = blockIdx.x;
    const int tid = threadIdx.x;

    if (bid < PREP_A_BLOCKS) {
        const int i = bid * 256 + tid;
        float4 v = hidden[i];
        uint2 H;
        H.x = pack2h(v.x, v.y);
        H.y = pack2h(v.z, v.w);
        A16[i] = H;
        return;
    }

    const int tx = tid & 31, ty = tid >> 5;
    if (bid < PREP_A_BLOCKS + PREP_B_BLOCKS) {
        const int local = bid - PREP_A_BLOCKS;
        const int n0 = (local % 192) * 32;
        const int k0 = (local / 192) * 32;
#pragma unroll
        for (int r = 0; r < 4; ++r)
            t[ty + 8 * r][tx] = W_attn[(size_t)(k0 + ty + 8 * r) * N_QKV + n0 + tx];
        __syncthreads();
        const bool write_lo = (n0 >= 4096);
#pragma unroll
        for (int r = 0; r < 4; ++r) {
            const int nn = ty + 8 * r;
            float v = t[tx][nn];
            __half hh = __float2half_rn(v);
            const size_t off = (size_t)(n0 + nn) * KDIM + k0 + tx;
            WAh[off] = hh;
            if (write_lo)
                WAl[off] = __float2half_rn(v - __half2float(hh));
        }
        return;
    }

    const int local = bid - PREP_A_BLOCKS - PREP_B_BLOCKS;
    const int n0 = (local % 64) * 32;
    const int k0 = (local / 64) * 32;
#pragma unroll
    for (int r = 0; r < 4; ++r)
        t[ty + 8 * r][tx] = W_proj[(size_t)(k0 + ty + 8 * r) * DMODEL + n0 + tx];
    __syncthreads();
    const bool write_lo = (k0 < 1024);   // proj lo used only for K < 1024
#pragma unroll
    for (int r = 0; r < 4; ++r) {
        const int nn = ty + 8 * r;
        float v = t[tx][nn];
        __half hh = __float2half_rn(v);
        const size_t off = (size_t)(n0 + nn) * KDIM + k0 + tx;
        WPh[off] = hh;
        if (write_lo)
            WPl[off] = __float2half_rn(v - __half2float(hh));
    }
}

// ---------------------------------------------------------------------------
// Host side
// ---------------------------------------------------------------------------
typedef CUresult (*PFN_tmEncode)(
    CUtensorMap*, CUtensorMapDataType, cuuint32_t, void*,
    const cuuint64_t*, const cuuint64_t*, const cuuint32_t*, const cuuint32_t*,
    CUtensorMapInterleave, CUtensorMapSwizzle, CUtensorMapL2promotion,
    CUtensorMapFloatOOBfill);

static void make_map(PFN_tmEncode fn, CUtensorMap* m, void* ptr,
                     unsigned long long rows, unsigned long long cols,
                     unsigned box0, unsigned box1)
{
    cuuint64_t dims[2]    = {(cuuint64_t)cols, (cuuint64_t)rows};
    cuuint64_t strides[1] = {(cuuint64_t)cols * 2};
    cuuint32_t box[2]     = {box0, box1};
    cuuint32_t es[2]      = {1u, 1u};
    fn(m, CU_TENSOR_MAP_DATA_TYPE_BFLOAT16, 2, ptr, dims, strides, box, es,
       CU_TENSOR_MAP_INTERLEAVE_NONE, CU_TENSOR_MAP_SWIZZLE_128B,
       CU_TENSOR_MAP_L2_PROMOTION_L2_128B, CU_TENSOR_MAP_FLOAT_OOB_FILL_NONE);
}

extern "C" void kernel_launch(void* const* d_in, const int* in_sizes, int n_in,
                              void* d_out, int out_size)
{
    const float* hidden = (const float*)d_in[0];
    const float* amask  = (const float*)d_in[1];
    const float* W_attn = (const float*)d_in[2];
    const float* b_attn = (const float*)d_in[3];
    const float* W_proj = (const float*)d_in[4];
    const float* b_proj = (const float*)d_in[5];
    const float* lam    = (const float*)d_in[6];
    float* out = (float*)d_out;

    void *qkv16, *A16, *WAh, *WAl, *WPh, *WPl, *O16;
    cudaGetSymbolAddress(&qkv16, g_qkv16);
    cudaGetSymbolAddress(&A16, g_A16);
    cudaGetSymbolAddress(&WAh, g_WAh);   cudaGetSymbolAddress(&WAl, g_WAl);
    cudaGetSymbolAddress(&WPh, g_WPh);   cudaGetSymbolAddress(&WPl, g_WPl);
    cudaGetSymbolAddress(&O16, g_O16);

    void* fnp = nullptr;
    cudaDriverEntryPointQueryResult qres;
    cudaGetDriverEntryPointByVersion("cuTensorMapEncodeTiled", &fnp, 12000,
                                     cudaEnableDefault, &qres);
    PFN_tmEncode enc = (PFN_tmEncode)fnp;

    CUtensorMap tA, tWAh, tWAl, tWPh, tWPl, tO, tT;
    make_map(enc, &tA,   A16,  M_TOK,  KDIM, 64, 128);
    make_map(enc, &tWAh, WAh,  N_QKV,  KDIM, 64, 64);
    make_map(enc, &tWAl, WAl,  N_QKV,  KDIM, 64, 64);
    make_map(enc, &tWPh, WPh,  DMODEL, KDIM, 64, 64);
    make_map(enc, &tWPl, WPl,  DMODEL, KDIM, 64, 64);
    make_map(enc, &tO,   O16,  M_TOK,  KDIM, 64, 128);
    make_map(enc, &tT,   qkv16, M_TOK, N_QKV, 64, 64);

    cudaFuncSetAttribute(gemm_fp16x2_kernel<0>,
                         cudaFuncAttributeMaxDynamicSharedMemorySize, GEMM_SMEM);
    cudaFuncSetAttribute(gemm_fp16x2_kernel<1>,
                         cudaFuncAttributeMaxDynamicSharedMemorySize, GEMM_SMEM);
    cudaFuncSetAttribute(diff_attn_fused_kernel,
                         cudaFuncAttributeMaxDynamicSharedMemorySize, AT_SMEM);

    // 1) merged preprocessing
    prep_kernel<<<PREP_BLOCKS, 256>>>((const float4*)hidden, W_attn, W_proj,
                                      (uint2*)A16,
                                      (__half*)WAh, (__half*)WAl,
                                      (__half*)WPh, (__half*)WPl);
    // 2) QKV GEMM: 1-term q/k (col<4096), 2-term v (all K); heavy CTAs first
    {
        dim3 g(N_QKV / 64, M_TOK / 128);   // (96, 32)
        gemm_fp16x2_kernel<1><<<g, 256, GEMM_SMEM>>>(tA, tWAh, tWAl, b_attn,
                                                     nullptr, (unsigned short*)qkv16,
                                                     N_QKV, 4096, 32, 64);
    }
    // 3) fused dual-stream differential attention -> fp16 O16
    {
        dim3 g(S_LEN / 64, B_SZ * NHEAD);
        diff_attn_fused_kernel<<<g, 256, AT_SMEM>>>(tT, amask, lam,
                                                    (unsigned short*)O16);
    }
    // 4) output projection: lo-term only for K-chunks 0..15 (half-K residual)
    {
        dim3 g(DMODEL / 64, M_TOK / 128);  // (32, 32)
        gemm_fp16x2_kernel<0><<<g, 256, GEMM_SMEM>>>(tO, tWPh, tWPl, b_proj,
                                                     out, nullptr, DMODEL, 0, 16, 0);
    }
}